// round 1
// baseline (speedup 1.0000x reference)
#include <cuda_runtime.h>
#include <cuda_bf16.h>
#include <math.h>

// Problem constants
#define B 2
#define L 2048
#define C 1024
#define H 16
#define D 64
#define L2 512
#define TD 768
#define FF 4096
#define EPS 1e-6f

#define BL (B*L)        // 4096
#define BL2 (B*L2)      // 1024

// ---------------- scratch (device globals; no allocation allowed) ------------
__device__ float g_silu[B * C];            // silu(t_mod)
__device__ float g_mods[B * 6 * C];        // adaLN output
__device__ float g_norm[BL * C];           // normed activations (GEMM input)
__device__ float g_qkv[BL * 3 * C];        // qkv; reused for qc
__device__ float g_attn[BL * C];           // attention output (b,l,h,d)
__device__ float g_proj[BL * C];           // projection output
__device__ float g_x[BL * C];              // running residual stream
__device__ float g_kv[BL2 * 2 * C];        // cross-attn k,v
__device__ float g_gate[BL * FF];          // mlp gate (then h)
__device__ float g_up[BL * FF];            // mlp up

// ---------------- SGEMM: C[M,N] = A[M,K] @ B[K,N] (+bias) --------------------
#define BM 64
#define BN 64
#define BK 16
#define TM 4
#define TN 4

__global__ void sgemm_kernel(const float* __restrict__ A,
                             const float* __restrict__ Bm,
                             const float* __restrict__ bias,
                             float* __restrict__ Cm,
                             int M, int N, int K) {
    __shared__ float As[BK][BM + 1];
    __shared__ float Bs[BK][BN];

    int tid = threadIdx.x;            // 256 threads
    int tx = tid % 16;
    int ty = tid / 16;
    int rowBase = blockIdx.y * BM;
    int colBase = blockIdx.x * BN;

    float acc[TM][TN];
#pragma unroll
    for (int i = 0; i < TM; i++)
#pragma unroll
        for (int j = 0; j < TN; j++) acc[i][j] = 0.f;

    for (int k0 = 0; k0 < K; k0 += BK) {
        // load A tile (BM x BK), store transposed
#pragma unroll
        for (int i = 0; i < 4; i++) {
            int t = tid + i * 256;
            int r = t / BK, c = t % BK;
            int gr = rowBase + r, gc = k0 + c;
            As[c][r] = (gr < M) ? A[(size_t)gr * K + gc] : 0.f;
        }
        // load B tile (BK x BN)
#pragma unroll
        for (int i = 0; i < 4; i++) {
            int t = tid + i * 256;
            int r = t / BN, c = t % BN;
            Bs[r][c] = Bm[(size_t)(k0 + r) * N + colBase + c];
        }
        __syncthreads();

#pragma unroll
        for (int kk = 0; kk < BK; kk++) {
            float a[TM], b[TN];
#pragma unroll
            for (int i = 0; i < TM; i++) a[i] = As[kk][ty * TM + i];
#pragma unroll
            for (int j = 0; j < TN; j++) b[j] = Bs[kk][tx * TN + j];
#pragma unroll
            for (int i = 0; i < TM; i++)
#pragma unroll
                for (int j = 0; j < TN; j++) acc[i][j] += a[i] * b[j];
        }
        __syncthreads();
    }

#pragma unroll
    for (int i = 0; i < TM; i++) {
        int gr = rowBase + ty * TM + i;
        if (gr >= M) continue;
#pragma unroll
        for (int j = 0; j < TN; j++) {
            int gc = colBase + tx * TN + j;
            float v = acc[i][j];
            if (bias) v += bias[gc];
            Cm[(size_t)gr * N + gc] = v;
        }
    }
}

static inline void sgemm(const float* A, const float* Bm, const float* bias,
                         float* Cm, int M, int N, int K) {
    dim3 grid((N + BN - 1) / BN, (M + BM - 1) / BM);
    sgemm_kernel<<<grid, 256>>>(A, Bm, bias, Cm, M, N, K);
}

// ---------------- elementwise kernels ---------------------------------------
__global__ void silu_kernel(const float* __restrict__ in, float* __restrict__ out, int n) {
    int i = blockIdx.x * blockDim.x + threadIdx.x;
    if (i >= n) return;
    float v = in[i];
    out[i] = v / (1.f + __expf(-v));
}

// rmsnorm with optional adaLN modulation.
// mods row layout per batch: [shift_sa, scale_sa, gate_sa, shift_mlp, scale_mlp, gate_mlp]
__global__ void rmsnorm_kernel(const float* __restrict__ x,
                               const float* __restrict__ w,
                               const float* __restrict__ mods,  // nullable
                               int shift_off, int scale_off,
                               float* __restrict__ out) {
    int row = blockIdx.x;              // BL rows
    int b = row / L;
    const float* xr = x + (size_t)row * C;

    float s = 0.f;
    for (int c = threadIdx.x; c < C; c += blockDim.x) {
        float v = xr[c];
        s += v * v;
    }
    __shared__ float red[32];
#pragma unroll
    for (int o = 16; o > 0; o >>= 1) s += __shfl_down_sync(0xffffffff, s, o);
    if ((threadIdx.x & 31) == 0) red[threadIdx.x >> 5] = s;
    __syncthreads();
    if (threadIdx.x < 32) {
        float v = (threadIdx.x < (blockDim.x >> 5)) ? red[threadIdx.x] : 0.f;
#pragma unroll
        for (int o = 16; o > 0; o >>= 1) v += __shfl_down_sync(0xffffffff, v, o);
        if (threadIdx.x == 0) red[0] = v;
    }
    __syncthreads();
    float inv = rsqrtf(red[0] / (float)C + EPS);

    for (int c = threadIdx.x; c < C; c += blockDim.x) {
        float n = xr[c] * inv * w[c];
        if (mods) {
            float sc = mods[(size_t)b * 6 * C + scale_off + c];
            float sh = mods[(size_t)b * 6 * C + shift_off + c];
            n = n * (1.f + sc) + sh;
        }
        out[(size_t)row * C + c] = n;
    }
}

// RoPE applied in-place to q and k slices of qkv (B,L,3,H,D)
__global__ void rope_kernel(float* __restrict__ qkv,
                            const float* __restrict__ fcos,
                            const float* __restrict__ fsin) {
    int i = blockIdx.x * blockDim.x + threadIdx.x;
    int total = B * L * H * (D / 2);
    if (i >= total) return;
    int p = i % (D / 2);
    int t = i / (D / 2);
    int h = t % H; t /= H;
    int l = t % L;
    int b = t / L;
    float c = fcos[l * (D / 2) + p];
    float s = fsin[l * (D / 2) + p];
#pragma unroll
    for (int sidx = 0; sidx < 2; sidx++) {  // 0=q, 1=k
        size_t base = ((((size_t)b * L + l) * 3 + sidx) * H + h) * D + 2 * p;
        float xr = qkv[base], xi = qkv[base + 1];
        qkv[base]     = xr * c - xi * s;
        qkv[base + 1] = xr * s + xi * c;
    }
}

// out[i] = x[i] + gate * p[i]   (gate from mods, or 1.0 if mods==null)
__global__ void residual_kernel(const float* __restrict__ x,
                                const float* __restrict__ p,
                                const float* __restrict__ mods,  // nullable
                                int gate_off,
                                float* __restrict__ out) {
    size_t i = (size_t)blockIdx.x * blockDim.x + threadIdx.x;
    if (i >= (size_t)BL * C) return;
    float g = 1.f;
    if (mods) {
        int c = (int)(i % C);
        int b = (int)(i / ((size_t)L * C));
        g = mods[(size_t)b * 6 * C + gate_off + c];
    }
    out[i] = x[i] + g * p[i];
}

// h = silu(gate) * up, in-place into gate
__global__ void swiglu_kernel(float* __restrict__ g, const float* __restrict__ u, size_t n) {
    size_t i = (size_t)blockIdx.x * blockDim.x + threadIdx.x;
    if (i >= n) return;
    float v = g[i];
    g[i] = (v / (1.f + __expf(-v))) * u[i];
}

// ---------------- flash attention (one query row per thread) -----------------
// grid: (Lq/64, H, B), block: 64 threads
#define KT 32  // kv tile
__global__ void attn_kernel(const float* __restrict__ qbase,
                            const float* __restrict__ kbase,
                            const float* __restrict__ vbase,
                            float* __restrict__ out,
                            int Lq, int Lk,
                            long q_sb, long q_sl,
                            long k_sb, long k_sl,
                            long v_sb, long v_sl) {
    int qi = blockIdx.x * 64 + threadIdx.x;
    int h = blockIdx.y, b = blockIdx.z;
    const float scale = 0.125f;  // 1/sqrt(64)

    const float* qp = qbase + (size_t)b * q_sb + (size_t)qi * q_sl + h * D;
    float q[D], acc[D];
#pragma unroll
    for (int d = 0; d < D; d++) { q[d] = qp[d]; acc[d] = 0.f; }
    float m = -1e30f, lsum = 0.f;

    __shared__ float Ks[KT * D];
    __shared__ float Vs[KT * D];
    __shared__ float Ps[64][KT + 1];

    for (int k0 = 0; k0 < Lk; k0 += KT) {
        // cooperative load of K,V tiles (coalesced)
        for (int idx = threadIdx.x; idx < KT * D; idx += 64) {
            int r = idx / D, c = idx % D;
            Ks[idx] = kbase[(size_t)b * k_sb + (size_t)(k0 + r) * k_sl + h * D + c];
            Vs[idx] = vbase[(size_t)b * v_sb + (size_t)(k0 + r) * v_sl + h * D + c];
        }
        __syncthreads();

        float mnew = m;
#pragma unroll 1
        for (int j = 0; j < KT; j++) {
            float s = 0.f;
#pragma unroll
            for (int d = 0; d < D; d++) s += q[d] * Ks[j * D + d];
            s *= scale;
            Ps[threadIdx.x][j] = s;
            mnew = fmaxf(mnew, s);
        }
        float corr = __expf(m - mnew);
        lsum *= corr;
#pragma unroll
        for (int d = 0; d < D; d++) acc[d] *= corr;
#pragma unroll 1
        for (int j = 0; j < KT; j++) {
            float pe = __expf(Ps[threadIdx.x][j] - mnew);
            lsum += pe;
#pragma unroll
            for (int d = 0; d < D; d++) acc[d] += pe * Vs[j * D + d];
        }
        m = mnew;
        __syncthreads();
    }

    float invl = 1.f / lsum;
    float* op = out + (((size_t)b * Lq + qi) * H + h) * D;
#pragma unroll
    for (int d = 0; d < D; d++) op[d] = acc[d] * invl;
}

// ---------------- launch ------------------------------------------------------
extern "C" void kernel_launch(void* const* d_in, const int* in_sizes, int n_in,
                              void* d_out, int out_size) {
    const float* x            = (const float*)d_in[0];
    const float* t_mod        = (const float*)d_in[1];
    const float* audio_ctx    = (const float*)d_in[2];
    const float* freqs_cos    = (const float*)d_in[3];
    const float* freqs_sin    = (const float*)d_in[4];
    const float* norm1_w      = (const float*)d_in[5];
    const float* norm2_w      = (const float*)d_in[6];
    const float* norm3_w      = (const float*)d_in[7];
    const float* W_qkv        = (const float*)d_in[8];
    const float* W_sa_out     = (const float*)d_in[9];
    const float* W_q          = (const float*)d_in[10];
    const float* W_kv         = (const float*)d_in[11];
    const float* W_ca_out     = (const float*)d_in[12];
    const float* W_gate       = (const float*)d_in[13];
    const float* W_up         = (const float*)d_in[14];
    const float* W_down       = (const float*)d_in[15];
    const float* adaLN_W      = (const float*)d_in[16];
    const float* adaLN_b      = (const float*)d_in[17];
    float* out = (float*)d_out;

    float *silu_p, *mods_p, *norm_p, *qkv_p, *attn_p, *proj_p, *x_p, *kv_p, *gate_p, *up_p;
    cudaGetSymbolAddress((void**)&silu_p, g_silu);
    cudaGetSymbolAddress((void**)&mods_p, g_mods);
    cudaGetSymbolAddress((void**)&norm_p, g_norm);
    cudaGetSymbolAddress((void**)&qkv_p,  g_qkv);
    cudaGetSymbolAddress((void**)&attn_p, g_attn);
    cudaGetSymbolAddress((void**)&proj_p, g_proj);
    cudaGetSymbolAddress((void**)&x_p,    g_x);
    cudaGetSymbolAddress((void**)&kv_p,   g_kv);
    cudaGetSymbolAddress((void**)&gate_p, g_gate);
    cudaGetSymbolAddress((void**)&up_p,   g_up);

    const size_t NXC = (size_t)BL * C;   // 4M

    // 1) adaLN modulation: mods = silu(t_mod) @ adaLN_W + adaLN_b
    silu_kernel<<<(B * C + 255) / 256, 256>>>(t_mod, silu_p, B * C);
    sgemm(silu_p, adaLN_W, adaLN_b, mods_p, B, 6 * C, C);

    // 2) self-attention branch
    rmsnorm_kernel<<<BL, 256>>>(x, norm1_w, mods_p, /*shift*/0, /*scale*/C, norm_p);
    sgemm(norm_p, W_qkv, nullptr, qkv_p, BL, 3 * C, C);
    {
        int total = B * L * H * (D / 2);
        rope_kernel<<<(total + 255) / 256, 256>>>(qkv_p, freqs_cos, freqs_sin);
    }
    {
        dim3 grid(L / 64, H, B);
        long sl = 3 * C, sb = (long)L * 3 * C;
        attn_kernel<<<grid, 64>>>(qkv_p /*q*/, qkv_p + C /*k*/, qkv_p + 2 * C /*v*/,
                                  attn_p, L, L, sb, sl, sb, sl, sb, sl);
    }
    sgemm(attn_p, W_sa_out, nullptr, proj_p, BL, C, C);
    residual_kernel<<<(NXC + 255) / 256, 256>>>(x, proj_p, mods_p, /*gate_sa*/2 * C, x_p);

    // 3) cross-attention branch
    rmsnorm_kernel<<<BL, 256>>>(x_p, norm2_w, nullptr, 0, 0, norm_p);
    sgemm(norm_p, W_q, nullptr, qkv_p, BL, C, C);          // qc reuses g_qkv
    sgemm(audio_ctx, W_kv, nullptr, kv_p, BL2, 2 * C, TD); // kc,vc
    {
        dim3 grid(L / 64, H, B);
        long q_sl = C, q_sb = (long)L * C;
        long kv_sl = 2 * C, kv_sb = (long)L2 * 2 * C;
        attn_kernel<<<grid, 64>>>(qkv_p, kv_p /*k*/, kv_p + C /*v*/,
                                  attn_p, L, L2, q_sb, q_sl, kv_sb, kv_sl, kv_sb, kv_sl);
    }
    sgemm(attn_p, W_ca_out, nullptr, proj_p, BL, C, C);
    residual_kernel<<<(NXC + 255) / 256, 256>>>(x_p, proj_p, nullptr, 0, x_p);

    // 4) MLP branch
    rmsnorm_kernel<<<BL, 256>>>(x_p, norm3_w, mods_p, /*shift_mlp*/3 * C, /*scale_mlp*/4 * C, norm_p);
    sgemm(norm_p, W_gate, nullptr, gate_p, BL, FF, C);
    sgemm(norm_p, W_up,   nullptr, up_p,   BL, FF, C);
    {
        size_t n = (size_t)BL * FF;
        swiglu_kernel<<<(int)((n + 255) / 256), 256>>>(gate_p, up_p, n);
    }
    sgemm(gate_p, W_down, nullptr, proj_p, BL, C, FF);
    residual_kernel<<<(NXC + 255) / 256, 256>>>(x_p, proj_p, mods_p, /*gate_mlp*/5 * C, out);
}

// round 2
// speedup vs baseline: 1.0036x; 1.0036x over previous
#include <cuda_runtime.h>
#include <cuda_bf16.h>
#include <math.h>

// Problem constants
#define B 2
#define L 2048
#define C 1024
#define H 16
#define D 64
#define L2 512
#define TD 768
#define FF 4096
#define EPS 1e-6f

#define BL (B*L)        // 4096
#define BL2 (B*L2)      // 1024

// ---------------- scratch (device globals; no allocation allowed) ------------
__device__ float g_silu[B * C];            // silu(t_mod)
__device__ float g_mods[B * 6 * C];        // adaLN output
__device__ float g_norm[BL * C];           // normed activations (GEMM input)
__device__ float g_qkv[BL * 3 * C];        // qkv; reused for qc
__device__ float g_attn[BL * C];           // attention output (b,l,h,d)
__device__ float g_proj[BL * C];           // projection output
__device__ float g_x[BL * C];              // running residual stream
__device__ float g_kv[BL2 * 2 * C];        // cross-attn k,v
__device__ float g_gate[BL * FF];          // mlp gate (then h)
__device__ float g_up[BL * FF];            // mlp up

// ---------------- SGEMM: C[M,N] = A[M,K] @ B[K,N] (+bias) --------------------
#define BM 64
#define BN 64
#define BK 16
#define TM 4
#define TN 4

__global__ void sgemm_kernel(const float* __restrict__ A,
                             const float* __restrict__ Bm,
                             const float* __restrict__ bias,
                             float* __restrict__ Cm,
                             int M, int N, int K) {
    __shared__ float As[BK][BM + 1];
    __shared__ float Bs[BK][BN];

    int tid = threadIdx.x;            // 256 threads
    int tx = tid % 16;
    int ty = tid / 16;
    int rowBase = blockIdx.y * BM;
    int colBase = blockIdx.x * BN;

    float acc[TM][TN];
#pragma unroll
    for (int i = 0; i < TM; i++)
#pragma unroll
        for (int j = 0; j < TN; j++) acc[i][j] = 0.f;

    for (int k0 = 0; k0 < K; k0 += BK) {
        // load A tile (BM x BK), store transposed
#pragma unroll
        for (int i = 0; i < 4; i++) {
            int t = tid + i * 256;
            int r = t / BK, c = t % BK;
            int gr = rowBase + r, gc = k0 + c;
            As[c][r] = (gr < M) ? A[(size_t)gr * K + gc] : 0.f;
        }
        // load B tile (BK x BN)
#pragma unroll
        for (int i = 0; i < 4; i++) {
            int t = tid + i * 256;
            int r = t / BN, c = t % BN;
            Bs[r][c] = Bm[(size_t)(k0 + r) * N + colBase + c];
        }
        __syncthreads();

#pragma unroll
        for (int kk = 0; kk < BK; kk++) {
            float a[TM], b[TN];
#pragma unroll
            for (int i = 0; i < TM; i++) a[i] = As[kk][ty * TM + i];
#pragma unroll
            for (int j = 0; j < TN; j++) b[j] = Bs[kk][tx * TN + j];
#pragma unroll
            for (int i = 0; i < TM; i++)
#pragma unroll
                for (int j = 0; j < TN; j++) acc[i][j] += a[i] * b[j];
        }
        __syncthreads();
    }

#pragma unroll
    for (int i = 0; i < TM; i++) {
        int gr = rowBase + ty * TM + i;
        if (gr >= M) continue;
#pragma unroll
        for (int j = 0; j < TN; j++) {
            int gc = colBase + tx * TN + j;
            float v = acc[i][j];
            if (bias) v += bias[gc];
            Cm[(size_t)gr * N + gc] = v;
        }
    }
}

static inline void sgemm(const float* A, const float* Bm, const float* bias,
                         float* Cm, int M, int N, int K) {
    dim3 grid((N + BN - 1) / BN, (M + BM - 1) / BM);
    sgemm_kernel<<<grid, 256>>>(A, Bm, bias, Cm, M, N, K);
}

// ---------------- elementwise kernels ---------------------------------------
__global__ void silu_kernel(const float* __restrict__ in, float* __restrict__ out, int n) {
    int i = blockIdx.x * blockDim.x + threadIdx.x;
    if (i >= n) return;
    float v = in[i];
    out[i] = v / (1.f + __expf(-v));
}

// rmsnorm with optional adaLN modulation.
// mods row layout per batch: [shift_sa, scale_sa, gate_sa, shift_mlp, scale_mlp, gate_mlp]
__global__ void rmsnorm_kernel(const float* __restrict__ x,
                               const float* __restrict__ w,
                               const float* __restrict__ mods,  // nullable
                               int shift_off, int scale_off,
                               float* __restrict__ out) {
    int row = blockIdx.x;              // BL rows
    int b = row / L;
    const float* xr = x + (size_t)row * C;

    float s = 0.f;
    for (int c = threadIdx.x; c < C; c += blockDim.x) {
        float v = xr[c];
        s += v * v;
    }
    __shared__ float red[32];
#pragma unroll
    for (int o = 16; o > 0; o >>= 1) s += __shfl_down_sync(0xffffffff, s, o);
    if ((threadIdx.x & 31) == 0) red[threadIdx.x >> 5] = s;
    __syncthreads();
    if (threadIdx.x < 32) {
        float v = (threadIdx.x < (blockDim.x >> 5)) ? red[threadIdx.x] : 0.f;
#pragma unroll
        for (int o = 16; o > 0; o >>= 1) v += __shfl_down_sync(0xffffffff, v, o);
        if (threadIdx.x == 0) red[0] = v;
    }
    __syncthreads();
    float inv = rsqrtf(red[0] / (float)C + EPS);

    for (int c = threadIdx.x; c < C; c += blockDim.x) {
        float n = xr[c] * inv * w[c];
        if (mods) {
            float sc = mods[(size_t)b * 6 * C + scale_off + c];
            float sh = mods[(size_t)b * 6 * C + shift_off + c];
            n = n * (1.f + sc) + sh;
        }
        out[(size_t)row * C + c] = n;
    }
}

// RoPE applied in-place to q and k slices of qkv (B,L,3,H,D)
__global__ void rope_kernel(float* __restrict__ qkv,
                            const float* __restrict__ fcos,
                            const float* __restrict__ fsin) {
    int i = blockIdx.x * blockDim.x + threadIdx.x;
    int total = B * L * H * (D / 2);
    if (i >= total) return;
    int p = i % (D / 2);
    int t = i / (D / 2);
    int h = t % H; t /= H;
    int l = t % L;
    int b = t / L;
    float c = fcos[l * (D / 2) + p];
    float s = fsin[l * (D / 2) + p];
#pragma unroll
    for (int sidx = 0; sidx < 2; sidx++) {  // 0=q, 1=k
        size_t base = ((((size_t)b * L + l) * 3 + sidx) * H + h) * D + 2 * p;
        float xr = qkv[base], xi = qkv[base + 1];
        qkv[base]     = xr * c - xi * s;
        qkv[base + 1] = xr * s + xi * c;
    }
}

// out[i] = x[i] + gate * p[i]   (gate from mods, or 1.0 if mods==null)
__global__ void residual_kernel(const float* __restrict__ x,
                                const float* __restrict__ p,
                                const float* __restrict__ mods,  // nullable
                                int gate_off,
                                float* __restrict__ out) {
    size_t i = (size_t)blockIdx.x * blockDim.x + threadIdx.x;
    if (i >= (size_t)BL * C) return;
    float g = 1.f;
    if (mods) {
        int c = (int)(i % C);
        int b = (int)(i / ((size_t)L * C));
        g = mods[(size_t)b * 6 * C + gate_off + c];
    }
    out[i] = x[i] + g * p[i];
}

// h = silu(gate) * up, in-place into gate
__global__ void swiglu_kernel(float* __restrict__ g, const float* __restrict__ u, size_t n) {
    size_t i = (size_t)blockIdx.x * blockDim.x + threadIdx.x;
    if (i >= n) return;
    float v = g[i];
    g[i] = (v / (1.f + __expf(-v))) * u[i];
}

// ---------------- flash attention (one query row per thread) -----------------
// grid: (Lq/64, H, B), block: 64 threads
#define KT 32  // kv tile
__global__ void attn_kernel(const float* __restrict__ qbase,
                            const float* __restrict__ kbase,
                            const float* __restrict__ vbase,
                            float* __restrict__ out,
                            int Lq, int Lk,
                            long q_sb, long q_sl,
                            long k_sb, long k_sl,
                            long v_sb, long v_sl) {
    int qi = blockIdx.x * 64 + threadIdx.x;
    int h = blockIdx.y, b = blockIdx.z;
    const float scale = 0.125f;  // 1/sqrt(64)

    const float* qp = qbase + (size_t)b * q_sb + (size_t)qi * q_sl + h * D;
    float q[D], acc[D];
#pragma unroll
    for (int d = 0; d < D; d++) { q[d] = qp[d]; acc[d] = 0.f; }
    float m = -1e30f, lsum = 0.f;

    __shared__ float Ks[KT * D];
    __shared__ float Vs[KT * D];
    __shared__ float Ps[64][KT + 1];

    for (int k0 = 0; k0 < Lk; k0 += KT) {
        // cooperative load of K,V tiles (coalesced)
        for (int idx = threadIdx.x; idx < KT * D; idx += 64) {
            int r = idx / D, c = idx % D;
            Ks[idx] = kbase[(size_t)b * k_sb + (size_t)(k0 + r) * k_sl + h * D + c];
            Vs[idx] = vbase[(size_t)b * v_sb + (size_t)(k0 + r) * v_sl + h * D + c];
        }
        __syncthreads();

        float mnew = m;
#pragma unroll 1
        for (int j = 0; j < KT; j++) {
            float s = 0.f;
#pragma unroll
            for (int d = 0; d < D; d++) s += q[d] * Ks[j * D + d];
            s *= scale;
            Ps[threadIdx.x][j] = s;
            mnew = fmaxf(mnew, s);
        }
        float corr = __expf(m - mnew);
        lsum *= corr;
#pragma unroll
        for (int d = 0; d < D; d++) acc[d] *= corr;
#pragma unroll 1
        for (int j = 0; j < KT; j++) {
            float pe = __expf(Ps[threadIdx.x][j] - mnew);
            lsum += pe;
#pragma unroll
            for (int d = 0; d < D; d++) acc[d] += pe * Vs[j * D + d];
        }
        m = mnew;
        __syncthreads();
    }

    float invl = 1.f / lsum;
    float* op = out + (((size_t)b * Lq + qi) * H + h) * D;
#pragma unroll
    for (int d = 0; d < D; d++) op[d] = acc[d] * invl;
}

// ---------------- launch ------------------------------------------------------
extern "C" void kernel_launch(void* const* d_in, const int* in_sizes, int n_in,
                              void* d_out, int out_size) {
    const float* x            = (const float*)d_in[0];
    const float* t_mod        = (const float*)d_in[1];
    const float* audio_ctx    = (const float*)d_in[2];
    const float* freqs_cos    = (const float*)d_in[3];
    const float* freqs_sin    = (const float*)d_in[4];
    const float* norm1_w      = (const float*)d_in[5];
    const float* norm2_w      = (const float*)d_in[6];
    const float* norm3_w      = (const float*)d_in[7];
    const float* W_qkv        = (const float*)d_in[8];
    const float* W_sa_out     = (const float*)d_in[9];
    const float* W_q          = (const float*)d_in[10];
    const float* W_kv         = (const float*)d_in[11];
    const float* W_ca_out     = (const float*)d_in[12];
    const float* W_gate       = (const float*)d_in[13];
    const float* W_up         = (const float*)d_in[14];
    const float* W_down       = (const float*)d_in[15];
    const float* adaLN_W      = (const float*)d_in[16];
    const float* adaLN_b      = (const float*)d_in[17];
    float* out = (float*)d_out;

    float *silu_p, *mods_p, *norm_p, *qkv_p, *attn_p, *proj_p, *x_p, *kv_p, *gate_p, *up_p;
    cudaGetSymbolAddress((void**)&silu_p, g_silu);
    cudaGetSymbolAddress((void**)&mods_p, g_mods);
    cudaGetSymbolAddress((void**)&norm_p, g_norm);
    cudaGetSymbolAddress((void**)&qkv_p,  g_qkv);
    cudaGetSymbolAddress((void**)&attn_p, g_attn);
    cudaGetSymbolAddress((void**)&proj_p, g_proj);
    cudaGetSymbolAddress((void**)&x_p,    g_x);
    cudaGetSymbolAddress((void**)&kv_p,   g_kv);
    cudaGetSymbolAddress((void**)&gate_p, g_gate);
    cudaGetSymbolAddress((void**)&up_p,   g_up);

    const size_t NXC = (size_t)BL * C;   // 4M

    // 1) adaLN modulation: mods = silu(t_mod) @ adaLN_W + adaLN_b
    silu_kernel<<<(B * C + 255) / 256, 256>>>(t_mod, silu_p, B * C);
    sgemm(silu_p, adaLN_W, adaLN_b, mods_p, B, 6 * C, C);

    // 2) self-attention branch
    rmsnorm_kernel<<<BL, 256>>>(x, norm1_w, mods_p, /*shift*/0, /*scale*/C, norm_p);
    sgemm(norm_p, W_qkv, nullptr, qkv_p, BL, 3 * C, C);
    {
        int total = B * L * H * (D / 2);
        rope_kernel<<<(total + 255) / 256, 256>>>(qkv_p, freqs_cos, freqs_sin);
    }
    {
        dim3 grid(L / 64, H, B);
        long sl = 3 * C, sb = (long)L * 3 * C;
        attn_kernel<<<grid, 64>>>(qkv_p /*q*/, qkv_p + C /*k*/, qkv_p + 2 * C /*v*/,
                                  attn_p, L, L, sb, sl, sb, sl, sb, sl);
    }
    sgemm(attn_p, W_sa_out, nullptr, proj_p, BL, C, C);
    residual_kernel<<<(NXC + 255) / 256, 256>>>(x, proj_p, mods_p, /*gate_sa*/2 * C, x_p);

    // 3) cross-attention branch
    rmsnorm_kernel<<<BL, 256>>>(x_p, norm2_w, nullptr, 0, 0, norm_p);
    sgemm(norm_p, W_q, nullptr, qkv_p, BL, C, C);          // qc reuses g_qkv
    sgemm(audio_ctx, W_kv, nullptr, kv_p, BL2, 2 * C, TD); // kc,vc
    {
        dim3 grid(L / 64, H, B);
        long q_sl = C, q_sb = (long)L * C;
        long kv_sl = 2 * C, kv_sb = (long)L2 * 2 * C;
        attn_kernel<<<grid, 64>>>(qkv_p, kv_p /*k*/, kv_p + C /*v*/,
                                  attn_p, L, L2, q_sb, q_sl, kv_sb, kv_sl, kv_sb, kv_sl);
    }
    sgemm(attn_p, W_ca_out, nullptr, proj_p, BL, C, C);
    residual_kernel<<<(NXC + 255) / 256, 256>>>(x_p, proj_p, nullptr, 0, x_p);

    // 4) MLP branch
    rmsnorm_kernel<<<BL, 256>>>(x_p, norm3_w, mods_p, /*shift_mlp*/3 * C, /*scale_mlp*/4 * C, norm_p);
    sgemm(norm_p, W_gate, nullptr, gate_p, BL, FF, C);
    sgemm(norm_p, W_up,   nullptr, up_p,   BL, FF, C);
    {
        size_t n = (size_t)BL * FF;
        swiglu_kernel<<<(int)((n + 255) / 256), 256>>>(gate_p, up_p, n);
    }
    sgemm(gate_p, W_down, nullptr, proj_p, BL, C, FF);
    residual_kernel<<<(NXC + 255) / 256, 256>>>(x_p, proj_p, mods_p, /*gate_mlp*/5 * C, out);
}

// round 3
// speedup vs baseline: 1.0041x; 1.0005x over previous
#include <cuda_runtime.h>
#include <cuda_bf16.h>
#include <math.h>

// Problem constants
#define B 2
#define L 2048
#define C 1024
#define H 16
#define D 64
#define L2 512
#define TD 768
#define FF 4096
#define EPS 1e-6f

#define BL (B*L)        // 4096
#define BL2 (B*L2)      // 1024

// ---------------- scratch (device globals; no allocation allowed) ------------
__device__ float g_silu[B * C];            // silu(t_mod)
__device__ float g_mods[B * 6 * C];        // adaLN output
__device__ float g_norm[BL * C];           // normed activations (GEMM input)
__device__ float g_qkv[BL * 3 * C];        // qkv; reused for qc
__device__ float g_attn[BL * C];           // attention output (b,l,h,d)
__device__ float g_proj[BL * C];           // projection output
__device__ float g_x[BL * C];              // running residual stream
__device__ float g_kv[BL2 * 2 * C];        // cross-attn k,v
__device__ float g_gate[BL * FF];          // mlp gate (then h)
__device__ float g_up[BL * FF];            // mlp up

// ---------------- SGEMM: C[M,N] = A[M,K] @ B[K,N] (+bias) --------------------
#define BM 64
#define BN 64
#define BK 16
#define TM 4
#define TN 4

__global__ void sgemm_kernel(const float* __restrict__ A,
                             const float* __restrict__ Bm,
                             const float* __restrict__ bias,
                             float* __restrict__ Cm,
                             int M, int N, int K) {
    __shared__ float As[BK][BM + 1];
    __shared__ float Bs[BK][BN];

    int tid = threadIdx.x;            // 256 threads
    int tx = tid % 16;
    int ty = tid / 16;
    int rowBase = blockIdx.y * BM;
    int colBase = blockIdx.x * BN;

    float acc[TM][TN];
#pragma unroll
    for (int i = 0; i < TM; i++)
#pragma unroll
        for (int j = 0; j < TN; j++) acc[i][j] = 0.f;

    for (int k0 = 0; k0 < K; k0 += BK) {
        // load A tile (BM x BK), store transposed
#pragma unroll
        for (int i = 0; i < 4; i++) {
            int t = tid + i * 256;
            int r = t / BK, c = t % BK;
            int gr = rowBase + r, gc = k0 + c;
            As[c][r] = (gr < M) ? A[(size_t)gr * K + gc] : 0.f;
        }
        // load B tile (BK x BN)
#pragma unroll
        for (int i = 0; i < 4; i++) {
            int t = tid + i * 256;
            int r = t / BN, c = t % BN;
            Bs[r][c] = Bm[(size_t)(k0 + r) * N + colBase + c];
        }
        __syncthreads();

#pragma unroll
        for (int kk = 0; kk < BK; kk++) {
            float a[TM], b[TN];
#pragma unroll
            for (int i = 0; i < TM; i++) a[i] = As[kk][ty * TM + i];
#pragma unroll
            for (int j = 0; j < TN; j++) b[j] = Bs[kk][tx * TN + j];
#pragma unroll
            for (int i = 0; i < TM; i++)
#pragma unroll
                for (int j = 0; j < TN; j++) acc[i][j] += a[i] * b[j];
        }
        __syncthreads();
    }

#pragma unroll
    for (int i = 0; i < TM; i++) {
        int gr = rowBase + ty * TM + i;
        if (gr >= M) continue;
#pragma unroll
        for (int j = 0; j < TN; j++) {
            int gc = colBase + tx * TN + j;
            float v = acc[i][j];
            if (bias) v += bias[gc];
            Cm[(size_t)gr * N + gc] = v;
        }
    }
}

static inline void sgemm(const float* A, const float* Bm, const float* bias,
                         float* Cm, int M, int N, int K) {
    dim3 grid((N + BN - 1) / BN, (M + BM - 1) / BM);
    sgemm_kernel<<<grid, 256>>>(A, Bm, bias, Cm, M, N, K);
}

// ---------------- elementwise kernels ---------------------------------------
__global__ void silu_kernel(const float* __restrict__ in, float* __restrict__ out, int n) {
    int i = blockIdx.x * blockDim.x + threadIdx.x;
    if (i >= n) return;
    float v = in[i];
    out[i] = v / (1.f + __expf(-v));
}

// rmsnorm with optional adaLN modulation.
// mods row layout per batch: [shift_sa, scale_sa, gate_sa, shift_mlp, scale_mlp, gate_mlp]
__global__ void rmsnorm_kernel(const float* __restrict__ x,
                               const float* __restrict__ w,
                               const float* __restrict__ mods,  // nullable
                               int shift_off, int scale_off,
                               float* __restrict__ out) {
    int row = blockIdx.x;              // BL rows
    int b = row / L;
    const float* xr = x + (size_t)row * C;

    float s = 0.f;
    for (int c = threadIdx.x; c < C; c += blockDim.x) {
        float v = xr[c];
        s += v * v;
    }
    __shared__ float red[32];
#pragma unroll
    for (int o = 16; o > 0; o >>= 1) s += __shfl_down_sync(0xffffffff, s, o);
    if ((threadIdx.x & 31) == 0) red[threadIdx.x >> 5] = s;
    __syncthreads();
    if (threadIdx.x < 32) {
        float v = (threadIdx.x < (blockDim.x >> 5)) ? red[threadIdx.x] : 0.f;
#pragma unroll
        for (int o = 16; o > 0; o >>= 1) v += __shfl_down_sync(0xffffffff, v, o);
        if (threadIdx.x == 0) red[0] = v;
    }
    __syncthreads();
    float inv = rsqrtf(red[0] / (float)C + EPS);

    for (int c = threadIdx.x; c < C; c += blockDim.x) {
        float n = xr[c] * inv * w[c];
        if (mods) {
            float sc = mods[(size_t)b * 6 * C + scale_off + c];
            float sh = mods[(size_t)b * 6 * C + shift_off + c];
            n = n * (1.f + sc) + sh;
        }
        out[(size_t)row * C + c] = n;
    }
}

// RoPE applied in-place to q and k slices of qkv (B,L,3,H,D)
__global__ void rope_kernel(float* __restrict__ qkv,
                            const float* __restrict__ fcos,
                            const float* __restrict__ fsin) {
    int i = blockIdx.x * blockDim.x + threadIdx.x;
    int total = B * L * H * (D / 2);
    if (i >= total) return;
    int p = i % (D / 2);
    int t = i / (D / 2);
    int h = t % H; t /= H;
    int l = t % L;
    int b = t / L;
    float c = fcos[l * (D / 2) + p];
    float s = fsin[l * (D / 2) + p];
#pragma unroll
    for (int sidx = 0; sidx < 2; sidx++) {  // 0=q, 1=k
        size_t base = ((((size_t)b * L + l) * 3 + sidx) * H + h) * D + 2 * p;
        float xr = qkv[base], xi = qkv[base + 1];
        qkv[base]     = xr * c - xi * s;
        qkv[base + 1] = xr * s + xi * c;
    }
}

// out[i] = x[i] + gate * p[i]   (gate from mods, or 1.0 if mods==null)
__global__ void residual_kernel(const float* __restrict__ x,
                                const float* __restrict__ p,
                                const float* __restrict__ mods,  // nullable
                                int gate_off,
                                float* __restrict__ out) {
    size_t i = (size_t)blockIdx.x * blockDim.x + threadIdx.x;
    if (i >= (size_t)BL * C) return;
    float g = 1.f;
    if (mods) {
        int c = (int)(i % C);
        int b = (int)(i / ((size_t)L * C));
        g = mods[(size_t)b * 6 * C + gate_off + c];
    }
    out[i] = x[i] + g * p[i];
}

// h = silu(gate) * up, in-place into gate
__global__ void swiglu_kernel(float* __restrict__ g, const float* __restrict__ u, size_t n) {
    size_t i = (size_t)blockIdx.x * blockDim.x + threadIdx.x;
    if (i >= n) return;
    float v = g[i];
    g[i] = (v / (1.f + __expf(-v))) * u[i];
}

// ---------------- flash attention (one query row per thread) -----------------
// grid: (Lq/64, H, B), block: 64 threads
#define KT 32  // kv tile
__global__ void attn_kernel(const float* __restrict__ qbase,
                            const float* __restrict__ kbase,
                            const float* __restrict__ vbase,
                            float* __restrict__ out,
                            int Lq, int Lk,
                            long q_sb, long q_sl,
                            long k_sb, long k_sl,
                            long v_sb, long v_sl) {
    int qi = blockIdx.x * 64 + threadIdx.x;
    int h = blockIdx.y, b = blockIdx.z;
    const float scale = 0.125f;  // 1/sqrt(64)

    const float* qp = qbase + (size_t)b * q_sb + (size_t)qi * q_sl + h * D;
    float q[D], acc[D];
#pragma unroll
    for (int d = 0; d < D; d++) { q[d] = qp[d]; acc[d] = 0.f; }
    float m = -1e30f, lsum = 0.f;

    __shared__ float Ks[KT * D];
    __shared__ float Vs[KT * D];
    __shared__ float Ps[64][KT + 1];

    for (int k0 = 0; k0 < Lk; k0 += KT) {
        // cooperative load of K,V tiles (coalesced)
        for (int idx = threadIdx.x; idx < KT * D; idx += 64) {
            int r = idx / D, c = idx % D;
            Ks[idx] = kbase[(size_t)b * k_sb + (size_t)(k0 + r) * k_sl + h * D + c];
            Vs[idx] = vbase[(size_t)b * v_sb + (size_t)(k0 + r) * v_sl + h * D + c];
        }
        __syncthreads();

        float mnew = m;
#pragma unroll 1
        for (int j = 0; j < KT; j++) {
            float s = 0.f;
#pragma unroll
            for (int d = 0; d < D; d++) s += q[d] * Ks[j * D + d];
            s *= scale;
            Ps[threadIdx.x][j] = s;
            mnew = fmaxf(mnew, s);
        }
        float corr = __expf(m - mnew);
        lsum *= corr;
#pragma unroll
        for (int d = 0; d < D; d++) acc[d] *= corr;
#pragma unroll 1
        for (int j = 0; j < KT; j++) {
            float pe = __expf(Ps[threadIdx.x][j] - mnew);
            lsum += pe;
#pragma unroll
            for (int d = 0; d < D; d++) acc[d] += pe * Vs[j * D + d];
        }
        m = mnew;
        __syncthreads();
    }

    float invl = 1.f / lsum;
    float* op = out + (((size_t)b * Lq + qi) * H + h) * D;
#pragma unroll
    for (int d = 0; d < D; d++) op[d] = acc[d] * invl;
}

// ---------------- launch ------------------------------------------------------
extern "C" void kernel_launch(void* const* d_in, const int* in_sizes, int n_in,
                              void* d_out, int out_size) {
    const float* x            = (const float*)d_in[0];
    const float* t_mod        = (const float*)d_in[1];
    const float* audio_ctx    = (const float*)d_in[2];
    const float* freqs_cos    = (const float*)d_in[3];
    const float* freqs_sin    = (const float*)d_in[4];
    const float* norm1_w      = (const float*)d_in[5];
    const float* norm2_w      = (const float*)d_in[6];
    const float* norm3_w      = (const float*)d_in[7];
    const float* W_qkv        = (const float*)d_in[8];
    const float* W_sa_out     = (const float*)d_in[9];
    const float* W_q          = (const float*)d_in[10];
    const float* W_kv         = (const float*)d_in[11];
    const float* W_ca_out     = (const float*)d_in[12];
    const float* W_gate       = (const float*)d_in[13];
    const float* W_up         = (const float*)d_in[14];
    const float* W_down       = (const float*)d_in[15];
    const float* adaLN_W      = (const float*)d_in[16];
    const float* adaLN_b      = (const float*)d_in[17];
    float* out = (float*)d_out;

    float *silu_p, *mods_p, *norm_p, *qkv_p, *attn_p, *proj_p, *x_p, *kv_p, *gate_p, *up_p;
    cudaGetSymbolAddress((void**)&silu_p, g_silu);
    cudaGetSymbolAddress((void**)&mods_p, g_mods);
    cudaGetSymbolAddress((void**)&norm_p, g_norm);
    cudaGetSymbolAddress((void**)&qkv_p,  g_qkv);
    cudaGetSymbolAddress((void**)&attn_p, g_attn);
    cudaGetSymbolAddress((void**)&proj_p, g_proj);
    cudaGetSymbolAddress((void**)&x_p,    g_x);
    cudaGetSymbolAddress((void**)&kv_p,   g_kv);
    cudaGetSymbolAddress((void**)&gate_p, g_gate);
    cudaGetSymbolAddress((void**)&up_p,   g_up);

    const size_t NXC = (size_t)BL * C;   // 4M

    // 1) adaLN modulation: mods = silu(t_mod) @ adaLN_W + adaLN_b
    silu_kernel<<<(B * C + 255) / 256, 256>>>(t_mod, silu_p, B * C);
    sgemm(silu_p, adaLN_W, adaLN_b, mods_p, B, 6 * C, C);

    // 2) self-attention branch
    rmsnorm_kernel<<<BL, 256>>>(x, norm1_w, mods_p, /*shift*/0, /*scale*/C, norm_p);
    sgemm(norm_p, W_qkv, nullptr, qkv_p, BL, 3 * C, C);
    {
        int total = B * L * H * (D / 2);
        rope_kernel<<<(total + 255) / 256, 256>>>(qkv_p, freqs_cos, freqs_sin);
    }
    {
        dim3 grid(L / 64, H, B);
        long sl = 3 * C, sb = (long)L * 3 * C;
        attn_kernel<<<grid, 64>>>(qkv_p /*q*/, qkv_p + C /*k*/, qkv_p + 2 * C /*v*/,
                                  attn_p, L, L, sb, sl, sb, sl, sb, sl);
    }
    sgemm(attn_p, W_sa_out, nullptr, proj_p, BL, C, C);
    residual_kernel<<<(NXC + 255) / 256, 256>>>(x, proj_p, mods_p, /*gate_sa*/2 * C, x_p);

    // 3) cross-attention branch
    rmsnorm_kernel<<<BL, 256>>>(x_p, norm2_w, nullptr, 0, 0, norm_p);
    sgemm(norm_p, W_q, nullptr, qkv_p, BL, C, C);          // qc reuses g_qkv
    sgemm(audio_ctx, W_kv, nullptr, kv_p, BL2, 2 * C, TD); // kc,vc
    {
        dim3 grid(L / 64, H, B);
        long q_sl = C, q_sb = (long)L * C;
        long kv_sl = 2 * C, kv_sb = (long)L2 * 2 * C;
        attn_kernel<<<grid, 64>>>(qkv_p, kv_p /*k*/, kv_p + C /*v*/,
                                  attn_p, L, L2, q_sb, q_sl, kv_sb, kv_sl, kv_sb, kv_sl);
    }
    sgemm(attn_p, W_ca_out, nullptr, proj_p, BL, C, C);
    residual_kernel<<<(NXC + 255) / 256, 256>>>(x_p, proj_p, nullptr, 0, x_p);

    // 4) MLP branch
    rmsnorm_kernel<<<BL, 256>>>(x_p, norm3_w, mods_p, /*shift_mlp*/3 * C, /*scale_mlp*/4 * C, norm_p);
    sgemm(norm_p, W_gate, nullptr, gate_p, BL, FF, C);
    sgemm(norm_p, W_up,   nullptr, up_p,   BL, FF, C);
    {
        size_t n = (size_t)BL * FF;
        swiglu_kernel<<<(int)((n + 255) / 256), 256>>>(gate_p, up_p, n);
    }
    sgemm(gate_p, W_down, nullptr, proj_p, BL, C, FF);
    residual_kernel<<<(NXC + 255) / 256, 256>>>(x_p, proj_p, mods_p, /*gate_mlp*/5 * C, out);
}

// round 5
// speedup vs baseline: 1.6050x; 1.5985x over previous
#include <cuda_runtime.h>
#include <cuda_bf16.h>
#include <stdint.h>

#define B 2
#define L 2048
#define C 1024
#define H 16
#define D 64
#define L2 512
#define TD 768
#define FF 4096
#define EPS 1e-6f
#define BL 4096
#define BL2 1024
typedef __nv_bfloat16 bf16;

// ---- scratch ----
__device__ float g_silu[128 * C];
__device__ float g_mods[128 * 6 * C];
__device__ float g_qkv[BL * 3 * C];
__device__ float g_attn[BL * C];
__device__ float g_proj[BL * C];
__device__ float g_x[BL * C];
__device__ float g_kvc[BL2 * 2 * C];
__device__ float g_gate[(size_t)BL * FF];
__device__ float g_up[(size_t)BL * FF];
__device__ bf16 g_ah[(size_t)BL * FF], g_al[(size_t)BL * FF];
__device__ bf16 g_ctxh[BL2 * TD], g_ctxl[BL2 * TD];
__device__ bf16 g_sh[128 * C], g_sl[128 * C];
__device__ bf16 w_qkv_h[3*C*C], w_qkv_l[3*C*C];
__device__ bf16 w_sa_h[C*C], w_sa_l[C*C];
__device__ bf16 w_q_h[C*C], w_q_l[C*C];
__device__ bf16 w_kv_h[2*C*TD], w_kv_l[2*C*TD];
__device__ bf16 w_ca_h[C*C], w_ca_l[C*C];
__device__ bf16 w_g_h[(size_t)C*FF], w_g_l[(size_t)C*FF];
__device__ bf16 w_u_h[(size_t)C*FF], w_u_l[(size_t)C*FF];
__device__ bf16 w_d_h[(size_t)FF*C], w_d_l[(size_t)FF*C];
__device__ bf16 w_ada_h[6*C*C], w_ada_l[6*C*C];

// ---- helpers ----
__device__ __forceinline__ uint32_t smem_u32(const void* p) {
    uint32_t a;
    asm("{ .reg .u64 t; cvta.to.shared.u64 t, %1; cvt.u32.u64 %0, t; }" : "=r"(a) : "l"(p));
    return a;
}
__device__ __forceinline__ void split_bf16(float v, bf16& h, bf16& l) {
    h = __float2bfloat16(v);
    l = __float2bfloat16(v - __bfloat162float(h));
}
__device__ __forceinline__ void fma2(uint64_t& a, uint64_t x, uint64_t y) {
    asm("fma.rn.f32x2 %0, %1, %2, %0;" : "+l"(a) : "l"(x), "l"(y));
}
__device__ __forceinline__ uint64_t pack2(float lo, float hi) {
    uint64_t r; asm("mov.b64 %0, {%1, %2};" : "=l"(r) : "f"(lo), "f"(hi)); return r;
}
__device__ __forceinline__ void unpack2(uint64_t v, float& lo, float& hi) {
    asm("mov.b64 {%0, %1}, %2;" : "=f"(lo), "=f"(hi) : "l"(v));
}
__device__ __forceinline__ void cp16(uint32_t s, const void* g) {
    asm volatile("cp.async.cg.shared.global [%0], [%1], 16;" :: "r"(s), "l"(g));
}
__device__ __forceinline__ void ldsm4(uint32_t* r, uint32_t a) {
    asm volatile("ldmatrix.sync.aligned.m8n8.x4.shared.b16 {%0,%1,%2,%3}, [%4];"
        : "=r"(r[0]), "=r"(r[1]), "=r"(r[2]), "=r"(r[3]) : "r"(a));
}
__device__ __forceinline__ void mma16816(float* d, const uint32_t* a, uint32_t b0, uint32_t b1) {
    asm volatile("mma.sync.aligned.m16n8k16.row.col.f32.bf16.bf16.f32 "
        "{%0,%1,%2,%3}, {%4,%5,%6,%7}, {%8,%9}, {%0,%1,%2,%3};"
        : "+f"(d[0]), "+f"(d[1]), "+f"(d[2]), "+f"(d[3])
        : "r"(a[0]), "r"(a[1]), "r"(a[2]), "r"(a[3]), "r"(b0), "r"(b1));
}

// ---- pipelined bf16 mma.sync GEMM: C[M,N] = (Ah+Al)[M,K] @ (Bh+Bl)[N,K]^T ----
#define NSTAGE 3
#define STGB 32768

__global__ void __launch_bounds__(256) mma_gemm_kernel(
    const bf16* __restrict__ Ah, const bf16* __restrict__ Al,
    const bf16* __restrict__ Bh, const bf16* __restrict__ Bl,
    float* __restrict__ Co, int M, int N, int K)
{
    extern __shared__ char smem[];
    uint32_t sb = smem_u32(smem);
    const int tid = threadIdx.x, lane = tid & 31, wid = tid >> 5;
    const int wm = (wid & 3) << 5, wn = (wid >> 2) << 6;
    const int tM = blockIdx.y << 7, tN = blockIdx.x << 7;
    const bf16* gsrc[4] = {Ah, Al, Bh, Bl};
    const int rb[4] = {tM, tM, tN, tN};

    float acc[2][8][4];
#pragma unroll
    for (int f = 0; f < 2; f++)
#pragma unroll
        for (int n = 0; n < 8; n++)
#pragma unroll
            for (int v = 0; v < 4; v++) acc[f][n][v] = 0.f;

    const int kIters = K >> 5;
    for (int s = 0; s < NSTAGE - 1; s++) {
#pragma unroll
        for (int t = 0; t < 4; t++)
#pragma unroll
            for (int i = 0; i < 2; i++) {
                int id = tid + (i << 8);
                int row = id >> 2, c = id & 3;
                const bf16* g = gsrc[t] + (size_t)(rb[t] + row) * K + (s << 5) + (c << 3);
                cp16(sb + s*STGB + t*8192 + row*64 + ((c ^ (row & 3)) << 4), g);
            }
        asm volatile("cp.async.commit_group;");
    }

    const int lrow = lane & 15, lch = lane >> 4;

    for (int it = 0; it < kIters; it++) {
        asm volatile("cp.async.wait_group 1;");
        __syncthreads();
        if (it + NSTAGE - 1 < kIters) {
            int s = (it + NSTAGE - 1) % NSTAGE, k0 = (it + NSTAGE - 1) << 5;
#pragma unroll
            for (int t = 0; t < 4; t++)
#pragma unroll
                for (int i = 0; i < 2; i++) {
                    int id = tid + (i << 8);
                    int row = id >> 2, c = id & 3;
                    const bf16* g = gsrc[t] + (size_t)(rb[t] + row) * K + k0 + (c << 3);
                    cp16(sb + s*STGB + t*8192 + row*64 + ((c ^ (row & 3)) << 4), g);
                }
        }
        asm volatile("cp.async.commit_group;");

        uint32_t stg = sb + (uint32_t)(it % NSTAGE) * STGB;
#pragma unroll
        for (int pass = 0; pass < 3; pass++) {
            uint32_t ao = stg + ((pass < 2) ? 0u : 8192u);
            uint32_t bo = stg + 16384u + ((pass == 1) ? 8192u : 0u);
#pragma unroll
            for (int ks = 0; ks < 2; ks++) {
                uint32_t a[2][4], b[4][4];
#pragma unroll
                for (int f = 0; f < 2; f++) {
                    int row = wm + (f << 4) + lrow;
                    int ch = (ks << 1) + lch;
                    ldsm4(a[f], ao + row*64 + ((ch ^ (row & 3)) << 4));
                }
#pragma unroll
                for (int p = 0; p < 4; p++) {
                    int row = wn + (p << 4) + lrow;
                    int ch = (ks << 1) + lch;
                    ldsm4(b[p], bo + row*64 + ((ch ^ (row & 3)) << 4));
                }
#pragma unroll
                for (int f = 0; f < 2; f++)
#pragma unroll
                    for (int n = 0; n < 8; n++)
                        mma16816(acc[f][n], a[f], b[n >> 1][n & 1], b[n >> 1][2 + (n & 1)]);
            }
        }
    }

#pragma unroll
    for (int f = 0; f < 2; f++) {
        int r0 = tM + wm + (f << 4) + (lane >> 2);
#pragma unroll
        for (int n = 0; n < 8; n++) {
            int col = tN + wn + (n << 3) + ((lane & 3) << 1);
            float2 v0 = {acc[f][n][0], acc[f][n][1]};
            float2 v1 = {acc[f][n][2], acc[f][n][3]};
            *(float2*)(Co + (size_t)r0 * N + col) = v0;
            *(float2*)(Co + (size_t)(r0 + 8) * N + col) = v1;
        }
    }
}

static inline void mgemm(const bf16* Ah, const bf16* Al, const bf16* Bh, const bf16* Bl,
                         float* Co, int M, int N, int K) {
    cudaFuncSetAttribute(mma_gemm_kernel, cudaFuncAttributeMaxDynamicSharedMemorySize, NSTAGE*STGB);
    mma_gemm_kernel<<<dim3(N/128, M/128), 256, NSTAGE*STGB>>>(Ah, Al, Bh, Bl, Co, M, N, K);
}

// ---- converts ----
__global__ void wconvert_kernel(const float* __restrict__ W, bf16* __restrict__ Th,
                                bf16* __restrict__ Tl, int K, int N) {
    __shared__ float t[32][33];
    int k0 = blockIdx.y * 32, n0 = blockIdx.x * 32;
    int tx = threadIdx.x, ty = threadIdx.y;
#pragma unroll
    for (int i = 0; i < 32; i += 8) t[ty + i][tx] = W[(size_t)(k0 + ty + i) * N + n0 + tx];
    __syncthreads();
#pragma unroll
    for (int i = 0; i < 32; i += 8) {
        bf16 h, l; split_bf16(t[tx][ty + i], h, l);
        size_t o = (size_t)(n0 + ty + i) * K + k0 + tx;
        Th[o] = h; Tl[o] = l;
    }
}
static inline void wconvert(const float* W, bf16* Th, bf16* Tl, int K, int N) {
    wconvert_kernel<<<dim3(N/32, K/32), dim3(32, 8)>>>(W, Th, Tl, K, N);
}
__global__ void aconvert_kernel(const float* __restrict__ a, bf16* __restrict__ h,
                                bf16* __restrict__ l, size_t n) {
    size_t i = (size_t)blockIdx.x * blockDim.x + threadIdx.x;
    if (i >= n) return;
    bf16 hh, ll; split_bf16(a[i], hh, ll);
    h[i] = hh; l[i] = ll;
}

// ---- elementwise ----
__global__ void silu_kernel(const float* __restrict__ in, float* __restrict__ o, int n) {
    int i = blockIdx.x * blockDim.x + threadIdx.x;
    if (i >= n) return;
    float v = in[i];
    o[i] = v / (1.f + __expf(-v));
}
__global__ void rmsnorm_kernel(const float* __restrict__ x, const float* __restrict__ w,
                               const float* __restrict__ mods, const float* __restrict__ bias,
                               int sh_off, int sc_off,
                               bf16* __restrict__ oh, bf16* __restrict__ ol) {
    int row = blockIdx.x, b = row / L;
    const float* xr = x + (size_t)row * C;
    float s = 0.f;
    for (int c = threadIdx.x; c < C; c += blockDim.x) { float v = xr[c]; s += v * v; }
    __shared__ float red[32];
#pragma unroll
    for (int o = 16; o > 0; o >>= 1) s += __shfl_down_sync(0xffffffff, s, o);
    if ((threadIdx.x & 31) == 0) red[threadIdx.x >> 5] = s;
    __syncthreads();
    if (threadIdx.x < 32) {
        float v = (threadIdx.x < (blockDim.x >> 5)) ? red[threadIdx.x] : 0.f;
#pragma unroll
        for (int o = 16; o > 0; o >>= 1) v += __shfl_down_sync(0xffffffff, v, o);
        if (threadIdx.x == 0) red[0] = v;
    }
    __syncthreads();
    float inv = rsqrtf(red[0] / (float)C + EPS);
    for (int c = threadIdx.x; c < C; c += blockDim.x) {
        float n = xr[c] * inv * w[c];
        if (mods) {
            float sc = mods[(size_t)b * 6 * C + sc_off + c] + bias[sc_off + c];
            float sh = mods[(size_t)b * 6 * C + sh_off + c] + bias[sh_off + c];
            n = n * (1.f + sc) + sh;
        }
        bf16 hh, ll; split_bf16(n, hh, ll);
        oh[(size_t)row * C + c] = hh; ol[(size_t)row * C + c] = ll;
    }
}
__global__ void rope_kernel(float* __restrict__ qkv, const float* __restrict__ fc,
                            const float* __restrict__ fs) {
    int i = blockIdx.x * blockDim.x + threadIdx.x;
    if (i >= B * L * H * (D/2)) return;
    int p = i % (D/2), t = i / (D/2);
    int h = t % H; t /= H;
    int l = t % L, b = t / L;
    float c = fc[l * (D/2) + p], s = fs[l * (D/2) + p];
#pragma unroll
    for (int si = 0; si < 2; si++) {
        size_t base = ((((size_t)b * L + l) * 3 + si) * H + h) * D + 2 * p;
        float xr = qkv[base], xi = qkv[base + 1];
        qkv[base] = xr * c - xi * s;
        qkv[base + 1] = xr * s + xi * c;
    }
}
__global__ void residual_kernel(const float* __restrict__ x, const float* __restrict__ p,
                                const float* __restrict__ mods, const float* __restrict__ bias,
                                int g_off, float* __restrict__ out) {
    size_t i = (size_t)blockIdx.x * blockDim.x + threadIdx.x;
    if (i >= (size_t)BL * C) return;
    float g = 1.f;
    if (mods) {
        int c = (int)(i % C), b = (int)(i / ((size_t)L * C));
        g = mods[(size_t)b * 6 * C + g_off + c] + bias[g_off + c];
    }
    out[i] = x[i] + g * p[i];
}
__global__ void swiglu_kernel(const float* __restrict__ g, const float* __restrict__ u,
                              bf16* __restrict__ oh, bf16* __restrict__ ol, size_t n) {
    size_t i = (size_t)blockIdx.x * blockDim.x + threadIdx.x;
    if (i >= n) return;
    float v = g[i];
    float r = (v / (1.f + __expf(-v))) * u[i];
    bf16 hh, ll; split_bf16(r, hh, ll);
    oh[i] = hh; ol[i] = ll;
}

// ---- flash attention (f32x2 packed) ----
#define KT 32
__global__ void attn_kernel(const float* __restrict__ qb, const float* __restrict__ kb,
                            const float* __restrict__ vb, float* __restrict__ out,
                            int Lq, int Lk, long q_sb, long q_sl,
                            long k_sb, long k_sl, long v_sb, long v_sl) {
    int qi = blockIdx.x * 64 + threadIdx.x;
    int h = blockIdx.y, b = blockIdx.z;
    const float* qp = qb + (size_t)b * q_sb + (size_t)qi * q_sl + h * D;
    uint64_t q2[32], a2[32];
#pragma unroll
    for (int d = 0; d < 32; d++) { q2[d] = ((const uint64_t*)qp)[d]; a2[d] = 0ull; }
    float m = -1e30f, lsum = 0.f;
    __shared__ __align__(16) float Ks[KT * D];
    __shared__ __align__(16) float Vs[KT * D];
    __shared__ float Ps[64][KT + 1];

    for (int k0 = 0; k0 < Lk; k0 += KT) {
        for (int idx = threadIdx.x; idx < KT * D; idx += 64) {
            int r = idx / D, c = idx % D;
            Ks[idx] = kb[(size_t)b * k_sb + (size_t)(k0 + r) * k_sl + h * D + c];
            Vs[idx] = vb[(size_t)b * v_sb + (size_t)(k0 + r) * v_sl + h * D + c];
        }
        __syncthreads();
        float mnew = m;
#pragma unroll 1
        for (int j = 0; j < KT; j++) {
            uint64_t s0 = 0, s1 = 0, s2 = 0, s3 = 0;
            const uint64_t* kr = (const uint64_t*)(Ks + j * D);
#pragma unroll
            for (int d = 0; d < 32; d += 4) {
                fma2(s0, q2[d], kr[d]); fma2(s1, q2[d+1], kr[d+1]);
                fma2(s2, q2[d+2], kr[d+2]); fma2(s3, q2[d+3], kr[d+3]);
            }
            float l0, h0, l1, h1, l2, h2, l3, h3;
            unpack2(s0, l0, h0); unpack2(s1, l1, h1); unpack2(s2, l2, h2); unpack2(s3, l3, h3);
            float s = ((l0 + h0) + (l1 + h1) + ((l2 + h2) + (l3 + h3))) * 0.125f;
            Ps[threadIdx.x][j] = s;
            mnew = fmaxf(mnew, s);
        }
        float corr = __expf(m - mnew);
        lsum *= corr;
        uint64_t c2 = pack2(corr, corr);
#pragma unroll
        for (int d = 0; d < 32; d++) { uint64_t t = a2[d]; a2[d] = 0ull; fma2(a2[d], t, c2); }
#pragma unroll 1
        for (int j = 0; j < KT; j++) {
            float pe = __expf(Ps[threadIdx.x][j] - mnew);
            lsum += pe;
            uint64_t p2 = pack2(pe, pe);
            const uint64_t* vr = (const uint64_t*)(Vs + j * D);
#pragma unroll
            for (int d = 0; d < 32; d++) fma2(a2[d], p2, vr[d]);
        }
        m = mnew;
        __syncthreads();
    }
    float invl = 1.f / lsum;
    float* op = out + (((size_t)b * Lq + qi) * H + h) * D;
#pragma unroll
    for (int d = 0; d < 32; d++) {
        float lo, hi; unpack2(a2[d], lo, hi);
        op[2*d] = lo * invl; op[2*d+1] = hi * invl;
    }
}

// ---- launch ----
#define GSYM(p, s) cudaGetSymbolAddress((void**)&p, s)
extern "C" void kernel_launch(void* const* d_in, const int* in_sizes, int n_in,
                              void* d_out, int out_size) {
    const float* x     = (const float*)d_in[0];
    const float* t_mod = (const float*)d_in[1];
    const float* audio = (const float*)d_in[2];
    const float* fcos  = (const float*)d_in[3];
    const float* fsin  = (const float*)d_in[4];
    const float* n1w   = (const float*)d_in[5];
    const float* n2w   = (const float*)d_in[6];
    const float* n3w   = (const float*)d_in[7];
    const float* Wqkv  = (const float*)d_in[8];
    const float* Wsa   = (const float*)d_in[9];
    const float* Wq    = (const float*)d_in[10];
    const float* Wkv   = (const float*)d_in[11];
    const float* Wca   = (const float*)d_in[12];
    const float* Wg    = (const float*)d_in[13];
    const float* Wu    = (const float*)d_in[14];
    const float* Wd    = (const float*)d_in[15];
    const float* adaW  = (const float*)d_in[16];
    const float* adaB  = (const float*)d_in[17];
    float* out = (float*)d_out;

    float *silu_p, *mods_p, *qkv_p, *attn_p, *proj_p, *x_p, *kv_p, *gate_p, *up_p;
    bf16 *ah, *al, *ch, *cl, *sh, *sl;
    bf16 *qkvh, *qkvl, *sah, *sal, *qh, *ql, *kvh, *kvl, *cah, *cal;
    bf16 *gh, *gl, *uh, *ul, *dh, *dl, *adh, *adl;
    GSYM(silu_p, g_silu); GSYM(mods_p, g_mods); GSYM(qkv_p, g_qkv);
    GSYM(attn_p, g_attn); GSYM(proj_p, g_proj); GSYM(x_p, g_x);
    GSYM(kv_p, g_kvc); GSYM(gate_p, g_gate); GSYM(up_p, g_up);
    GSYM(ah, g_ah); GSYM(al, g_al); GSYM(ch, g_ctxh); GSYM(cl, g_ctxl);
    GSYM(sh, g_sh); GSYM(sl, g_sl);
    GSYM(qkvh, w_qkv_h); GSYM(qkvl, w_qkv_l); GSYM(sah, w_sa_h); GSYM(sal, w_sa_l);
    GSYM(qh, w_q_h); GSYM(ql, w_q_l); GSYM(kvh, w_kv_h); GSYM(kvl, w_kv_l);
    GSYM(cah, w_ca_h); GSYM(cal, w_ca_l); GSYM(gh, w_g_h); GSYM(gl, w_g_l);
    GSYM(uh, w_u_h); GSYM(ul, w_u_l); GSYM(dh, w_d_h); GSYM(dl, w_d_l);
    GSYM(adh, w_ada_h); GSYM(adl, w_ada_l);

    const size_t NXC = (size_t)BL * C;
    wconvert(Wqkv, qkvh, qkvl, C, 3*C);
    wconvert(Wsa,  sah,  sal,  C, C);
    wconvert(Wq,   qh,   ql,   C, C);
    wconvert(Wkv,  kvh,  kvl,  TD, 2*C);
    wconvert(Wca,  cah,  cal,  C, C);
    wconvert(Wg,   gh,   gl,   C, FF);
    wconvert(Wu,   uh,   ul,   C, FF);
    wconvert(Wd,   dh,   dl,   FF, C);
    wconvert(adaW, adh,  adl,  C, 6*C);

    // adaLN: mods = silu(t_mod) @ adaW (M padded to 128; bias folded at consumers)
    silu_kernel<<<(B*C + 255)/256, 256>>>(t_mod, silu_p, B*C);
    aconvert_kernel<<<(128*C + 255)/256, 256>>>(silu_p, sh, sl, 128*C);
    mgemm(sh, sl, adh, adl, mods_p, 128, 6*C, C);

    // self-attention
    rmsnorm_kernel<<<BL, 256>>>(x, n1w, mods_p, adaB, 0, C, ah, al);
    mgemm(ah, al, qkvh, qkvl, qkv_p, BL, 3*C, C);
    rope_kernel<<<(B*L*H*(D/2) + 255)/256, 256>>>(qkv_p, fcos, fsin);
    {
        long sl3 = 3*C, sb3 = (long)L*3*C;
        attn_kernel<<<dim3(L/64, H, B), 64>>>(qkv_p, qkv_p + C, qkv_p + 2*C, attn_p,
                                              L, L, sb3, sl3, sb3, sl3, sb3, sl3);
    }
    aconvert_kernel<<<(int)((NXC + 255)/256), 256>>>(attn_p, ah, al, NXC);
    mgemm(ah, al, sah, sal, proj_p, BL, C, C);
    residual_kernel<<<(int)((NXC + 255)/256), 256>>>(x, proj_p, mods_p, adaB, 2*C, x_p);

    // cross-attention
    rmsnorm_kernel<<<BL, 256>>>(x_p, n2w, nullptr, nullptr, 0, 0, ah, al);
    mgemm(ah, al, qh, ql, qkv_p, BL, C, C);
    aconvert_kernel<<<(BL2*TD + 255)/256, 256>>>(audio, ch, cl, (size_t)BL2*TD);
    mgemm(ch, cl, kvh, kvl, kv_p, BL2, 2*C, TD);
    {
        long qsl = C, qsb = (long)L*C, ksl = 2*C, ksb = (long)L2*2*C;
        attn_kernel<<<dim3(L/64, H, B), 64>>>(qkv_p, kv_p, kv_p + C, attn_p,
                                              L, L2, qsb, qsl, ksb, ksl, ksb, ksl);
    }
    aconvert_kernel<<<(int)((NXC + 255)/256), 256>>>(attn_p, ah, al, NXC);
    mgemm(ah, al, cah, cal, proj_p, BL, C, C);
    residual_kernel<<<(int)((NXC + 255)/256), 256>>>(x_p, proj_p, nullptr, nullptr, 0, x_p);

    // MLP
    rmsnorm_kernel<<<BL, 256>>>(x_p, n3w, mods_p, adaB, 3*C, 4*C, ah, al);
    mgemm(ah, al, gh, gl, gate_p, BL, FF, C);
    mgemm(ah, al, uh, ul, up_p, BL, FF, C);
    {
        size_t n = (size_t)BL * FF;
        swiglu_kernel<<<(int)((n + 255)/256), 256>>>(gate_p, up_p, ah, al, n);
    }
    mgemm(ah, al, dh, dl, proj_p, BL, C, FF);
    residual_kernel<<<(int)((NXC + 255)/256), 256>>>(x_p, proj_p, mods_p, adaB, 5*C, out);
}

// round 6
// speedup vs baseline: 1.6920x; 1.0542x over previous
#include <cuda_runtime.h>
#include <cuda_bf16.h>
#include <stdint.h>

#define B 2
#define L 2048
#define C 1024
#define H 16
#define D 64
#define L2 512
#define TD 768
#define FF 4096
#define EPS 1e-6f
#define BL 4096
#define BL2 1024
typedef __nv_bfloat16 bf16;

// ---- scratch ----
__device__ float g_silu[128 * C];
__device__ float g_mods[128 * 6 * C];
__device__ float g_qkv[BL * 3 * C];
__device__ float g_proj[BL * C];
__device__ float g_x[BL * C];
__device__ float g_kvc[BL2 * 2 * C];
__device__ float g_gu[(size_t)BL * 2 * FF];
__device__ bf16 g_ah[(size_t)BL * FF], g_al[(size_t)BL * FF];
__device__ bf16 g_ctxh[BL2 * TD], g_ctxl[BL2 * TD];
__device__ bf16 g_sh[128 * C], g_sl[128 * C];
__device__ bf16 w_qkv_h[3*C*C], w_qkv_l[3*C*C];
__device__ bf16 w_sa_h[C*C], w_sa_l[C*C];
__device__ bf16 w_q_h[C*C], w_q_l[C*C];
__device__ bf16 w_kv_h[2*C*TD], w_kv_l[2*C*TD];
__device__ bf16 w_ca_h[C*C], w_ca_l[C*C];
__device__ bf16 w_gu_h[(size_t)2*FF*C], w_gu_l[(size_t)2*FF*C];
__device__ bf16 w_d_h[(size_t)FF*C], w_d_l[(size_t)FF*C];
__device__ bf16 w_ada_h[6*C*C], w_ada_l[6*C*C];

// ---- helpers ----
__device__ __forceinline__ uint32_t smem_u32(const void* p) {
    uint32_t a;
    asm("{ .reg .u64 t; cvta.to.shared.u64 t, %1; cvt.u32.u64 %0, t; }" : "=r"(a) : "l"(p));
    return a;
}
__device__ __forceinline__ void split_bf16(float v, bf16& h, bf16& l) {
    h = __float2bfloat16(v);
    l = __float2bfloat16(v - __bfloat162float(h));
}
__device__ __forceinline__ void fma2(uint64_t& a, uint64_t x, uint64_t y) {
    asm("fma.rn.f32x2 %0, %1, %2, %0;" : "+l"(a) : "l"(x), "l"(y));
}
__device__ __forceinline__ uint64_t pack2(float lo, float hi) {
    uint64_t r; asm("mov.b64 %0, {%1, %2};" : "=l"(r) : "f"(lo), "f"(hi)); return r;
}
__device__ __forceinline__ void unpack2(uint64_t v, float& lo, float& hi) {
    asm("mov.b64 {%0, %1}, %2;" : "=f"(lo), "=f"(hi) : "l"(v));
}
__device__ __forceinline__ void cp16(uint32_t s, const void* g) {
    asm volatile("cp.async.cg.shared.global [%0], [%1], 16;" :: "r"(s), "l"(g));
}
__device__ __forceinline__ void ldsm4(uint32_t* r, uint32_t a) {
    asm volatile("ldmatrix.sync.aligned.m8n8.x4.shared.b16 {%0,%1,%2,%3}, [%4];"
        : "=r"(r[0]), "=r"(r[1]), "=r"(r[2]), "=r"(r[3]) : "r"(a));
}
__device__ __forceinline__ void mma16816(float* d, const uint32_t* a, uint32_t b0, uint32_t b1) {
    asm volatile("mma.sync.aligned.m16n8k16.row.col.f32.bf16.bf16.f32 "
        "{%0,%1,%2,%3}, {%4,%5,%6,%7}, {%8,%9}, {%0,%1,%2,%3};"
        : "+f"(d[0]), "+f"(d[1]), "+f"(d[2]), "+f"(d[3])
        : "r"(a[0]), "r"(a[1]), "r"(a[2]), "r"(a[3]), "r"(b0), "r"(b1));
}

// ---- pipelined bf16 mma.sync GEMM, tile 128x256, 3-pass hi/lo ----
#define NSTAGE 3
#define STGB 49152   // Ah 8K | Al 8K | Bh 16K | Bl 16K

__global__ void __launch_bounds__(256) mma_gemm_kernel(
    const bf16* __restrict__ Ah, const bf16* __restrict__ Al,
    const bf16* __restrict__ Bh, const bf16* __restrict__ Bl,
    float* __restrict__ Co, int M, int N, int K)
{
    extern __shared__ char smem[];
    uint32_t sb = smem_u32(smem);
    const int tid = threadIdx.x, lane = tid & 31, wid = tid >> 5;
    const int wm = (wid & 1) << 6, wn = (wid >> 1) << 6;
    const int tM = blockIdx.y << 7, tN = blockIdx.x << 8;

    float acc[4][8][4];
#pragma unroll
    for (int f = 0; f < 4; f++)
#pragma unroll
        for (int n = 0; n < 8; n++)
#pragma unroll
            for (int v = 0; v < 4; v++) acc[f][n][v] = 0.f;

    const int kIters = K >> 5;

    // stage loader: 12 cp16/thread (A 1024 ops, B 2048 ops)
    auto load_stage = [&](int s, int k0) {
#pragma unroll
        for (int i = 0; i < 12; i++) {
            int id = tid + (i << 8);
            const bf16* g; uint32_t dst;
            if (id < 1024) {
                int t = id >> 9, a = id & 511;
                int row = a >> 2, c = a & 3;
                g = (t ? Al : Ah) + (size_t)(tM + row) * K + k0 + (c << 3);
                dst = sb + s * STGB + t * 8192 + row * 64 + ((c ^ (row & 3)) << 4);
            } else {
                int t = (id - 1024) >> 10, a = (id - 1024) & 1023;
                int row = a >> 2, c = a & 3;
                g = (t ? Bl : Bh) + (size_t)(tN + row) * K + k0 + (c << 3);
                dst = sb + s * STGB + 16384 + t * 16384 + row * 64 + ((c ^ (row & 3)) << 4);
            }
            cp16(dst, g);
        }
    };

    for (int s = 0; s < NSTAGE - 1; s++) {
        load_stage(s, s << 5);
        asm volatile("cp.async.commit_group;");
    }

    const int lrow = lane & 15, lch = lane >> 4;

    for (int it = 0; it < kIters; it++) {
        asm volatile("cp.async.wait_group 1;");
        __syncthreads();
        if (it + NSTAGE - 1 < kIters)
            load_stage((it + NSTAGE - 1) % NSTAGE, (it + NSTAGE - 1) << 5);
        asm volatile("cp.async.commit_group;");

        uint32_t stg = sb + (uint32_t)(it % NSTAGE) * STGB;
#pragma unroll
        for (int pass = 0; pass < 3; pass++) {
            uint32_t ao = stg + ((pass < 2) ? 0u : 8192u);
            uint32_t bo = stg + 16384u + ((pass == 1) ? 16384u : 0u);
#pragma unroll
            for (int ks = 0; ks < 2; ks++) {
                uint32_t a[4][4], b[4][4];
                int ch = (ks << 1) + lch;
#pragma unroll
                for (int f = 0; f < 4; f++) {
                    int row = wm + (f << 4) + lrow;
                    ldsm4(a[f], ao + row * 64 + ((ch ^ (row & 3)) << 4));
                }
#pragma unroll
                for (int p = 0; p < 4; p++) {
                    int row = wn + (p << 4) + lrow;
                    ldsm4(b[p], bo + row * 64 + ((ch ^ (row & 3)) << 4));
                }
#pragma unroll
                for (int f = 0; f < 4; f++)
#pragma unroll
                    for (int n = 0; n < 8; n++)
                        mma16816(acc[f][n], a[f], b[n >> 1][n & 1], b[n >> 1][2 + (n & 1)]);
            }
        }
    }

#pragma unroll
    for (int f = 0; f < 4; f++) {
        int r0 = tM + wm + (f << 4) + (lane >> 2);
#pragma unroll
        for (int n = 0; n < 8; n++) {
            int col = tN + wn + (n << 3) + ((lane & 3) << 1);
            float2 v0 = {acc[f][n][0], acc[f][n][1]};
            float2 v1 = {acc[f][n][2], acc[f][n][3]};
            *(float2*)(Co + (size_t)r0 * N + col) = v0;
            *(float2*)(Co + (size_t)(r0 + 8) * N + col) = v1;
        }
    }
}

static inline void mgemm(const bf16* Ah, const bf16* Al, const bf16* Bh, const bf16* Bl,
                         float* Co, int M, int N, int K) {
    cudaFuncSetAttribute(mma_gemm_kernel, cudaFuncAttributeMaxDynamicSharedMemorySize, NSTAGE*STGB);
    mma_gemm_kernel<<<dim3(N/256, M/128), 256, NSTAGE*STGB>>>(Ah, Al, Bh, Bl, Co, M, N, K);
}

// ---- converts ----
__global__ void wconvert_kernel(const float* __restrict__ W, bf16* __restrict__ Th,
                                bf16* __restrict__ Tl, int K, int N) {
    __shared__ float t[32][33];
    int k0 = blockIdx.y * 32, n0 = blockIdx.x * 32;
    int tx = threadIdx.x, ty = threadIdx.y;
#pragma unroll
    for (int i = 0; i < 32; i += 8) t[ty + i][tx] = W[(size_t)(k0 + ty + i) * N + n0 + tx];
    __syncthreads();
#pragma unroll
    for (int i = 0; i < 32; i += 8) {
        bf16 h, l; split_bf16(t[tx][ty + i], h, l);
        size_t o = (size_t)(n0 + ty + i) * K + k0 + tx;
        Th[o] = h; Tl[o] = l;
    }
}
static inline void wconvert(const float* W, bf16* Th, bf16* Tl, int K, int N) {
    wconvert_kernel<<<dim3(N/32, K/32), dim3(32, 8)>>>(W, Th, Tl, K, N);
}
__global__ void aconvert_kernel(const float* __restrict__ a, bf16* __restrict__ h,
                                bf16* __restrict__ l, size_t n) {
    size_t i = (size_t)blockIdx.x * blockDim.x + threadIdx.x;
    if (i >= n) return;
    bf16 hh, ll; split_bf16(a[i], hh, ll);
    h[i] = hh; l[i] = ll;
}

// ---- elementwise ----
__global__ void silu_kernel(const float* __restrict__ in, float* __restrict__ o, int n) {
    int i = blockIdx.x * blockDim.x + threadIdx.x;
    if (i >= n) return;
    float v = in[i];
    o[i] = v / (1.f + __expf(-v));
}
__global__ void rmsnorm_kernel(const float* __restrict__ x, const float* __restrict__ w,
                               const float* __restrict__ mods, const float* __restrict__ bias,
                               int sh_off, int sc_off,
                               bf16* __restrict__ oh, bf16* __restrict__ ol) {
    int row = blockIdx.x, b = row / L;
    const float* xr = x + (size_t)row * C;
    float s = 0.f;
    for (int c = threadIdx.x; c < C; c += blockDim.x) { float v = xr[c]; s += v * v; }
    __shared__ float red[32];
#pragma unroll
    for (int o = 16; o > 0; o >>= 1) s += __shfl_down_sync(0xffffffff, s, o);
    if ((threadIdx.x & 31) == 0) red[threadIdx.x >> 5] = s;
    __syncthreads();
    if (threadIdx.x < 32) {
        float v = (threadIdx.x < (blockDim.x >> 5)) ? red[threadIdx.x] : 0.f;
#pragma unroll
        for (int o = 16; o > 0; o >>= 1) v += __shfl_down_sync(0xffffffff, v, o);
        if (threadIdx.x == 0) red[0] = v;
    }
    __syncthreads();
    float inv = rsqrtf(red[0] / (float)C + EPS);
    for (int c = threadIdx.x; c < C; c += blockDim.x) {
        float n = xr[c] * inv * w[c];
        if (mods) {
            float sc = mods[(size_t)b * 6 * C + sc_off + c] + bias[sc_off + c];
            float sh = mods[(size_t)b * 6 * C + sh_off + c] + bias[sh_off + c];
            n = n * (1.f + sc) + sh;
        }
        bf16 hh, ll; split_bf16(n, hh, ll);
        oh[(size_t)row * C + c] = hh; ol[(size_t)row * C + c] = ll;
    }
}
__global__ void rope_kernel(float* __restrict__ qkv, const float* __restrict__ fc,
                            const float* __restrict__ fs) {
    int i = blockIdx.x * blockDim.x + threadIdx.x;
    if (i >= B * L * H * (D/2)) return;
    int p = i % (D/2), t = i / (D/2);
    int h = t % H; t /= H;
    int l = t % L, b = t / L;
    float c = fc[l * (D/2) + p], s = fs[l * (D/2) + p];
#pragma unroll
    for (int si = 0; si < 2; si++) {
        size_t base = ((((size_t)b * L + l) * 3 + si) * H + h) * D + 2 * p;
        float xr = qkv[base], xi = qkv[base + 1];
        qkv[base] = xr * c - xi * s;
        qkv[base + 1] = xr * s + xi * c;
    }
}
__global__ void residual_kernel(const float* __restrict__ x, const float* __restrict__ p,
                                const float* __restrict__ mods, const float* __restrict__ bias,
                                int g_off, float* __restrict__ out) {
    size_t i = (size_t)blockIdx.x * blockDim.x + threadIdx.x;
    if (i >= (size_t)BL * C) return;
    float g = 1.f;
    if (mods) {
        int c = (int)(i % C), b = (int)(i / ((size_t)L * C));
        g = mods[(size_t)b * 6 * C + g_off + c] + bias[g_off + c];
    }
    out[i] = x[i] + g * p[i];
}
// gu: [BL][2*FF] with gate in cols [0,FF), up in cols [FF,2FF)
__global__ void swiglu_kernel(const float* __restrict__ gu,
                              bf16* __restrict__ oh, bf16* __restrict__ ol, size_t n) {
    size_t i = (size_t)blockIdx.x * blockDim.x + threadIdx.x;
    if (i >= n) return;
    size_t row = i >> 12, c = i & (FF - 1);
    float v = gu[(row << 13) + c];
    float u = gu[(row << 13) + FF + c];
    float r = (v / (1.f + __expf(-v))) * u;
    bf16 hh, ll; split_bf16(r, hh, ll);
    oh[i] = hh; ol[i] = ll;
}

// ---- flash attention (f32x2 packed), writes hi/lo bf16 directly ----
#define KT 32
__global__ void attn_kernel(const float* __restrict__ qb, const float* __restrict__ kb,
                            const float* __restrict__ vb,
                            bf16* __restrict__ oh, bf16* __restrict__ ol,
                            int Lq, int Lk, long q_sb, long q_sl,
                            long k_sb, long k_sl, long v_sb, long v_sl) {
    int qi = blockIdx.x * 64 + threadIdx.x;
    int h = blockIdx.y, b = blockIdx.z;
    const float* qp = qb + (size_t)b * q_sb + (size_t)qi * q_sl + h * D;
    uint64_t q2[32], a2[32];
#pragma unroll
    for (int d = 0; d < 32; d++) { q2[d] = ((const uint64_t*)qp)[d]; a2[d] = 0ull; }
    float m = -1e30f, lsum = 0.f;
    __shared__ __align__(16) float Ks[KT * D];
    __shared__ __align__(16) float Vs[KT * D];
    __shared__ float Ps[64][KT + 1];

    for (int k0 = 0; k0 < Lk; k0 += KT) {
        for (int idx = threadIdx.x; idx < KT * D; idx += 64) {
            int r = idx / D, c = idx % D;
            Ks[idx] = kb[(size_t)b * k_sb + (size_t)(k0 + r) * k_sl + h * D + c];
            Vs[idx] = vb[(size_t)b * v_sb + (size_t)(k0 + r) * v_sl + h * D + c];
        }
        __syncthreads();
        float mnew = m;
#pragma unroll 1
        for (int j = 0; j < KT; j++) {
            uint64_t s0 = 0, s1 = 0, s2 = 0, s3 = 0;
            const uint64_t* kr = (const uint64_t*)(Ks + j * D);
#pragma unroll
            for (int d = 0; d < 32; d += 4) {
                fma2(s0, q2[d], kr[d]); fma2(s1, q2[d+1], kr[d+1]);
                fma2(s2, q2[d+2], kr[d+2]); fma2(s3, q2[d+3], kr[d+3]);
            }
            float l0, h0, l1, h1, l2, h2, l3, h3;
            unpack2(s0, l0, h0); unpack2(s1, l1, h1); unpack2(s2, l2, h2); unpack2(s3, l3, h3);
            float s = ((l0 + h0) + (l1 + h1) + ((l2 + h2) + (l3 + h3))) * 0.125f;
            Ps[threadIdx.x][j] = s;
            mnew = fmaxf(mnew, s);
        }
        float corr = __expf(m - mnew);
        lsum *= corr;
        uint64_t c2 = pack2(corr, corr);
#pragma unroll
        for (int d = 0; d < 32; d++) { uint64_t t = a2[d]; a2[d] = 0ull; fma2(a2[d], t, c2); }
#pragma unroll 1
        for (int j = 0; j < KT; j++) {
            float pe = __expf(Ps[threadIdx.x][j] - mnew);
            lsum += pe;
            uint64_t p2 = pack2(pe, pe);
            const uint64_t* vr = (const uint64_t*)(Vs + j * D);
#pragma unroll
            for (int d = 0; d < 32; d++) fma2(a2[d], p2, vr[d]);
        }
        m = mnew;
        __syncthreads();
    }
    float invl = 1.f / lsum;
    size_t ob = ((size_t)((size_t)b * Lq + qi) * H + h) * D;
#pragma unroll
    for (int d = 0; d < 32; d++) {
        float lo, hi; unpack2(a2[d], lo, hi);
        bf16 hh, ll;
        split_bf16(lo * invl, hh, ll); oh[ob + 2*d] = hh;   ol[ob + 2*d] = ll;
        split_bf16(hi * invl, hh, ll); oh[ob + 2*d+1] = hh; ol[ob + 2*d+1] = ll;
    }
}

// ---- launch ----
#define GSYM(p, s) cudaGetSymbolAddress((void**)&p, s)
extern "C" void kernel_launch(void* const* d_in, const int* in_sizes, int n_in,
                              void* d_out, int out_size) {
    const float* x     = (const float*)d_in[0];
    const float* t_mod = (const float*)d_in[1];
    const float* audio = (const float*)d_in[2];
    const float* fcos  = (const float*)d_in[3];
    const float* fsin  = (const float*)d_in[4];
    const float* n1w   = (const float*)d_in[5];
    const float* n2w   = (const float*)d_in[6];
    const float* n3w   = (const float*)d_in[7];
    const float* Wqkv  = (const float*)d_in[8];
    const float* Wsa   = (const float*)d_in[9];
    const float* Wq    = (const float*)d_in[10];
    const float* Wkv   = (const float*)d_in[11];
    const float* Wca   = (const float*)d_in[12];
    const float* Wg    = (const float*)d_in[13];
    const float* Wu    = (const float*)d_in[14];
    const float* Wd    = (const float*)d_in[15];
    const float* adaW  = (const float*)d_in[16];
    const float* adaB  = (const float*)d_in[17];
    float* out = (float*)d_out;

    float *silu_p, *mods_p, *qkv_p, *proj_p, *x_p, *kv_p, *gu_p;
    bf16 *ah, *al, *ch, *cl, *sh, *sl;
    bf16 *qkvh, *qkvl, *sah, *sal, *qh, *ql, *kvh, *kvl, *cah, *cal;
    bf16 *guh, *gul, *dh, *dl, *adh, *adl;
    GSYM(silu_p, g_silu); GSYM(mods_p, g_mods); GSYM(qkv_p, g_qkv);
    GSYM(proj_p, g_proj); GSYM(x_p, g_x); GSYM(kv_p, g_kvc); GSYM(gu_p, g_gu);
    GSYM(ah, g_ah); GSYM(al, g_al); GSYM(ch, g_ctxh); GSYM(cl, g_ctxl);
    GSYM(sh, g_sh); GSYM(sl, g_sl);
    GSYM(qkvh, w_qkv_h); GSYM(qkvl, w_qkv_l); GSYM(sah, w_sa_h); GSYM(sal, w_sa_l);
    GSYM(qh, w_q_h); GSYM(ql, w_q_l); GSYM(kvh, w_kv_h); GSYM(kvl, w_kv_l);
    GSYM(cah, w_ca_h); GSYM(cal, w_ca_l); GSYM(guh, w_gu_h); GSYM(gul, w_gu_l);
    GSYM(dh, w_d_h); GSYM(dl, w_d_l); GSYM(adh, w_ada_h); GSYM(adl, w_ada_l);

    const size_t NXC = (size_t)BL * C;
    wconvert(Wqkv, qkvh, qkvl, C, 3*C);
    wconvert(Wsa,  sah,  sal,  C, C);
    wconvert(Wq,   qh,   ql,   C, C);
    wconvert(Wkv,  kvh,  kvl,  TD, 2*C);
    wconvert(Wca,  cah,  cal,  C, C);
    wconvert(Wg,   guh,             gul,             C, FF);      // rows [0,FF)
    wconvert(Wu,   guh + (size_t)FF*C, gul + (size_t)FF*C, C, FF); // rows [FF,2FF)
    wconvert(Wd,   dh,   dl,   FF, C);
    wconvert(adaW, adh,  adl,  C, 6*C);

    // adaLN: mods = silu(t_mod) @ adaW  (M padded to 128; bias folded at consumers)
    silu_kernel<<<(B*C + 255)/256, 256>>>(t_mod, silu_p, B*C);
    aconvert_kernel<<<(128*C + 255)/256, 256>>>(silu_p, sh, sl, 128*C);
    mgemm(sh, sl, adh, adl, mods_p, 128, 6*C, C);

    // self-attention
    rmsnorm_kernel<<<BL, 256>>>(x, n1w, mods_p, adaB, 0, C, ah, al);
    mgemm(ah, al, qkvh, qkvl, qkv_p, BL, 3*C, C);
    rope_kernel<<<(B*L*H*(D/2) + 255)/256, 256>>>(qkv_p, fcos, fsin);
    {
        long sl3 = 3*C, sb3 = (long)L*3*C;
        attn_kernel<<<dim3(L/64, H, B), 64>>>(qkv_p, qkv_p + C, qkv_p + 2*C, ah, al,
                                              L, L, sb3, sl3, sb3, sl3, sb3, sl3);
    }
    mgemm(ah, al, sah, sal, proj_p, BL, C, C);
    residual_kernel<<<(int)((NXC + 255)/256), 256>>>(x, proj_p, mods_p, adaB, 2*C, x_p);

    // cross-attention
    rmsnorm_kernel<<<BL, 256>>>(x_p, n2w, nullptr, nullptr, 0, 0, ah, al);
    mgemm(ah, al, qh, ql, qkv_p, BL, C, C);
    aconvert_kernel<<<(BL2*TD + 255)/256, 256>>>(audio, ch, cl, (size_t)BL2*TD);
    mgemm(ch, cl, kvh, kvl, kv_p, BL2, 2*C, TD);
    {
        long qsl = C, qsb = (long)L*C, ksl = 2*C, ksb = (long)L2*2*C;
        attn_kernel<<<dim3(L/64, H, B), 64>>>(qkv_p, kv_p, kv_p + C, ah, al,
                                              L, L2, qsb, qsl, ksb, ksl, ksb, ksl);
    }
    mgemm(ah, al, cah, cal, proj_p, BL, C, C);
    residual_kernel<<<(int)((NXC + 255)/256), 256>>>(x_p, proj_p, nullptr, nullptr, 0, x_p);

    // MLP (gate+up fused into one GEMM, N=2*FF)
    rmsnorm_kernel<<<BL, 256>>>(x_p, n3w, mods_p, adaB, 3*C, 4*C, ah, al);
    mgemm(ah, al, guh, gul, gu_p, BL, 2*FF, C);
    {
        size_t n = (size_t)BL * FF;
        swiglu_kernel<<<(int)((n + 255)/256), 256>>>(gu_p, ah, al, n);
    }
    mgemm(ah, al, dh, dl, proj_p, BL, C, FF);
    residual_kernel<<<(int)((NXC + 255)/256), 256>>>(x_p, proj_p, mods_p, adaB, 5*C, out);
}

// round 7
// speedup vs baseline: 1.9518x; 1.1535x over previous
#include <cuda_runtime.h>
#include <cuda_fp16.h>
#include <stdint.h>

#define B 2
#define L 2048
#define C 1024
#define H 16
#define D 64
#define L2 512
#define TD 768
#define FF 4096
#define EPS 1e-6f
#define BL 4096
#define BL2 1024

// ---- scratch ----
__device__ float g_silu[128 * C];
__device__ float g_mods[128 * 6 * C];
__device__ float g_qkv[BL * 3 * C];
__device__ float g_proj[BL * C];
__device__ float g_x[BL * C];
__device__ float g_kvc[BL2 * 2 * C];
__device__ float g_gu[(size_t)BL * 2 * FF];
__device__ half g_act[(size_t)BL * FF];      // activation A operand (single fp16)
__device__ half g_ctx[BL2 * TD];
__device__ half g_sm[128 * C];
__device__ half w_qkv_h[3*C*C], w_qkv_l[3*C*C];
__device__ half w_sa_h[C*C], w_sa_l[C*C];
__device__ half w_q_h[C*C], w_q_l[C*C];
__device__ half w_kv_h[2*C*TD], w_kv_l[2*C*TD];
__device__ half w_ca_h[C*C], w_ca_l[C*C];
__device__ half w_gu_h[(size_t)2*FF*C], w_gu_l[(size_t)2*FF*C];
__device__ half w_d_h[(size_t)FF*C], w_d_l[(size_t)FF*C];
__device__ half w_ada_h[6*C*C], w_ada_l[6*C*C];

// ---- helpers ----
__device__ __forceinline__ uint32_t smem_u32(const void* p) {
    uint32_t a;
    asm("{ .reg .u64 t; cvta.to.shared.u64 t, %1; cvt.u32.u64 %0, t; }" : "=r"(a) : "l"(p));
    return a;
}
__device__ __forceinline__ void split_half(float v, half& h, half& l) {
    h = __float2half(v);
    l = __float2half(v - __half2float(h));
}
__device__ __forceinline__ void fma2(uint64_t& a, uint64_t x, uint64_t y) {
    asm("fma.rn.f32x2 %0, %1, %2, %0;" : "+l"(a) : "l"(x), "l"(y));
}
__device__ __forceinline__ uint64_t pack2(float lo, float hi) {
    uint64_t r; asm("mov.b64 %0, {%1, %2};" : "=l"(r) : "f"(lo), "f"(hi)); return r;
}
__device__ __forceinline__ void unpack2(uint64_t v, float& lo, float& hi) {
    asm("mov.b64 {%0, %1}, %2;" : "=f"(lo), "=f"(hi) : "l"(v));
}
__device__ __forceinline__ void cp16(uint32_t s, const void* g) {
    asm volatile("cp.async.cg.shared.global [%0], [%1], 16;" :: "r"(s), "l"(g));
}
__device__ __forceinline__ void ldsm4(uint32_t* r, uint32_t a) {
    asm volatile("ldmatrix.sync.aligned.m8n8.x4.shared.b16 {%0,%1,%2,%3}, [%4];"
        : "=r"(r[0]), "=r"(r[1]), "=r"(r[2]), "=r"(r[3]) : "r"(a));
}
__device__ __forceinline__ void mma16816(float* d, const uint32_t* a, uint32_t b0, uint32_t b1) {
    asm volatile("mma.sync.aligned.m16n8k16.row.col.f32.f16.f16.f32 "
        "{%0,%1,%2,%3}, {%4,%5,%6,%7}, {%8,%9}, {%0,%1,%2,%3};"
        : "+f"(d[0]), "+f"(d[1]), "+f"(d[2]), "+f"(d[3])
        : "r"(a[0]), "r"(a[1]), "r"(a[2]), "r"(a[3]), "r"(b0), "r"(b1));
}

// ---- pipelined fp16 mma.sync GEMM, tile 128x256, 2-pass (A single, B hi/lo) ----
#define NSTAGE 3
#define STGB 40960   // A 8K | Bh 16K | Bl 16K

__global__ void __launch_bounds__(256) mma_gemm_kernel(
    const half* __restrict__ Ax,
    const half* __restrict__ Bh, const half* __restrict__ Bl,
    float* __restrict__ Co, int M, int N, int K)
{
    extern __shared__ char smem[];
    uint32_t sb = smem_u32(smem);
    const int tid = threadIdx.x, lane = tid & 31, wid = tid >> 5;
    const int wm = (wid & 1) << 6, wn = (wid >> 1) << 6;
    const int tM = blockIdx.y << 7, tN = blockIdx.x << 8;

    float acc[4][8][4];
#pragma unroll
    for (int f = 0; f < 4; f++)
#pragma unroll
        for (int n = 0; n < 8; n++)
#pragma unroll
            for (int v = 0; v < 4; v++) acc[f][n][v] = 0.f;

    const int kIters = K >> 5;

    auto load_stage = [&](int s, int k0) {
#pragma unroll
        for (int i = 0; i < 10; i++) {
            int id = tid + (i << 8);
            const half* g; uint32_t dst;
            if (id < 512) {
                int row = id >> 2, c = id & 3;
                g = Ax + (size_t)(tM + row) * K + k0 + (c << 3);
                dst = sb + s * STGB + row * 64 + ((c ^ (row & 3)) << 4);
            } else {
                int idB = id - 512;
                int t = idB >> 10, a = idB & 1023;
                int row = a >> 2, c = a & 3;
                g = (t ? Bl : Bh) + (size_t)(tN + row) * K + k0 + (c << 3);
                dst = sb + s * STGB + 8192 + t * 16384 + row * 64 + ((c ^ (row & 3)) << 4);
            }
            cp16(dst, g);
        }
    };

    for (int s = 0; s < NSTAGE - 1; s++) {
        load_stage(s, s << 5);
        asm volatile("cp.async.commit_group;");
    }

    const int lrow = lane & 15, lch = lane >> 4;

    for (int it = 0; it < kIters; it++) {
        asm volatile("cp.async.wait_group 1;");
        __syncthreads();
        if (it + NSTAGE - 1 < kIters)
            load_stage((it + NSTAGE - 1) % NSTAGE, (it + NSTAGE - 1) << 5);
        asm volatile("cp.async.commit_group;");

        uint32_t stg = sb + (uint32_t)(it % NSTAGE) * STGB;
#pragma unroll
        for (int ks = 0; ks < 2; ks++) {
            int ch = (ks << 1) + lch;
            uint32_t a[4][4];
#pragma unroll
            for (int f = 0; f < 4; f++) {
                int row = wm + (f << 4) + lrow;
                ldsm4(a[f], stg + row * 64 + ((ch ^ (row & 3)) << 4));
            }
#pragma unroll
            for (int pass = 0; pass < 2; pass++) {
                uint32_t bo = stg + 8192u + (uint32_t)pass * 16384u;
                uint32_t b[4][4];
#pragma unroll
                for (int p = 0; p < 4; p++) {
                    int row = wn + (p << 4) + lrow;
                    ldsm4(b[p], bo + row * 64 + ((ch ^ (row & 3)) << 4));
                }
#pragma unroll
                for (int f = 0; f < 4; f++)
#pragma unroll
                    for (int n = 0; n < 8; n++)
                        mma16816(acc[f][n], a[f], b[n >> 1][n & 1], b[n >> 1][2 + (n & 1)]);
            }
        }
    }

#pragma unroll
    for (int f = 0; f < 4; f++) {
        int r0 = tM + wm + (f << 4) + (lane >> 2);
#pragma unroll
        for (int n = 0; n < 8; n++) {
            int col = tN + wn + (n << 3) + ((lane & 3) << 1);
            float2 v0 = {acc[f][n][0], acc[f][n][1]};
            float2 v1 = {acc[f][n][2], acc[f][n][3]};
            *(float2*)(Co + (size_t)r0 * N + col) = v0;
            *(float2*)(Co + (size_t)(r0 + 8) * N + col) = v1;
        }
    }
}

static inline void mgemm(const half* Ax, const half* Bh, const half* Bl,
                         float* Co, int M, int N, int K) {
    cudaFuncSetAttribute(mma_gemm_kernel, cudaFuncAttributeMaxDynamicSharedMemorySize, NSTAGE*STGB);
    mma_gemm_kernel<<<dim3(N/256, M/128), 256, NSTAGE*STGB>>>(Ax, Bh, Bl, Co, M, N, K);
}

// ---- converts ----
__global__ void wconvert_kernel(const float* __restrict__ W, half* __restrict__ Th,
                                half* __restrict__ Tl, int K, int N) {
    __shared__ float t[32][33];
    int k0 = blockIdx.y * 32, n0 = blockIdx.x * 32;
    int tx = threadIdx.x, ty = threadIdx.y;
#pragma unroll
    for (int i = 0; i < 32; i += 8) t[ty + i][tx] = W[(size_t)(k0 + ty + i) * N + n0 + tx];
    __syncthreads();
#pragma unroll
    for (int i = 0; i < 32; i += 8) {
        half h, l; split_half(t[tx][ty + i], h, l);
        size_t o = (size_t)(n0 + ty + i) * K + k0 + tx;
        Th[o] = h; Tl[o] = l;
    }
}
static inline void wconvert(const float* W, half* Th, half* Tl, int K, int N) {
    wconvert_kernel<<<dim3(N/32, K/32), dim3(32, 8)>>>(W, Th, Tl, K, N);
}
__global__ void aconvert_kernel(const float* __restrict__ a, half* __restrict__ o, size_t n) {
    size_t i = (size_t)blockIdx.x * blockDim.x + threadIdx.x;
    if (i >= n) return;
    o[i] = __float2half(a[i]);
}

// ---- elementwise ----
__global__ void silu_kernel(const float* __restrict__ in, float* __restrict__ o, int n) {
    int i = blockIdx.x * blockDim.x + threadIdx.x;
    if (i >= n) return;
    float v = in[i];
    o[i] = v / (1.f + __expf(-v));
}
__global__ void rmsnorm_kernel(const float* __restrict__ x, const float* __restrict__ w,
                               const float* __restrict__ mods, const float* __restrict__ bias,
                               int sh_off, int sc_off, half* __restrict__ o) {
    int row = blockIdx.x, b = row / L;
    const float* xr = x + (size_t)row * C;
    float s = 0.f;
    for (int c = threadIdx.x; c < C; c += blockDim.x) { float v = xr[c]; s += v * v; }
    __shared__ float red[32];
#pragma unroll
    for (int o2 = 16; o2 > 0; o2 >>= 1) s += __shfl_down_sync(0xffffffff, s, o2);
    if ((threadIdx.x & 31) == 0) red[threadIdx.x >> 5] = s;
    __syncthreads();
    if (threadIdx.x < 32) {
        float v = (threadIdx.x < (blockDim.x >> 5)) ? red[threadIdx.x] : 0.f;
#pragma unroll
        for (int o2 = 16; o2 > 0; o2 >>= 1) v += __shfl_down_sync(0xffffffff, v, o2);
        if (threadIdx.x == 0) red[0] = v;
    }
    __syncthreads();
    float inv = rsqrtf(red[0] / (float)C + EPS);
    for (int c = threadIdx.x; c < C; c += blockDim.x) {
        float n = xr[c] * inv * w[c];
        if (mods) {
            float sc = mods[(size_t)b * 6 * C + sc_off + c] + bias[sc_off + c];
            float sh = mods[(size_t)b * 6 * C + sh_off + c] + bias[sh_off + c];
            n = n * (1.f + sc) + sh;
        }
        o[(size_t)row * C + c] = __float2half(n);
    }
}
__global__ void rope_kernel(float* __restrict__ qkv, const float* __restrict__ fc,
                            const float* __restrict__ fs) {
    int i = blockIdx.x * blockDim.x + threadIdx.x;
    if (i >= B * L * H * (D/2)) return;
    int p = i % (D/2), t = i / (D/2);
    int h = t % H; t /= H;
    int l = t % L, b = t / L;
    float c = fc[l * (D/2) + p], s = fs[l * (D/2) + p];
#pragma unroll
    for (int si = 0; si < 2; si++) {
        size_t base = ((((size_t)b * L + l) * 3 + si) * H + h) * D + 2 * p;
        float xr = qkv[base], xi = qkv[base + 1];
        qkv[base] = xr * c - xi * s;
        qkv[base + 1] = xr * s + xi * c;
    }
}
__global__ void residual_kernel(const float* __restrict__ x, const float* __restrict__ p,
                                const float* __restrict__ mods, const float* __restrict__ bias,
                                int g_off, float* __restrict__ out) {
    size_t i = (size_t)blockIdx.x * blockDim.x + threadIdx.x;
    if (i >= (size_t)BL * C) return;
    float g = 1.f;
    if (mods) {
        int c = (int)(i % C), b = (int)(i / ((size_t)L * C));
        g = mods[(size_t)b * 6 * C + g_off + c] + bias[g_off + c];
    }
    out[i] = x[i] + g * p[i];
}
// gu: [BL][2*FF] gate cols [0,FF), up cols [FF,2FF)
__global__ void swiglu_kernel(const float* __restrict__ gu, half* __restrict__ o, size_t n) {
    size_t i = (size_t)blockIdx.x * blockDim.x + threadIdx.x;
    if (i >= n) return;
    size_t row = i >> 12, c = i & (FF - 1);
    float v = gu[(row << 13) + c];
    float u = gu[(row << 13) + FF + c];
    o[i] = __float2half((v / (1.f + __expf(-v))) * u);
}

// ---- flash attention (f32x2 packed), writes fp16 directly ----
#define KT 32
__global__ void attn_kernel(const float* __restrict__ qb, const float* __restrict__ kb,
                            const float* __restrict__ vb, half* __restrict__ oh,
                            int Lq, int Lk, long q_sb, long q_sl,
                            long k_sb, long k_sl, long v_sb, long v_sl) {
    int qi = blockIdx.x * 64 + threadIdx.x;
    int h = blockIdx.y, b = blockIdx.z;
    const float* qp = qb + (size_t)b * q_sb + (size_t)qi * q_sl + h * D;
    uint64_t q2[32], a2[32];
#pragma unroll
    for (int d = 0; d < 32; d++) { q2[d] = ((const uint64_t*)qp)[d]; a2[d] = 0ull; }
    float m = -1e30f, lsum = 0.f;
    __shared__ __align__(16) float Ks[KT * D];
    __shared__ __align__(16) float Vs[KT * D];
    __shared__ float Ps[64][KT + 1];

    for (int k0 = 0; k0 < Lk; k0 += KT) {
        for (int idx = threadIdx.x; idx < KT * D; idx += 64) {
            int r = idx / D, c = idx % D;
            Ks[idx] = kb[(size_t)b * k_sb + (size_t)(k0 + r) * k_sl + h * D + c];
            Vs[idx] = vb[(size_t)b * v_sb + (size_t)(k0 + r) * v_sl + h * D + c];
        }
        __syncthreads();
        float mnew = m;
#pragma unroll 1
        for (int j = 0; j < KT; j++) {
            uint64_t s0 = 0, s1 = 0, s2 = 0, s3 = 0;
            const uint64_t* kr = (const uint64_t*)(Ks + j * D);
#pragma unroll
            for (int d = 0; d < 32; d += 4) {
                fma2(s0, q2[d], kr[d]); fma2(s1, q2[d+1], kr[d+1]);
                fma2(s2, q2[d+2], kr[d+2]); fma2(s3, q2[d+3], kr[d+3]);
            }
            float l0, h0, l1, h1, l2, h2, l3, h3;
            unpack2(s0, l0, h0); unpack2(s1, l1, h1); unpack2(s2, l2, h2); unpack2(s3, l3, h3);
            float s = ((l0 + h0) + (l1 + h1) + ((l2 + h2) + (l3 + h3))) * 0.125f;
            Ps[threadIdx.x][j] = s;
            mnew = fmaxf(mnew, s);
        }
        float corr = __expf(m - mnew);
        lsum *= corr;
        uint64_t c2 = pack2(corr, corr);
#pragma unroll
        for (int d = 0; d < 32; d++) { uint64_t t = a2[d]; a2[d] = 0ull; fma2(a2[d], t, c2); }
#pragma unroll 1
        for (int j = 0; j < KT; j++) {
            float pe = __expf(Ps[threadIdx.x][j] - mnew);
            lsum += pe;
            uint64_t p2 = pack2(pe, pe);
            const uint64_t* vr = (const uint64_t*)(Vs + j * D);
#pragma unroll
            for (int d = 0; d < 32; d++) fma2(a2[d], p2, vr[d]);
        }
        m = mnew;
        __syncthreads();
    }
    float invl = 1.f / lsum;
    size_t ob = ((size_t)((size_t)b * Lq + qi) * H + h) * D;
#pragma unroll
    for (int d = 0; d < 32; d++) {
        float lo, hi; unpack2(a2[d], lo, hi);
        oh[ob + 2*d]   = __float2half(lo * invl);
        oh[ob + 2*d+1] = __float2half(hi * invl);
    }
}

// ---- launch ----
#define GSYM(p, s) cudaGetSymbolAddress((void**)&p, s)
extern "C" void kernel_launch(void* const* d_in, const int* in_sizes, int n_in,
                              void* d_out, int out_size) {
    const float* x     = (const float*)d_in[0];
    const float* t_mod = (const float*)d_in[1];
    const float* audio = (const float*)d_in[2];
    const float* fcos  = (const float*)d_in[3];
    const float* fsin  = (const float*)d_in[4];
    const float* n1w   = (const float*)d_in[5];
    const float* n2w   = (const float*)d_in[6];
    const float* n3w   = (const float*)d_in[7];
    const float* Wqkv  = (const float*)d_in[8];
    const float* Wsa   = (const float*)d_in[9];
    const float* Wq    = (const float*)d_in[10];
    const float* Wkv   = (const float*)d_in[11];
    const float* Wca   = (const float*)d_in[12];
    const float* Wg    = (const float*)d_in[13];
    const float* Wu    = (const float*)d_in[14];
    const float* Wd    = (const float*)d_in[15];
    const float* adaW  = (const float*)d_in[16];
    const float* adaB  = (const float*)d_in[17];
    float* out = (float*)d_out;

    float *silu_p, *mods_p, *qkv_p, *proj_p, *x_p, *kv_p, *gu_p;
    half *act, *ctx, *sm;
    half *qkvh, *qkvl, *sah, *sal, *qh, *ql, *kvh, *kvl, *cah, *cal;
    half *guh, *gul, *dh, *dl, *adh, *adl;
    GSYM(silu_p, g_silu); GSYM(mods_p, g_mods); GSYM(qkv_p, g_qkv);
    GSYM(proj_p, g_proj); GSYM(x_p, g_x); GSYM(kv_p, g_kvc); GSYM(gu_p, g_gu);
    GSYM(act, g_act); GSYM(ctx, g_ctx); GSYM(sm, g_sm);
    GSYM(qkvh, w_qkv_h); GSYM(qkvl, w_qkv_l); GSYM(sah, w_sa_h); GSYM(sal, w_sa_l);
    GSYM(qh, w_q_h); GSYM(ql, w_q_l); GSYM(kvh, w_kv_h); GSYM(kvl, w_kv_l);
    GSYM(cah, w_ca_h); GSYM(cal, w_ca_l); GSYM(guh, w_gu_h); GSYM(gul, w_gu_l);
    GSYM(dh, w_d_h); GSYM(dl, w_d_l); GSYM(adh, w_ada_h); GSYM(adl, w_ada_l);

    const size_t NXC = (size_t)BL * C;
    wconvert(Wqkv, qkvh, qkvl, C, 3*C);
    wconvert(Wsa,  sah,  sal,  C, C);
    wconvert(Wq,   qh,   ql,   C, C);
    wconvert(Wkv,  kvh,  kvl,  TD, 2*C);
    wconvert(Wca,  cah,  cal,  C, C);
    wconvert(Wg,   guh,              gul,              C, FF);
    wconvert(Wu,   guh + (size_t)FF*C, gul + (size_t)FF*C, C, FF);
    wconvert(Wd,   dh,   dl,   FF, C);
    wconvert(adaW, adh,  adl,  C, 6*C);

    // adaLN (M padded to 128; bias folded at consumers)
    silu_kernel<<<(B*C + 255)/256, 256>>>(t_mod, silu_p, B*C);
    aconvert_kernel<<<(128*C + 255)/256, 256>>>(silu_p, sm, 128*C);
    mgemm(sm, adh, adl, mods_p, 128, 6*C, C);

    // self-attention
    rmsnorm_kernel<<<BL, 256>>>(x, n1w, mods_p, adaB, 0, C, act);
    mgemm(act, qkvh, qkvl, qkv_p, BL, 3*C, C);
    rope_kernel<<<(B*L*H*(D/2) + 255)/256, 256>>>(qkv_p, fcos, fsin);
    {
        long sl3 = 3*C, sb3 = (long)L*3*C;
        attn_kernel<<<dim3(L/64, H, B), 64>>>(qkv_p, qkv_p + C, qkv_p + 2*C, act,
                                              L, L, sb3, sl3, sb3, sl3, sb3, sl3);
    }
    mgemm(act, sah, sal, proj_p, BL, C, C);
    residual_kernel<<<(int)((NXC + 255)/256), 256>>>(x, proj_p, mods_p, adaB, 2*C, x_p);

    // cross-attention
    rmsnorm_kernel<<<BL, 256>>>(x_p, n2w, nullptr, nullptr, 0, 0, act);
    mgemm(act, qh, ql, qkv_p, BL, C, C);
    aconvert_kernel<<<(BL2*TD + 255)/256, 256>>>(audio, ctx, (size_t)BL2*TD);
    mgemm(ctx, kvh, kvl, kv_p, BL2, 2*C, TD);
    {
        long qsl = C, qsb = (long)L*C, ksl = 2*C, ksb = (long)L2*2*C;
        attn_kernel<<<dim3(L/64, H, B), 64>>>(qkv_p, kv_p, kv_p + C, act,
                                              L, L2, qsb, qsl, ksb, ksl, ksb, ksl);
    }
    mgemm(act, cah, cal, proj_p, BL, C, C);
    residual_kernel<<<(int)((NXC + 255)/256), 256>>>(x_p, proj_p, nullptr, nullptr, 0, x_p);

    // MLP (gate+up fused, N=2*FF)
    rmsnorm_kernel<<<BL, 256>>>(x_p, n3w, mods_p, adaB, 3*C, 4*C, act);
    mgemm(act, guh, gul, gu_p, BL, 2*FF, C);
    {
        size_t n = (size_t)BL * FF;
        swiglu_kernel<<<(int)((n + 255)/256), 256>>>(gu_p, act, n);
    }
    mgemm(act, dh, dl, proj_p, BL, C, FF);
    residual_kernel<<<(int)((NXC + 255)/256), 256>>>(x_p, proj_p, mods_p, adaB, 5*C, out);
}

// round 8
// speedup vs baseline: 3.8777x; 1.9868x over previous
#include <cuda_runtime.h>
#include <cuda_fp16.h>
#include <stdint.h>

#define B 2
#define L 2048
#define C 1024
#define H 16
#define D 64
#define L2 512
#define TD 768
#define FF 4096
#define EPS 1e-6f
#define BL 4096
#define BL2 1024
#define ZB 32            // B*H batches

// ---- scratch ----
__device__ float g_silu[128 * C];
__device__ float g_mods[128 * 6 * C];
__device__ float g_qkv[BL * 3 * C];
__device__ float g_proj[BL * C];
__device__ float g_x[BL * C];
__device__ float g_kvc[BL2 * 2 * C];
__device__ float g_gu[(size_t)BL * 2 * FF];
__device__ half g_act[(size_t)BL * FF];
__device__ half g_ctx[BL2 * TD];
__device__ half g_sm[128 * C];
// attention buffers
__device__ half  g_S[(size_t)ZB * L * L];       // scores/P (256MB), reused SA/CA
__device__ float g_O[(size_t)ZB * L * D];
__device__ float g_ls[ZB * L];
__device__ half  g_qh[(size_t)ZB * L * D];
__device__ half  g_kh[(size_t)ZB * L * D];
__device__ half  g_vt[(size_t)ZB * D * L];
// weights hi/lo fp16, transposed [N][K]
__device__ half w_qkv_h[3*C*C], w_qkv_l[3*C*C];
__device__ half w_sa_h[C*C], w_sa_l[C*C];
__device__ half w_q_h[C*C], w_q_l[C*C];
__device__ half w_kv_h[2*C*TD], w_kv_l[2*C*TD];
__device__ half w_ca_h[C*C], w_ca_l[C*C];
__device__ half w_gu_h[(size_t)2*FF*C], w_gu_l[(size_t)2*FF*C];
__device__ half w_d_h[(size_t)FF*C], w_d_l[(size_t)FF*C];
__device__ half w_ada_h[6*C*C], w_ada_l[6*C*C];

// ---- helpers ----
__device__ __forceinline__ uint32_t smem_u32(const void* p) {
    uint32_t a;
    asm("{ .reg .u64 t; cvta.to.shared.u64 t, %1; cvt.u32.u64 %0, t; }" : "=r"(a) : "l"(p));
    return a;
}
__device__ __forceinline__ void split_half(float v, half& h, half& l) {
    h = __float2half(v);
    l = __float2half(v - __half2float(h));
}
__device__ __forceinline__ void cp16(uint32_t s, const void* g) {
    asm volatile("cp.async.cg.shared.global [%0], [%1], 16;" :: "r"(s), "l"(g));
}
__device__ __forceinline__ void ldsm4(uint32_t* r, uint32_t a) {
    asm volatile("ldmatrix.sync.aligned.m8n8.x4.shared.b16 {%0,%1,%2,%3}, [%4];"
        : "=r"(r[0]), "=r"(r[1]), "=r"(r[2]), "=r"(r[3]) : "r"(a));
}
__device__ __forceinline__ void mma16816(float* d, const uint32_t* a, uint32_t b0, uint32_t b1) {
    asm volatile("mma.sync.aligned.m16n8k16.row.col.f32.f16.f16.f32 "
        "{%0,%1,%2,%3}, {%4,%5,%6,%7}, {%8,%9}, {%0,%1,%2,%3};"
        : "+f"(d[0]), "+f"(d[1]), "+f"(d[2]), "+f"(d[3])
        : "r"(a[0]), "r"(a[1]), "r"(a[2]), "r"(a[3]), "r"(b0), "r"(b1));
}

// ---- templated pipelined fp16 mma GEMM ----
// C[z][M,N](OutT) = A[z][M,K] @ (B0 (+B1 if NPASS==2))[z][N,K]^T
#define NSTAGE 3

template<int BN, int NPASS, typename OT>
__global__ void __launch_bounds__(256) gmma(
    const half* __restrict__ Ax, const half* __restrict__ B0, const half* __restrict__ B1,
    OT* __restrict__ Co, int M, int N, int K,
    size_t sA, size_t sB, size_t sC)
{
    constexpr int BNB = BN * 64;               // bytes per B plane per stage
    constexpr int STG = 8192 + NPASS * BNB;
    constexpr int WN = (BN == 256) ? 4 : 2;
    constexpr int WM = 8 / WN;
    constexpr int MF = (128 / WM) / 16;
    constexpr int NF = (BN / WN) / 8;
    constexpr int TOT = 512 + NPASS * BN * 4;  // cp16 ops per stage

    extern __shared__ char smem[];
    uint32_t sb = smem_u32(smem);
    const int tid = threadIdx.x, lane = tid & 31, wid = tid >> 5;
    const int wm = (wid % WM) * MF * 16;
    const int wn = (wid / WM) * NF * 8;
    const int tM = blockIdx.y << 7, tN = blockIdx.x * BN;
    const int z = blockIdx.z;
    Ax += (size_t)z * sA; B0 += (size_t)z * sB;
    if (NPASS == 2) B1 += (size_t)z * sB;
    Co += (size_t)z * sC;

    float acc[MF][NF][4];
#pragma unroll
    for (int f = 0; f < MF; f++)
#pragma unroll
        for (int n = 0; n < NF; n++)
#pragma unroll
            for (int v = 0; v < 4; v++) acc[f][n][v] = 0.f;

    const int kIters = K >> 5;

    auto load_stage = [&](int s, int k0) {
        for (int id = tid; id < TOT; id += 256) {
            const half* g; uint32_t dst;
            if (id < 512) {
                int row = id >> 2, c = id & 3;
                g = Ax + (size_t)(tM + row) * K + k0 + (c << 3);
                dst = sb + s * STG + row * 64 + ((c ^ (row & 3)) << 4);
            } else {
                int idB = id - 512;
                int t = idB / (BN * 4), a = idB % (BN * 4);
                int row = a >> 2, c = a & 3;
                const half* Bp = (NPASS == 2 && t) ? B1 : B0;
                g = Bp + (size_t)(tN + row) * K + k0 + (c << 3);
                dst = sb + s * STG + 8192 + t * BNB + row * 64 + ((c ^ (row & 3)) << 4);
            }
            cp16(dst, g);
        }
    };

    for (int s = 0; s < NSTAGE - 1; s++) {
        load_stage(s, s << 5);
        asm volatile("cp.async.commit_group;");
    }

    const int lrow = lane & 15, lch = lane >> 4;

    for (int it = 0; it < kIters; it++) {
        asm volatile("cp.async.wait_group 1;");
        __syncthreads();
        if (it + NSTAGE - 1 < kIters)
            load_stage((it + NSTAGE - 1) % NSTAGE, (it + NSTAGE - 1) << 5);
        asm volatile("cp.async.commit_group;");

        uint32_t stg = sb + (uint32_t)(it % NSTAGE) * STG;
#pragma unroll
        for (int ks = 0; ks < 2; ks++) {
            int ch = (ks << 1) + lch;
            uint32_t a[MF][4];
#pragma unroll
            for (int f = 0; f < MF; f++) {
                int row = wm + (f << 4) + lrow;
                ldsm4(a[f], stg + row * 64 + ((ch ^ (row & 3)) << 4));
            }
#pragma unroll
            for (int pass = 0; pass < NPASS; pass++) {
                uint32_t bo = stg + 8192u + (uint32_t)pass * BNB;
                uint32_t b[NF / 2][4];
#pragma unroll
                for (int p = 0; p < NF / 2; p++) {
                    int row = wn + (p << 4) + lrow;
                    ldsm4(b[p], bo + row * 64 + ((ch ^ (row & 3)) << 4));
                }
#pragma unroll
                for (int f = 0; f < MF; f++)
#pragma unroll
                    for (int n = 0; n < NF; n++)
                        mma16816(acc[f][n], a[f], b[n >> 1][n & 1], b[n >> 1][2 + (n & 1)]);
            }
        }
    }

#pragma unroll
    for (int f = 0; f < MF; f++) {
        int r0 = tM + wm + (f << 4) + (lane >> 2);
#pragma unroll
        for (int n = 0; n < NF; n++) {
            int col = tN + wn + (n << 3) + ((lane & 3) << 1);
            if (sizeof(OT) == 4) {
                float2 v0 = {acc[f][n][0], acc[f][n][1]};
                float2 v1 = {acc[f][n][2], acc[f][n][3]};
                *(float2*)((float*)Co + (size_t)r0 * N + col) = v0;
                *(float2*)((float*)Co + (size_t)(r0 + 8) * N + col) = v1;
            } else {
                half2 v0 = __floats2half2_rn(acc[f][n][0], acc[f][n][1]);
                half2 v1 = __floats2half2_rn(acc[f][n][2], acc[f][n][3]);
                *(half2*)((half*)Co + (size_t)r0 * N + col) = v0;
                *(half2*)((half*)Co + (size_t)(r0 + 8) * N + col) = v1;
            }
        }
    }
}

static inline void wgemm(const half* A, const half* Bh, const half* Bl,
                         float* Co, int M, int N, int K) {
    constexpr int SM = NSTAGE * (8192 + 2 * 16384);
    cudaFuncSetAttribute(gmma<256,2,float>, cudaFuncAttributeMaxDynamicSharedMemorySize, SM);
    gmma<256,2,float><<<dim3(N/256, M/128, 1), 256, SM>>>(A, Bh, Bl, Co, M, N, K, 0, 0, 0);
}
static inline void qkgemm(const half* Q, const half* Kk, half* S, int Lk) {
    constexpr int SM = NSTAGE * (8192 + 16384);
    cudaFuncSetAttribute(gmma<256,1,half>, cudaFuncAttributeMaxDynamicSharedMemorySize, SM);
    gmma<256,1,half><<<dim3(Lk/256, L/128, ZB), 256, SM>>>(
        Q, Kk, nullptr, S, L, Lk, D, (size_t)L*D, (size_t)Lk*D, (size_t)L*Lk);
}
static inline void pvgemm(const half* P, const half* Vt, float* O, int Lk) {
    constexpr int SM = NSTAGE * (8192 + 4096);
    cudaFuncSetAttribute(gmma<64,1,float>, cudaFuncAttributeMaxDynamicSharedMemorySize, SM);
    gmma<64,1,float><<<dim3(1, L/128, ZB), 256, SM>>>(
        P, Vt, nullptr, O, L, D, Lk, (size_t)L*Lk, (size_t)D*Lk, (size_t)L*D);
}

// ---- attention support kernels ----
// SA prep: rope q,k; split heads; transpose v. One thread per (b,l,h,p<32).
__global__ void sa_prep_kernel(const float* __restrict__ qkv,
                               const float* __restrict__ fc, const float* __restrict__ fs,
                               half* __restrict__ qh, half* __restrict__ kh,
                               half* __restrict__ vt) {
    int i = blockIdx.x * blockDim.x + threadIdx.x;
    if (i >= B * L * H * 32) return;
    int p = i & 31, t = i >> 5;
    int h = t & 15; t >>= 4;
    int l = t & 2047; int b = t >> 11;
    float c = fc[l * 32 + p], s = fs[l * 32 + p];
    size_t rb = ((size_t)b * L + l) * 3072 + h * 64 + 2 * p;
    float q0 = qkv[rb], q1 = qkv[rb + 1];
    float k0 = qkv[rb + 1024], k1 = qkv[rb + 1025];
    float v0 = qkv[rb + 2048], v1 = qkv[rb + 2049];
    int z = b * H + h;
    size_t qo = ((size_t)z * L + l) * 64 + 2 * p;
    qh[qo]   = __float2half(q0 * c - q1 * s);
    qh[qo+1] = __float2half(q0 * s + q1 * c);
    kh[qo]   = __float2half(k0 * c - k1 * s);
    kh[qo+1] = __float2half(k0 * s + k1 * c);
    vt[((size_t)z * 64 + 2*p)     * L + l] = __float2half(v0);
    vt[((size_t)z * 64 + 2*p + 1) * L + l] = __float2half(v1);
}
// CA prep: q from qc [BL][C]
__global__ void ca_prep_q_kernel(const float* __restrict__ qc, half* __restrict__ qh) {
    int i = blockIdx.x * blockDim.x + threadIdx.x;
    if (i >= B * L * C) return;
    int col = i & 1023, row = i >> 10;
    int h = col >> 6, d = col & 63;
    int b = row >> 11, l = row & 2047;
    qh[(((size_t)(b * H + h)) * L + l) * 64 + d] = __float2half(qc[i]);
}
// CA prep: k,v from kv [BL2][2C]
__global__ void ca_prep_kv_kernel(const float* __restrict__ kv,
                                  half* __restrict__ kh, half* __restrict__ vt) {
    int i = blockIdx.x * blockDim.x + threadIdx.x;
    if (i >= B * L2 * C) return;
    int col = i & 1023, row = i >> 10;
    int h = col >> 6, d = col & 63;
    int b = row >> 9, k = row & 511;
    int z = b * H + h;
    kh[((size_t)z * L2 + k) * 64 + d] = __float2half(kv[(size_t)row * 2048 + col]);
    vt[((size_t)z * 64 + d) * L2 + k] = __float2half(kv[(size_t)row * 2048 + 1024 + col]);
}
// softmax: block per row; in-place S->P (fp16), lsum out; scale 0.125 folded.
__global__ void softmax_kernel(half* __restrict__ S, float* __restrict__ ls, int Lk) {
    size_t base = (size_t)blockIdx.x * Lk;
    __shared__ float red[8];
    float m = -1e30f;
    for (int i = threadIdx.x; i < Lk; i += 256)
        m = fmaxf(m, __half2float(S[base + i]) * 0.125f);
#pragma unroll
    for (int o = 16; o > 0; o >>= 1) m = fmaxf(m, __shfl_xor_sync(0xffffffff, m, o));
    if ((threadIdx.x & 31) == 0) red[threadIdx.x >> 5] = m;
    __syncthreads();
    m = red[threadIdx.x & 7];
#pragma unroll
    for (int o = 4; o > 0; o >>= 1) m = fmaxf(m, __shfl_xor_sync(0xffffffff, m, o));
    float sum = 0.f;
    for (int i = threadIdx.x; i < Lk; i += 256) {
        float e = __expf(__half2float(S[base + i]) * 0.125f - m);
        S[base + i] = __float2half(e);
        sum += e;
    }
#pragma unroll
    for (int o = 16; o > 0; o >>= 1) sum += __shfl_xor_sync(0xffffffff, sum, o);
    if ((threadIdx.x & 31) == 0) red[threadIdx.x >> 5] = sum;
    __syncthreads();
    if (threadIdx.x == 0) {
        float t = 0.f;
#pragma unroll
        for (int w = 0; w < 8; w++) t += red[w];
        ls[blockIdx.x] = t;
    }
}
// O [z][l][64] / lsum -> act [b,l][h*64+d] fp16
__global__ void o_finish_kernel(const float* __restrict__ O, const float* __restrict__ ls,
                                half* __restrict__ act) {
    int i = blockIdx.x * blockDim.x + threadIdx.x;
    if (i >= B * L * C) return;
    int col = i & 1023, row = i >> 10;
    int h = col >> 6, d = col & 63;
    int b = row >> 11, l = row & 2047;
    size_t zl = (size_t)(b * H + h) * L + l;
    act[i] = __float2half(O[zl * 64 + d] / ls[zl]);
}

// ---- converts ----
__global__ void wconvert_kernel(const float* __restrict__ W, half* __restrict__ Th,
                                half* __restrict__ Tl, int K, int N) {
    __shared__ float t[32][33];
    int k0 = blockIdx.y * 32, n0 = blockIdx.x * 32;
    int tx = threadIdx.x, ty = threadIdx.y;
#pragma unroll
    for (int i = 0; i < 32; i += 8) t[ty + i][tx] = W[(size_t)(k0 + ty + i) * N + n0 + tx];
    __syncthreads();
#pragma unroll
    for (int i = 0; i < 32; i += 8) {
        half h, l; split_half(t[tx][ty + i], h, l);
        size_t o = (size_t)(n0 + ty + i) * K + k0 + tx;
        Th[o] = h; Tl[o] = l;
    }
}
static inline void wconvert(const float* W, half* Th, half* Tl, int K, int N) {
    wconvert_kernel<<<dim3(N/32, K/32), dim3(32, 8)>>>(W, Th, Tl, K, N);
}
__global__ void aconvert_kernel(const float* __restrict__ a, half* __restrict__ o, size_t n) {
    size_t i = (size_t)blockIdx.x * blockDim.x + threadIdx.x;
    if (i >= n) return;
    o[i] = __float2half(a[i]);
}

// ---- elementwise ----
__global__ void silu_kernel(const float* __restrict__ in, float* __restrict__ o, int n) {
    int i = blockIdx.x * blockDim.x + threadIdx.x;
    if (i >= n) return;
    float v = in[i];
    o[i] = v / (1.f + __expf(-v));
}
__global__ void rmsnorm_kernel(const float* __restrict__ x, const float* __restrict__ w,
                               const float* __restrict__ mods, const float* __restrict__ bias,
                               int sh_off, int sc_off, half* __restrict__ o) {
    int row = blockIdx.x, b = row / L;
    const float* xr = x + (size_t)row * C;
    float s = 0.f;
    for (int c = threadIdx.x; c < C; c += blockDim.x) { float v = xr[c]; s += v * v; }
    __shared__ float red[32];
#pragma unroll
    for (int o2 = 16; o2 > 0; o2 >>= 1) s += __shfl_down_sync(0xffffffff, s, o2);
    if ((threadIdx.x & 31) == 0) red[threadIdx.x >> 5] = s;
    __syncthreads();
    if (threadIdx.x < 32) {
        float v = (threadIdx.x < (blockDim.x >> 5)) ? red[threadIdx.x] : 0.f;
#pragma unroll
        for (int o2 = 16; o2 > 0; o2 >>= 1) v += __shfl_down_sync(0xffffffff, v, o2);
        if (threadIdx.x == 0) red[0] = v;
    }
    __syncthreads();
    float inv = rsqrtf(red[0] / (float)C + EPS);
    for (int c = threadIdx.x; c < C; c += blockDim.x) {
        float n = xr[c] * inv * w[c];
        if (mods) {
            float sc = mods[(size_t)b * 6 * C + sc_off + c] + bias[sc_off + c];
            float sh = mods[(size_t)b * 6 * C + sh_off + c] + bias[sh_off + c];
            n = n * (1.f + sc) + sh;
        }
        o[(size_t)row * C + c] = __float2half(n);
    }
}
__global__ void residual_kernel(const float* __restrict__ x, const float* __restrict__ p,
                                const float* __restrict__ mods, const float* __restrict__ bias,
                                int g_off, float* __restrict__ out) {
    size_t i = (size_t)blockIdx.x * blockDim.x + threadIdx.x;
    if (i >= (size_t)BL * C) return;
    float g = 1.f;
    if (mods) {
        int c = (int)(i % C), b = (int)(i / ((size_t)L * C));
        g = mods[(size_t)b * 6 * C + g_off + c] + bias[g_off + c];
    }
    out[i] = x[i] + g * p[i];
}
__global__ void swiglu_kernel(const float* __restrict__ gu, half* __restrict__ o, size_t n) {
    size_t i = (size_t)blockIdx.x * blockDim.x + threadIdx.x;
    if (i >= n) return;
    size_t row = i >> 12, c = i & (FF - 1);
    float v = gu[(row << 13) + c];
    float u = gu[(row << 13) + FF + c];
    o[i] = __float2half((v / (1.f + __expf(-v))) * u);
}

// ---- launch ----
#define GSYM(p, s) cudaGetSymbolAddress((void**)&p, s)
extern "C" void kernel_launch(void* const* d_in, const int* in_sizes, int n_in,
                              void* d_out, int out_size) {
    const float* x     = (const float*)d_in[0];
    const float* t_mod = (const float*)d_in[1];
    const float* audio = (const float*)d_in[2];
    const float* fcos  = (const float*)d_in[3];
    const float* fsin  = (const float*)d_in[4];
    const float* n1w   = (const float*)d_in[5];
    const float* n2w   = (const float*)d_in[6];
    const float* n3w   = (const float*)d_in[7];
    const float* Wqkv  = (const float*)d_in[8];
    const float* Wsa   = (const float*)d_in[9];
    const float* Wq    = (const float*)d_in[10];
    const float* Wkv   = (const float*)d_in[11];
    const float* Wca   = (const float*)d_in[12];
    const float* Wg    = (const float*)d_in[13];
    const float* Wu    = (const float*)d_in[14];
    const float* Wd    = (const float*)d_in[15];
    const float* adaW  = (const float*)d_in[16];
    const float* adaB  = (const float*)d_in[17];
    float* out = (float*)d_out;

    float *silu_p, *mods_p, *qkv_p, *proj_p, *x_p, *kv_p, *gu_p, *O_p, *ls_p;
    half *act, *ctx, *sm, *S_p, *qh_p, *kh_p, *vt_p;
    half *qkvh, *qkvl, *sah, *sal, *qh, *ql, *kvh, *kvl, *cah, *cal;
    half *guh, *gul, *dh, *dl, *adh, *adl;
    GSYM(silu_p, g_silu); GSYM(mods_p, g_mods); GSYM(qkv_p, g_qkv);
    GSYM(proj_p, g_proj); GSYM(x_p, g_x); GSYM(kv_p, g_kvc); GSYM(gu_p, g_gu);
    GSYM(act, g_act); GSYM(ctx, g_ctx); GSYM(sm, g_sm);
    GSYM(S_p, g_S); GSYM(O_p, g_O); GSYM(ls_p, g_ls);
    GSYM(qh_p, g_qh); GSYM(kh_p, g_kh); GSYM(vt_p, g_vt);
    GSYM(qkvh, w_qkv_h); GSYM(qkvl, w_qkv_l); GSYM(sah, w_sa_h); GSYM(sal, w_sa_l);
    GSYM(qh, w_q_h); GSYM(ql, w_q_l); GSYM(kvh, w_kv_h); GSYM(kvl, w_kv_l);
    GSYM(cah, w_ca_h); GSYM(cal, w_ca_l); GSYM(guh, w_gu_h); GSYM(gul, w_gu_l);
    GSYM(dh, w_d_h); GSYM(dl, w_d_l); GSYM(adh, w_ada_h); GSYM(adl, w_ada_l);

    const size_t NXC = (size_t)BL * C;
    wconvert(Wqkv, qkvh, qkvl, C, 3*C);
    wconvert(Wsa,  sah,  sal,  C, C);
    wconvert(Wq,   qh,   ql,   C, C);
    wconvert(Wkv,  kvh,  kvl,  TD, 2*C);
    wconvert(Wca,  cah,  cal,  C, C);
    wconvert(Wg,   guh,               gul,               C, FF);
    wconvert(Wu,   guh + (size_t)FF*C, gul + (size_t)FF*C, C, FF);
    wconvert(Wd,   dh,   dl,   FF, C);
    wconvert(adaW, adh,  adl,  C, 6*C);

    // adaLN (M padded to 128; bias folded at consumers)
    silu_kernel<<<(B*C + 255)/256, 256>>>(t_mod, silu_p, B*C);
    aconvert_kernel<<<(128*C + 255)/256, 256>>>(silu_p, sm, 128*C);
    wgemm(sm, adh, adl, mods_p, 128, 6*C, C);

    // ---- self-attention ----
    rmsnorm_kernel<<<BL, 256>>>(x, n1w, mods_p, adaB, 0, C, act);
    wgemm(act, qkvh, qkvl, qkv_p, BL, 3*C, C);
    sa_prep_kernel<<<(B*L*H*32 + 255)/256, 256>>>(qkv_p, fcos, fsin, qh_p, kh_p, vt_p);
    qkgemm(qh_p, kh_p, S_p, L);
    softmax_kernel<<<ZB * L, 256>>>(S_p, ls_p, L);
    pvgemm(S_p, vt_p, O_p, L);
    o_finish_kernel<<<(B*L*C + 255)/256, 256>>>(O_p, ls_p, act);
    wgemm(act, sah, sal, proj_p, BL, C, C);
    residual_kernel<<<(int)((NXC + 255)/256), 256>>>(x, proj_p, mods_p, adaB, 2*C, x_p);

    // ---- cross-attention ----
    rmsnorm_kernel<<<BL, 256>>>(x_p, n2w, nullptr, nullptr, 0, 0, act);
    wgemm(act, qh, ql, qkv_p, BL, C, C);
    aconvert_kernel<<<(BL2*TD + 255)/256, 256>>>(audio, ctx, (size_t)BL2*TD);
    wgemm(ctx, kvh, kvl, kv_p, BL2, 2*C, TD);
    ca_prep_q_kernel<<<(B*L*C + 255)/256, 256>>>(qkv_p, qh_p);
    ca_prep_kv_kernel<<<(B*L2*C + 255)/256, 256>>>(kv_p, kh_p, vt_p);
    qkgemm(qh_p, kh_p, S_p, L2);
    softmax_kernel<<<ZB * L, 256>>>(S_p, ls_p, L2);
    pvgemm(S_p, vt_p, O_p, L2);
    o_finish_kernel<<<(B*L*C + 255)/256, 256>>>(O_p, ls_p, act);
    wgemm(act, cah, cal, proj_p, BL, C, C);
    residual_kernel<<<(int)((NXC + 255)/256), 256>>>(x_p, proj_p, nullptr, nullptr, 0, x_p);

    // ---- MLP (gate+up fused, N=2*FF) ----
    rmsnorm_kernel<<<BL, 256>>>(x_p, n3w, mods_p, adaB, 3*C, 4*C, act);
    wgemm(act, guh, gul, gu_p, BL, 2*FF, C);
    {
        size_t n = (size_t)BL * FF;
        swiglu_kernel<<<(int)((n + 255)/256), 256>>>(gu_p, act, n);
    }
    wgemm(act, dh, dl, proj_p, BL, C, FF);
    residual_kernel<<<(int)((NXC + 255)/256), 256>>>(x_p, proj_p, mods_p, adaB, 5*C, out);
}

// round 9
// speedup vs baseline: 4.6059x; 1.1878x over previous
#include <cuda_runtime.h>
#include <cuda_fp16.h>
#include <stdint.h>

#define B 2
#define L 2048
#define C 1024
#define H 16
#define D 64
#define L2 512
#define TD 768
#define FF 4096
#define EPS 1e-6f
#define BL 4096
#define BL2 1024
#define ZB 32            // B*H batches

// ---- scratch ----
__device__ float g_silu[128 * C];
__device__ float g_mods[128 * 6 * C];
__device__ float g_qkv[BL * 3 * C];
__device__ float g_proj[BL * C];
__device__ float g_x[BL * C];
__device__ float g_kvc[BL2 * 2 * C];
__device__ float g_gu[(size_t)BL * 2 * FF];
__device__ half g_act[(size_t)BL * FF];
__device__ half g_ctx[BL2 * TD];
__device__ half g_sm[128 * C];
// attention buffers
__device__ half  g_S[(size_t)ZB * L * L];
__device__ float g_O[(size_t)ZB * L * D];
__device__ float g_ls[ZB * L];
__device__ half  g_qh[(size_t)ZB * L * D];
__device__ half  g_kh[(size_t)ZB * L * D];
__device__ half  g_vt[(size_t)ZB * D * L];
// weights fp16 (single plane), transposed [N][K]
__device__ half w_qkv[3*C*C];
__device__ half w_sa[C*C];
__device__ half w_q[C*C];
__device__ half w_kv[2*C*TD];
__device__ half w_ca[C*C];
__device__ half w_gu[(size_t)2*FF*C];
__device__ half w_d[(size_t)FF*C];
__device__ half w_ada[6*C*C];

// ---- helpers ----
__device__ __forceinline__ uint32_t smem_u32(const void* p) {
    uint32_t a;
    asm("{ .reg .u64 t; cvta.to.shared.u64 t, %1; cvt.u32.u64 %0, t; }" : "=r"(a) : "l"(p));
    return a;
}
__device__ __forceinline__ void cp16(uint32_t s, const void* g) {
    asm volatile("cp.async.cg.shared.global [%0], [%1], 16;" :: "r"(s), "l"(g));
}
__device__ __forceinline__ void ldsm4(uint32_t* r, uint32_t a) {
    asm volatile("ldmatrix.sync.aligned.m8n8.x4.shared.b16 {%0,%1,%2,%3}, [%4];"
        : "=r"(r[0]), "=r"(r[1]), "=r"(r[2]), "=r"(r[3]) : "r"(a));
}
__device__ __forceinline__ void mma16816(float* d, const uint32_t* a, uint32_t b0, uint32_t b1) {
    asm volatile("mma.sync.aligned.m16n8k16.row.col.f32.f16.f16.f32 "
        "{%0,%1,%2,%3}, {%4,%5,%6,%7}, {%8,%9}, {%0,%1,%2,%3};"
        : "+f"(d[0]), "+f"(d[1]), "+f"(d[2]), "+f"(d[3])
        : "r"(a[0]), "r"(a[1]), "r"(a[2]), "r"(a[3]), "r"(b0), "r"(b1));
}

// ---- templated pipelined fp16 mma GEMM ----
// C[z][M,N](OT) = A[z][M,K] @ B0[z][N,K]^T
#define NSTAGE 3

template<int BN, typename OT>
__global__ void __launch_bounds__(256) gmma(
    const half* __restrict__ Ax, const half* __restrict__ B0,
    OT* __restrict__ Co, int M, int N, int K,
    size_t sA, size_t sB, size_t sC)
{
    constexpr int BNB = BN * 64;
    constexpr int STG = 8192 + BNB;
    constexpr int WN = (BN == 256) ? 4 : 2;
    constexpr int WM = 8 / WN;
    constexpr int MF = (128 / WM) / 16;
    constexpr int NF = (BN / WN) / 8;
    constexpr int TOT = 512 + BN * 4;

    extern __shared__ char smem[];
    uint32_t sb = smem_u32(smem);
    const int tid = threadIdx.x, lane = tid & 31, wid = tid >> 5;
    const int wm = (wid % WM) * MF * 16;
    const int wn = (wid / WM) * NF * 8;
    const int tM = blockIdx.y << 7, tN = blockIdx.x * BN;
    const int z = blockIdx.z;
    Ax += (size_t)z * sA; B0 += (size_t)z * sB; Co += (size_t)z * sC;

    float acc[MF][NF][4];
#pragma unroll
    for (int f = 0; f < MF; f++)
#pragma unroll
        for (int n = 0; n < NF; n++)
#pragma unroll
            for (int v = 0; v < 4; v++) acc[f][n][v] = 0.f;

    const int kIters = K >> 5;

    auto load_stage = [&](int s, int k0) {
        for (int id = tid; id < TOT; id += 256) {
            const half* g; uint32_t dst;
            if (id < 512) {
                int row = id >> 2, c = id & 3;
                g = Ax + (size_t)(tM + row) * K + k0 + (c << 3);
                dst = sb + s * STG + row * 64 + ((c ^ (row & 3)) << 4);
            } else {
                int a = id - 512;
                int row = a >> 2, c = a & 3;
                g = B0 + (size_t)(tN + row) * K + k0 + (c << 3);
                dst = sb + s * STG + 8192 + row * 64 + ((c ^ (row & 3)) << 4);
            }
            cp16(dst, g);
        }
    };

    for (int s = 0; s < NSTAGE - 1; s++) {
        load_stage(s, s << 5);
        asm volatile("cp.async.commit_group;");
    }

    const int lrow = lane & 15, lch = lane >> 4;

    for (int it = 0; it < kIters; it++) {
        asm volatile("cp.async.wait_group 1;");
        __syncthreads();
        if (it + NSTAGE - 1 < kIters)
            load_stage((it + NSTAGE - 1) % NSTAGE, (it + NSTAGE - 1) << 5);
        asm volatile("cp.async.commit_group;");

        uint32_t stg = sb + (uint32_t)(it % NSTAGE) * STG;
#pragma unroll
        for (int ks = 0; ks < 2; ks++) {
            int ch = (ks << 1) + lch;
            uint32_t a[MF][4], b[NF / 2][4];
#pragma unroll
            for (int f = 0; f < MF; f++) {
                int row = wm + (f << 4) + lrow;
                ldsm4(a[f], stg + row * 64 + ((ch ^ (row & 3)) << 4));
            }
#pragma unroll
            for (int p = 0; p < NF / 2; p++) {
                int row = wn + (p << 4) + lrow;
                ldsm4(b[p], stg + 8192u + row * 64 + ((ch ^ (row & 3)) << 4));
            }
#pragma unroll
            for (int f = 0; f < MF; f++)
#pragma unroll
                for (int n = 0; n < NF; n++)
                    mma16816(acc[f][n], a[f], b[n >> 1][n & 1], b[n >> 1][2 + (n & 1)]);
        }
    }

#pragma unroll
    for (int f = 0; f < MF; f++) {
        int r0 = tM + wm + (f << 4) + (lane >> 2);
#pragma unroll
        for (int n = 0; n < NF; n++) {
            int col = tN + wn + (n << 3) + ((lane & 3) << 1);
            if (sizeof(OT) == 4) {
                float2 v0 = {acc[f][n][0], acc[f][n][1]};
                float2 v1 = {acc[f][n][2], acc[f][n][3]};
                *(float2*)((float*)Co + (size_t)r0 * N + col) = v0;
                *(float2*)((float*)Co + (size_t)(r0 + 8) * N + col) = v1;
            } else {
                half2 v0 = __floats2half2_rn(acc[f][n][0], acc[f][n][1]);
                half2 v1 = __floats2half2_rn(acc[f][n][2], acc[f][n][3]);
                *(half2*)((half*)Co + (size_t)r0 * N + col) = v0;
                *(half2*)((half*)Co + (size_t)(r0 + 8) * N + col) = v1;
            }
        }
    }
}

static inline void wgemm(const half* A, const half* Bw, float* Co, int M, int N, int K) {
    constexpr int SM = NSTAGE * (8192 + 16384);
    cudaFuncSetAttribute(gmma<256,float>, cudaFuncAttributeMaxDynamicSharedMemorySize, SM);
    gmma<256,float><<<dim3(N/256, M/128, 1), 256, SM>>>(A, Bw, Co, M, N, K, 0, 0, 0);
}
static inline void qkgemm(const half* Q, const half* Kk, half* S, int Lk) {
    constexpr int SM = NSTAGE * (8192 + 16384);
    cudaFuncSetAttribute(gmma<256,half>, cudaFuncAttributeMaxDynamicSharedMemorySize, SM);
    gmma<256,half><<<dim3(Lk/256, L/128, ZB), 256, SM>>>(
        Q, Kk, S, L, Lk, D, (size_t)L*D, (size_t)Lk*D, (size_t)L*Lk);
}
static inline void pvgemm(const half* P, const half* Vt, float* O, int Lk) {
    constexpr int SM = NSTAGE * (8192 + 4096);
    cudaFuncSetAttribute(gmma<64,float>, cudaFuncAttributeMaxDynamicSharedMemorySize, SM);
    gmma<64,float><<<dim3(1, L/128, ZB), 256, SM>>>(
        P, Vt, O, L, D, Lk, (size_t)L*Lk, (size_t)D*Lk, (size_t)L*D);
}

// ---- attention support kernels ----
__global__ void sa_prep_kernel(const float* __restrict__ qkv,
                               const float* __restrict__ fc, const float* __restrict__ fs,
                               half* __restrict__ qh, half* __restrict__ kh,
                               half* __restrict__ vt) {
    int i = blockIdx.x * blockDim.x + threadIdx.x;
    if (i >= B * L * H * 32) return;
    int p = i & 31, t = i >> 5;
    int h = t & 15; t >>= 4;
    int l = t & 2047; int b = t >> 11;
    float c = fc[l * 32 + p], s = fs[l * 32 + p];
    size_t rb = ((size_t)b * L + l) * 3072 + h * 64 + 2 * p;
    float q0 = qkv[rb], q1 = qkv[rb + 1];
    float k0 = qkv[rb + 1024], k1 = qkv[rb + 1025];
    float v0 = qkv[rb + 2048], v1 = qkv[rb + 2049];
    int z = b * H + h;
    size_t qo = ((size_t)z * L + l) * 64 + 2 * p;
    qh[qo]   = __float2half(q0 * c - q1 * s);
    qh[qo+1] = __float2half(q0 * s + q1 * c);
    kh[qo]   = __float2half(k0 * c - k1 * s);
    kh[qo+1] = __float2half(k0 * s + k1 * c);
    vt[((size_t)z * 64 + 2*p)     * L + l] = __float2half(v0);
    vt[((size_t)z * 64 + 2*p + 1) * L + l] = __float2half(v1);
}
__global__ void ca_prep_q_kernel(const float* __restrict__ qc, half* __restrict__ qh) {
    int i = blockIdx.x * blockDim.x + threadIdx.x;
    if (i >= B * L * C) return;
    int col = i & 1023, row = i >> 10;
    int h = col >> 6, d = col & 63;
    int b = row >> 11, l = row & 2047;
    qh[(((size_t)(b * H + h)) * L + l) * 64 + d] = __float2half(qc[i]);
}
__global__ void ca_prep_kv_kernel(const float* __restrict__ kv,
                                  half* __restrict__ kh, half* __restrict__ vt) {
    int i = blockIdx.x * blockDim.x + threadIdx.x;
    if (i >= B * L2 * C) return;
    int col = i & 1023, row = i >> 10;
    int h = col >> 6, d = col & 63;
    int b = row >> 9, k = row & 511;
    int z = b * H + h;
    kh[((size_t)z * L2 + k) * 64 + d] = __float2half(kv[(size_t)row * 2048 + col]);
    vt[((size_t)z * 64 + d) * L2 + k] = __float2half(kv[(size_t)row * 2048 + 1024 + col]);
}
__global__ void softmax_kernel(half* __restrict__ S, float* __restrict__ ls, int Lk) {
    size_t base = (size_t)blockIdx.x * Lk;
    __shared__ float red[8];
    float m = -1e30f;
    for (int i = threadIdx.x; i < Lk; i += 256)
        m = fmaxf(m, __half2float(S[base + i]) * 0.125f);
#pragma unroll
    for (int o = 16; o > 0; o >>= 1) m = fmaxf(m, __shfl_xor_sync(0xffffffff, m, o));
    if ((threadIdx.x & 31) == 0) red[threadIdx.x >> 5] = m;
    __syncthreads();
    m = red[threadIdx.x & 7];
#pragma unroll
    for (int o = 4; o > 0; o >>= 1) m = fmaxf(m, __shfl_xor_sync(0xffffffff, m, o));
    float sum = 0.f;
    for (int i = threadIdx.x; i < Lk; i += 256) {
        float e = __expf(__half2float(S[base + i]) * 0.125f - m);
        S[base + i] = __float2half(e);
        sum += e;
    }
#pragma unroll
    for (int o = 16; o > 0; o >>= 1) sum += __shfl_xor_sync(0xffffffff, sum, o);
    if ((threadIdx.x & 31) == 0) red[threadIdx.x >> 5] = sum;
    __syncthreads();
    if (threadIdx.x == 0) {
        float t = 0.f;
#pragma unroll
        for (int w = 0; w < 8; w++) t += red[w];
        ls[blockIdx.x] = t;
    }
}
__global__ void o_finish_kernel(const float* __restrict__ O, const float* __restrict__ ls,
                                half* __restrict__ act) {
    int i = blockIdx.x * blockDim.x + threadIdx.x;
    if (i >= B * L * C) return;
    int col = i & 1023, row = i >> 10;
    int h = col >> 6, d = col & 63;
    int b = row >> 11, l = row & 2047;
    size_t zl = (size_t)(b * H + h) * L + l;
    act[i] = __float2half(O[zl * 64 + d] / ls[zl]);
}

// ---- converts ----
__global__ void wconvert_kernel(const float* __restrict__ W, half* __restrict__ Th,
                                int K, int N) {
    __shared__ float t[32][33];
    int k0 = blockIdx.y * 32, n0 = blockIdx.x * 32;
    int tx = threadIdx.x, ty = threadIdx.y;
#pragma unroll
    for (int i = 0; i < 32; i += 8) t[ty + i][tx] = W[(size_t)(k0 + ty + i) * N + n0 + tx];
    __syncthreads();
#pragma unroll
    for (int i = 0; i < 32; i += 8)
        Th[(size_t)(n0 + ty + i) * K + k0 + tx] = __float2half(t[tx][ty + i]);
}
static inline void wconvert(const float* W, half* Th, int K, int N) {
    wconvert_kernel<<<dim3(N/32, K/32), dim3(32, 8)>>>(W, Th, K, N);
}
__global__ void aconvert_kernel(const float* __restrict__ a, half* __restrict__ o, size_t n) {
    size_t i = (size_t)blockIdx.x * blockDim.x + threadIdx.x;
    if (i >= n) return;
    o[i] = __float2half(a[i]);
}

// ---- elementwise ----
__global__ void silu_kernel(const float* __restrict__ in, float* __restrict__ o, int n) {
    int i = blockIdx.x * blockDim.x + threadIdx.x;
    if (i >= n) return;
    float v = in[i];
    o[i] = v / (1.f + __expf(-v));
}
__global__ void rmsnorm_kernel(const float* __restrict__ x, const float* __restrict__ w,
                               const float* __restrict__ mods, const float* __restrict__ bias,
                               int sh_off, int sc_off, half* __restrict__ o) {
    int row = blockIdx.x, b = row / L;
    const float* xr = x + (size_t)row * C;
    float s = 0.f;
    for (int c = threadIdx.x; c < C; c += blockDim.x) { float v = xr[c]; s += v * v; }
    __shared__ float red[32];
#pragma unroll
    for (int o2 = 16; o2 > 0; o2 >>= 1) s += __shfl_down_sync(0xffffffff, s, o2);
    if ((threadIdx.x & 31) == 0) red[threadIdx.x >> 5] = s;
    __syncthreads();
    if (threadIdx.x < 32) {
        float v = (threadIdx.x < (blockDim.x >> 5)) ? red[threadIdx.x] : 0.f;
#pragma unroll
        for (int o2 = 16; o2 > 0; o2 >>= 1) v += __shfl_down_sync(0xffffffff, v, o2);
        if (threadIdx.x == 0) red[0] = v;
    }
    __syncthreads();
    float inv = rsqrtf(red[0] / (float)C + EPS);
    for (int c = threadIdx.x; c < C; c += blockDim.x) {
        float n = xr[c] * inv * w[c];
        if (mods) {
            float sc = mods[(size_t)b * 6 * C + sc_off + c] + bias[sc_off + c];
            float sh = mods[(size_t)b * 6 * C + sh_off + c] + bias[sh_off + c];
            n = n * (1.f + sc) + sh;
        }
        o[(size_t)row * C + c] = __float2half(n);
    }
}
__global__ void residual_kernel(const float* __restrict__ x, const float* __restrict__ p,
                                const float* __restrict__ mods, const float* __restrict__ bias,
                                int g_off, float* __restrict__ out) {
    size_t i = (size_t)blockIdx.x * blockDim.x + threadIdx.x;
    if (i >= (size_t)BL * C) return;
    float g = 1.f;
    if (mods) {
        int c = (int)(i % C), b = (int)(i / ((size_t)L * C));
        g = mods[(size_t)b * 6 * C + g_off + c] + bias[g_off + c];
    }
    out[i] = x[i] + g * p[i];
}
__global__ void swiglu_kernel(const float* __restrict__ gu, half* __restrict__ o, size_t n) {
    size_t i = (size_t)blockIdx.x * blockDim.x + threadIdx.x;
    if (i >= n) return;
    size_t row = i >> 12, c = i & (FF - 1);
    float v = gu[(row << 13) + c];
    float u = gu[(row << 13) + FF + c];
    o[i] = __float2half((v / (1.f + __expf(-v))) * u);
}

// ---- launch ----
#define GSYM(p, s) cudaGetSymbolAddress((void**)&p, s)
extern "C" void kernel_launch(void* const* d_in, const int* in_sizes, int n_in,
                              void* d_out, int out_size) {
    const float* x     = (const float*)d_in[0];
    const float* t_mod = (const float*)d_in[1];
    const float* audio = (const float*)d_in[2];
    const float* fcos  = (const float*)d_in[3];
    const float* fsin  = (const float*)d_in[4];
    const float* n1w   = (const float*)d_in[5];
    const float* n2w   = (const float*)d_in[6];
    const float* n3w   = (const float*)d_in[7];
    const float* Wqkv  = (const float*)d_in[8];
    const float* Wsa   = (const float*)d_in[9];
    const float* Wq    = (const float*)d_in[10];
    const float* Wkv   = (const float*)d_in[11];
    const float* Wca   = (const float*)d_in[12];
    const float* Wg    = (const float*)d_in[13];
    const float* Wu    = (const float*)d_in[14];
    const float* Wd    = (const float*)d_in[15];
    const float* adaW  = (const float*)d_in[16];
    const float* adaB  = (const float*)d_in[17];
    float* out = (float*)d_out;

    float *silu_p, *mods_p, *qkv_p, *proj_p, *x_p, *kv_p, *gu_p, *O_p, *ls_p;
    half *act, *ctx, *sm, *S_p, *qh_p, *kh_p, *vt_p;
    half *qkvw, *saw, *qw, *kvw, *caw, *guw, *dw, *adw;
    GSYM(silu_p, g_silu); GSYM(mods_p, g_mods); GSYM(qkv_p, g_qkv);
    GSYM(proj_p, g_proj); GSYM(x_p, g_x); GSYM(kv_p, g_kvc); GSYM(gu_p, g_gu);
    GSYM(act, g_act); GSYM(ctx, g_ctx); GSYM(sm, g_sm);
    GSYM(S_p, g_S); GSYM(O_p, g_O); GSYM(ls_p, g_ls);
    GSYM(qh_p, g_qh); GSYM(kh_p, g_kh); GSYM(vt_p, g_vt);
    GSYM(qkvw, w_qkv); GSYM(saw, w_sa); GSYM(qw, w_q); GSYM(kvw, w_kv);
    GSYM(caw, w_ca); GSYM(guw, w_gu); GSYM(dw, w_d); GSYM(adw, w_ada);

    const size_t NXC = (size_t)BL * C;
    wconvert(Wqkv, qkvw, C, 3*C);
    wconvert(Wsa,  saw,  C, C);
    wconvert(Wq,   qw,   C, C);
    wconvert(Wkv,  kvw,  TD, 2*C);
    wconvert(Wca,  caw,  C, C);
    wconvert(Wg,   guw,               C, FF);
    wconvert(Wu,   guw + (size_t)FF*C, C, FF);
    wconvert(Wd,   dw,   FF, C);
    wconvert(adaW, adw,  C, 6*C);

    // adaLN (M padded to 128; bias folded at consumers)
    silu_kernel<<<(B*C + 255)/256, 256>>>(t_mod, silu_p, B*C);
    aconvert_kernel<<<(128*C + 255)/256, 256>>>(silu_p, sm, 128*C);
    wgemm(sm, adw, mods_p, 128, 6*C, C);

    // ---- self-attention ----
    rmsnorm_kernel<<<BL, 256>>>(x, n1w, mods_p, adaB, 0, C, act);
    wgemm(act, qkvw, qkv_p, BL, 3*C, C);
    sa_prep_kernel<<<(B*L*H*32 + 255)/256, 256>>>(qkv_p, fcos, fsin, qh_p, kh_p, vt_p);
    qkgemm(qh_p, kh_p, S_p, L);
    softmax_kernel<<<ZB * L, 256>>>(S_p, ls_p, L);
    pvgemm(S_p, vt_p, O_p, L);
    o_finish_kernel<<<(B*L*C + 255)/256, 256>>>(O_p, ls_p, act);
    wgemm(act, saw, proj_p, BL, C, C);
    residual_kernel<<<(int)((NXC + 255)/256), 256>>>(x, proj_p, mods_p, adaB, 2*C, x_p);

    // ---- cross-attention ----
    rmsnorm_kernel<<<BL, 256>>>(x_p, n2w, nullptr, nullptr, 0, 0, act);
    wgemm(act, qw, qkv_p, BL, C, C);
    aconvert_kernel<<<(BL2*TD + 255)/256, 256>>>(audio, ctx, (size_t)BL2*TD);
    wgemm(ctx, kvw, kv_p, BL2, 2*C, TD);
    ca_prep_q_kernel<<<(B*L*C + 255)/256, 256>>>(qkv_p, qh_p);
    ca_prep_kv_kernel<<<(B*L2*C + 255)/256, 256>>>(kv_p, kh_p, vt_p);
    qkgemm(qh_p, kh_p, S_p, L2);
    softmax_kernel<<<ZB * L, 256>>>(S_p, ls_p, L2);
    pvgemm(S_p, vt_p, O_p, L2);
    o_finish_kernel<<<(B*L*C + 255)/256, 256>>>(O_p, ls_p, act);
    wgemm(act, caw, proj_p, BL, C, C);
    residual_kernel<<<(int)((NXC + 255)/256), 256>>>(x_p, proj_p, nullptr, nullptr, 0, x_p);

    // ---- MLP (gate+up fused, N=2*FF) ----
    rmsnorm_kernel<<<BL, 256>>>(x_p, n3w, mods_p, adaB, 3*C, 4*C, act);
    wgemm(act, guw, gu_p, BL, 2*FF, C);
    {
        size_t n = (size_t)BL * FF;
        swiglu_kernel<<<(int)((n + 255)/256), 256>>>(gu_p, act, n);
    }
    wgemm(act, dw, proj_p, BL, C, FF);
    residual_kernel<<<(int)((NXC + 255)/256), 256>>>(x_p, proj_p, mods_p, adaB, 5*C, out);
}

// round 10
// speedup vs baseline: 5.9091x; 1.2829x over previous
#include <cuda_runtime.h>
#include <cuda_fp16.h>
#include <stdint.h>

#define B 2
#define L 2048
#define C 1024
#define H 16
#define D 64
#define L2 512
#define TD 768
#define FF 4096
#define EPS 1e-6f
#define BL 4096
#define BL2 1024
#define ZB 32            // B*H batches

// ---- scratch ----
__device__ float g_silu[128 * C];
__device__ float g_mods[128 * 6 * C];
__device__ float g_qkv[BL * 3 * C];
__device__ float g_proj[BL * C];
__device__ float g_x[BL * C];
__device__ float g_kvc[BL2 * 2 * C];
__device__ float g_gu[(size_t)BL * 2 * FF];
__device__ half g_act[(size_t)BL * FF];
__device__ half g_ctx[BL2 * TD];
__device__ half g_sm[128 * C];
// attention operand buffers
__device__ half g_qh[(size_t)ZB * L * D];
__device__ half g_kh[(size_t)ZB * L * D];
__device__ half g_vt[(size_t)ZB * D * L];
// weights fp16, transposed [N][K]
__device__ half w_qkv[3*C*C];
__device__ half w_sa[C*C];
__device__ half w_q[C*C];
__device__ half w_kv[2*C*TD];
__device__ half w_ca[C*C];
__device__ half w_gu[(size_t)2*FF*C];
__device__ half w_d[(size_t)FF*C];
__device__ half w_ada[6*C*C];

// ---- helpers ----
__device__ __forceinline__ uint32_t smem_u32(const void* p) {
    uint32_t a;
    asm("{ .reg .u64 t; cvta.to.shared.u64 t, %1; cvt.u32.u64 %0, t; }" : "=r"(a) : "l"(p));
    return a;
}
__device__ __forceinline__ void cp16(uint32_t s, const void* g) {
    asm volatile("cp.async.cg.shared.global [%0], [%1], 16;" :: "r"(s), "l"(g));
}
__device__ __forceinline__ void ldsm4(uint32_t* r, uint32_t a) {
    asm volatile("ldmatrix.sync.aligned.m8n8.x4.shared.b16 {%0,%1,%2,%3}, [%4];"
        : "=r"(r[0]), "=r"(r[1]), "=r"(r[2]), "=r"(r[3]) : "r"(a));
}
__device__ __forceinline__ void mma16816(float* d, const uint32_t* a, uint32_t b0, uint32_t b1) {
    asm volatile("mma.sync.aligned.m16n8k16.row.col.f32.f16.f16.f32 "
        "{%0,%1,%2,%3}, {%4,%5,%6,%7}, {%8,%9}, {%0,%1,%2,%3};"
        : "+f"(d[0]), "+f"(d[1]), "+f"(d[2]), "+f"(d[3])
        : "r"(a[0]), "r"(a[1]), "r"(a[2]), "r"(a[3]), "r"(b0), "r"(b1));
}
__device__ __forceinline__ uint32_t h2pack(float a, float b) {
    half2 h = __floats2half2_rn(a, b);
    return *(uint32_t*)&h;
}

// ---- templated pipelined fp16 mma GEMM (weights path) ----
#define NSTAGE 3

template<int BN, typename OT>
__global__ void __launch_bounds__(256) gmma(
    const half* __restrict__ Ax, const half* __restrict__ B0,
    OT* __restrict__ Co, int M, int N, int K,
    size_t sA, size_t sB, size_t sC)
{
    constexpr int BNB = BN * 64;
    constexpr int STG = 8192 + BNB;
    constexpr int WN = (BN == 256) ? 4 : 2;
    constexpr int WM = 8 / WN;
    constexpr int MF = (128 / WM) / 16;
    constexpr int NF = (BN / WN) / 8;
    constexpr int TOT = 512 + BN * 4;

    extern __shared__ char smem[];
    uint32_t sb = smem_u32(smem);
    const int tid = threadIdx.x, lane = tid & 31, wid = tid >> 5;
    const int wm = (wid % WM) * MF * 16;
    const int wn = (wid / WM) * NF * 8;
    const int tM = blockIdx.y << 7, tN = blockIdx.x * BN;
    const int z = blockIdx.z;
    Ax += (size_t)z * sA; B0 += (size_t)z * sB; Co += (size_t)z * sC;

    float acc[MF][NF][4];
#pragma unroll
    for (int f = 0; f < MF; f++)
#pragma unroll
        for (int n = 0; n < NF; n++)
#pragma unroll
            for (int v = 0; v < 4; v++) acc[f][n][v] = 0.f;

    const int kIters = K >> 5;

    auto load_stage = [&](int s, int k0) {
        for (int id = tid; id < TOT; id += 256) {
            const half* g; uint32_t dst;
            if (id < 512) {
                int row = id >> 2, c = id & 3;
                g = Ax + (size_t)(tM + row) * K + k0 + (c << 3);
                dst = sb + s * STG + row * 64 + ((c ^ (row & 3)) << 4);
            } else {
                int a = id - 512;
                int row = a >> 2, c = a & 3;
                g = B0 + (size_t)(tN + row) * K + k0 + (c << 3);
                dst = sb + s * STG + 8192 + row * 64 + ((c ^ (row & 3)) << 4);
            }
            cp16(dst, g);
        }
    };

    for (int s = 0; s < NSTAGE - 1; s++) {
        load_stage(s, s << 5);
        asm volatile("cp.async.commit_group;");
    }

    const int lrow = lane & 15, lch = lane >> 4;

    for (int it = 0; it < kIters; it++) {
        asm volatile("cp.async.wait_group 1;");
        __syncthreads();
        if (it + NSTAGE - 1 < kIters)
            load_stage((it + NSTAGE - 1) % NSTAGE, (it + NSTAGE - 1) << 5);
        asm volatile("cp.async.commit_group;");

        uint32_t stg = sb + (uint32_t)(it % NSTAGE) * STG;
#pragma unroll
        for (int ks = 0; ks < 2; ks++) {
            int ch = (ks << 1) + lch;
            uint32_t a[MF][4], b[NF / 2][4];
#pragma unroll
            for (int f = 0; f < MF; f++) {
                int row = wm + (f << 4) + lrow;
                ldsm4(a[f], stg + row * 64 + ((ch ^ (row & 3)) << 4));
            }
#pragma unroll
            for (int p = 0; p < NF / 2; p++) {
                int row = wn + (p << 4) + lrow;
                ldsm4(b[p], stg + 8192u + row * 64 + ((ch ^ (row & 3)) << 4));
            }
#pragma unroll
            for (int f = 0; f < MF; f++)
#pragma unroll
                for (int n = 0; n < NF; n++)
                    mma16816(acc[f][n], a[f], b[n >> 1][n & 1], b[n >> 1][2 + (n & 1)]);
        }
    }

#pragma unroll
    for (int f = 0; f < MF; f++) {
        int r0 = tM + wm + (f << 4) + (lane >> 2);
#pragma unroll
        for (int n = 0; n < NF; n++) {
            int col = tN + wn + (n << 3) + ((lane & 3) << 1);
            if (sizeof(OT) == 4) {
                float2 v0 = {acc[f][n][0], acc[f][n][1]};
                float2 v1 = {acc[f][n][2], acc[f][n][3]};
                *(float2*)((float*)Co + (size_t)r0 * N + col) = v0;
                *(float2*)((float*)Co + (size_t)(r0 + 8) * N + col) = v1;
            } else {
                half2 v0 = __floats2half2_rn(acc[f][n][0], acc[f][n][1]);
                half2 v1 = __floats2half2_rn(acc[f][n][2], acc[f][n][3]);
                *(half2*)((half*)Co + (size_t)r0 * N + col) = v0;
                *(half2*)((half*)Co + (size_t)(r0 + 8) * N + col) = v1;
            }
        }
    }
}

static inline void wgemm(const half* A, const half* Bw, float* Co, int M, int N, int K) {
    constexpr int SM = NSTAGE * (8192 + 16384);
    cudaFuncSetAttribute(gmma<256,float>, cudaFuncAttributeMaxDynamicSharedMemorySize, SM);
    gmma<256,float><<<dim3(N/256, M/128, 1), 256, SM>>>(A, Bw, Co, M, N, K, 0, 0, 0);
}

// ---- fused flash attention (mma.sync, online softmax in registers) ----
// grid: (L/128, ZB). Q pre-scaled by 0.125. act out: [b*L+l][h*64+d] fp16.
#define FA_SMEM 49152   // Q 16K | KV buf0 16K | KV buf1 16K

__global__ void __launch_bounds__(256) fattn_kernel(
    const half* __restrict__ Qg, const half* __restrict__ Kg, const half* __restrict__ Vt,
    half* __restrict__ act, int Lk)
{
    extern __shared__ char smem[];
    uint32_t sb = smem_u32(smem);
    const uint32_t sQ = sb, sKV = sb + 16384;
    const int tid = threadIdx.x, lane = tid & 31, wid = tid >> 5;
    const int lrow = lane & 15, lch = lane >> 4;
    const int z = blockIdx.y;
    const int q0 = blockIdx.x << 7;
    const half* Qz = Qg + ((size_t)z * L + q0) * D;
    const half* Kz = Kg + (size_t)z * Lk * D;
    const half* Vz = Vt + (size_t)z * D * Lk;

    // Q tile load (128 rows x 128B, swizzled)
    for (int id = tid; id < 1024; id += 256) {
        int row = id >> 3, c = id & 7;
        cp16(sQ + row * 128 + ((c ^ (row & 7)) << 4), Qz + row * D + c * 8);
    }
    auto load_kv = [&](int j, int buf) {
        uint32_t base = sKV + (uint32_t)buf * 16384;
        for (int id = tid; id < 1024; id += 256) {
            int row = (id >> 3) & 63, c = id & 7;
            if (id < 512)
                cp16(base + row * 128 + ((c ^ (row & 7)) << 4),
                     Kz + (size_t)(j * 64 + row) * D + c * 8);
            else
                cp16(base + 8192 + row * 128 + ((c ^ (row & 7)) << 4),
                     Vz + (size_t)row * Lk + j * 64 + c * 8);
        }
    };
    load_kv(0, 0);
    asm volatile("cp.async.commit_group;");
    const int nch = Lk >> 6;
    load_kv(1, 1);
    asm volatile("cp.async.commit_group;");

    float accO[8][4];
#pragma unroll
    for (int n = 0; n < 8; n++)
#pragma unroll
        for (int v = 0; v < 4; v++) accO[n][v] = 0.f;
    float m0 = -1e30f, m1 = -1e30f, l0 = 0.f, l1 = 0.f;
    uint32_t aq[4][4];

    for (int j = 0; j < nch; j++) {
        asm volatile("cp.async.wait_group 1;");
        __syncthreads();
        if (j == 0) {
#pragma unroll
            for (int ks = 0; ks < 4; ks++) {
                int row = (wid << 4) + lrow;
                int ch = (ks << 1) + lch;
                ldsm4(aq[ks], sQ + row * 128 + ((ch ^ (row & 7)) << 4));
            }
        }
        uint32_t bK = sKV + (uint32_t)(j & 1) * 16384;
        uint32_t bV = bK + 8192;

        // S = Q @ K^T over this 64-kv chunk
        float s[8][4];
#pragma unroll
        for (int n = 0; n < 8; n++)
#pragma unroll
            for (int v = 0; v < 4; v++) s[n][v] = 0.f;
#pragma unroll
        for (int ks = 0; ks < 4; ks++) {
            uint32_t b[4][4];
            int ch = (ks << 1) + lch;
#pragma unroll
            for (int p = 0; p < 4; p++) {
                int row = (p << 4) + lrow;
                ldsm4(b[p], bK + row * 128 + ((ch ^ (row & 7)) << 4));
            }
#pragma unroll
            for (int n = 0; n < 8; n++)
                mma16816(s[n], aq[ks], b[n >> 1][n & 1], b[n >> 1][2 + (n & 1)]);
        }

        // online softmax (rows r0 = g, r1 = g+8)
        float mt0 = -1e30f, mt1 = -1e30f;
#pragma unroll
        for (int n = 0; n < 8; n++) {
            mt0 = fmaxf(mt0, fmaxf(s[n][0], s[n][1]));
            mt1 = fmaxf(mt1, fmaxf(s[n][2], s[n][3]));
        }
        mt0 = fmaxf(mt0, __shfl_xor_sync(0xffffffff, mt0, 1));
        mt0 = fmaxf(mt0, __shfl_xor_sync(0xffffffff, mt0, 2));
        mt1 = fmaxf(mt1, __shfl_xor_sync(0xffffffff, mt1, 1));
        mt1 = fmaxf(mt1, __shfl_xor_sync(0xffffffff, mt1, 2));
        float M0 = fmaxf(m0, mt0), M1 = fmaxf(m1, mt1);
        float c0 = __expf(m0 - M0), c1 = __expf(m1 - M1);
        m0 = M0; m1 = M1;
        float ls0 = 0.f, ls1 = 0.f;
#pragma unroll
        for (int n = 0; n < 8; n++) {
            s[n][0] = __expf(s[n][0] - M0);
            s[n][1] = __expf(s[n][1] - M0);
            s[n][2] = __expf(s[n][2] - M1);
            s[n][3] = __expf(s[n][3] - M1);
            ls0 += s[n][0] + s[n][1];
            ls1 += s[n][2] + s[n][3];
        }
        l0 = l0 * c0 + ls0;
        l1 = l1 * c1 + ls1;
#pragma unroll
        for (int n = 0; n < 8; n++) {
            accO[n][0] *= c0; accO[n][1] *= c0;
            accO[n][2] *= c1; accO[n][3] *= c1;
        }

        // pack P into A fragments (S C-layout == PV A-layout)
        uint32_t pa[4][4];
#pragma unroll
        for (int t = 0; t < 4; t++) {
            pa[t][0] = h2pack(s[2*t][0],   s[2*t][1]);
            pa[t][1] = h2pack(s[2*t][2],   s[2*t][3]);
            pa[t][2] = h2pack(s[2*t+1][0], s[2*t+1][1]);
            pa[t][3] = h2pack(s[2*t+1][2], s[2*t+1][3]);
        }

        // O += P @ V  (Vt tile: rows = d, cols = kv chunk)
#pragma unroll
        for (int kt = 0; kt < 4; kt++) {
            uint32_t b[4][4];
            int ch = (kt << 1) + lch;
#pragma unroll
            for (int p = 0; p < 4; p++) {
                int row = (p << 4) + lrow;
                ldsm4(b[p], bV + row * 128 + ((ch ^ (row & 7)) << 4));
            }
#pragma unroll
            for (int n = 0; n < 8; n++)
                mma16816(accO[n], pa[kt], b[n >> 1][n & 1], b[n >> 1][2 + (n & 1)]);
        }

        __syncthreads();
        if (j + 2 < nch) load_kv(j + 2, j & 1);
        asm volatile("cp.async.commit_group;");
    }

    // epilogue: normalize and write act[b*L+l][h*64+d]
    l0 += __shfl_xor_sync(0xffffffff, l0, 1);
    l0 += __shfl_xor_sync(0xffffffff, l0, 2);
    l1 += __shfl_xor_sync(0xffffffff, l1, 1);
    l1 += __shfl_xor_sync(0xffffffff, l1, 2);
    float inv0 = 1.f / l0, inv1 = 1.f / l1;
    int b = z >> 4, h = z & 15;
    int row0 = q0 + (wid << 4) + (lane >> 2);
    half* a0 = act + ((size_t)(b * L + row0) * C) + h * 64;
    half* a1 = a0 + (size_t)8 * C;
#pragma unroll
    for (int n = 0; n < 8; n++) {
        int col = (n << 3) + ((lane & 3) << 1);
        half2 v0 = __floats2half2_rn(accO[n][0] * inv0, accO[n][1] * inv0);
        half2 v1 = __floats2half2_rn(accO[n][2] * inv1, accO[n][3] * inv1);
        *(half2*)(a0 + col) = v0;
        *(half2*)(a1 + col) = v1;
    }
}

static inline void fattn(const half* Q, const half* K, const half* Vt, half* act, int Lk) {
    cudaFuncSetAttribute(fattn_kernel, cudaFuncAttributeMaxDynamicSharedMemorySize, FA_SMEM);
    fattn_kernel<<<dim3(L/128, ZB), 256, FA_SMEM>>>(Q, K, Vt, act, Lk);
}

// ---- attention preps (q pre-scaled by 0.125) ----
__global__ void sa_prep_kernel(const float* __restrict__ qkv,
                               const float* __restrict__ fc, const float* __restrict__ fs,
                               half* __restrict__ qh, half* __restrict__ kh,
                               half* __restrict__ vt) {
    int i = blockIdx.x * blockDim.x + threadIdx.x;
    if (i >= B * L * H * 32) return;
    int p = i & 31, t = i >> 5;
    int h = t & 15; t >>= 4;
    int l = t & 2047; int b = t >> 11;
    float c = fc[l * 32 + p], s = fs[l * 32 + p];
    size_t rb = ((size_t)b * L + l) * 3072 + h * 64 + 2 * p;
    float q0 = qkv[rb], q1 = qkv[rb + 1];
    float k0 = qkv[rb + 1024], k1 = qkv[rb + 1025];
    float v0 = qkv[rb + 2048], v1 = qkv[rb + 2049];
    int z = b * H + h;
    size_t qo = ((size_t)z * L + l) * 64 + 2 * p;
    qh[qo]   = __float2half((q0 * c - q1 * s) * 0.125f);
    qh[qo+1] = __float2half((q0 * s + q1 * c) * 0.125f);
    kh[qo]   = __float2half(k0 * c - k1 * s);
    kh[qo+1] = __float2half(k0 * s + k1 * c);
    vt[((size_t)z * 64 + 2*p)     * L + l] = __float2half(v0);
    vt[((size_t)z * 64 + 2*p + 1) * L + l] = __float2half(v1);
}
__global__ void ca_prep_q_kernel(const float* __restrict__ qc, half* __restrict__ qh) {
    int i = blockIdx.x * blockDim.x + threadIdx.x;
    if (i >= B * L * C) return;
    int col = i & 1023, row = i >> 10;
    int h = col >> 6, d = col & 63;
    int b = row >> 11, l = row & 2047;
    qh[(((size_t)(b * H + h)) * L + l) * 64 + d] = __float2half(qc[i] * 0.125f);
}
__global__ void ca_prep_kv_kernel(const float* __restrict__ kv,
                                  half* __restrict__ kh, half* __restrict__ vt) {
    int i = blockIdx.x * blockDim.x + threadIdx.x;
    if (i >= B * L2 * C) return;
    int col = i & 1023, row = i >> 10;
    int h = col >> 6, d = col & 63;
    int b = row >> 9, k = row & 511;
    int z = b * H + h;
    kh[((size_t)z * L2 + k) * 64 + d] = __float2half(kv[(size_t)row * 2048 + col]);
    vt[((size_t)z * 64 + d) * L2 + k] = __float2half(kv[(size_t)row * 2048 + 1024 + col]);
}

// ---- converts ----
__global__ void wconvert_kernel(const float* __restrict__ W, half* __restrict__ Th,
                                int K, int N) {
    __shared__ float t[32][33];
    int k0 = blockIdx.y * 32, n0 = blockIdx.x * 32;
    int tx = threadIdx.x, ty = threadIdx.y;
#pragma unroll
    for (int i = 0; i < 32; i += 8) t[ty + i][tx] = W[(size_t)(k0 + ty + i) * N + n0 + tx];
    __syncthreads();
#pragma unroll
    for (int i = 0; i < 32; i += 8)
        Th[(size_t)(n0 + ty + i) * K + k0 + tx] = __float2half(t[tx][ty + i]);
}
static inline void wconvert(const float* W, half* Th, int K, int N) {
    wconvert_kernel<<<dim3(N/32, K/32), dim3(32, 8)>>>(W, Th, K, N);
}
__global__ void aconvert_kernel(const float* __restrict__ a, half* __restrict__ o, size_t n) {
    size_t i = (size_t)blockIdx.x * blockDim.x + threadIdx.x;
    if (i >= n) return;
    o[i] = __float2half(a[i]);
}

// ---- elementwise ----
__global__ void silu_kernel(const float* __restrict__ in, float* __restrict__ o, int n) {
    int i = blockIdx.x * blockDim.x + threadIdx.x;
    if (i >= n) return;
    float v = in[i];
    o[i] = v / (1.f + __expf(-v));
}
__global__ void rmsnorm_kernel(const float* __restrict__ x, const float* __restrict__ w,
                               const float* __restrict__ mods, const float* __restrict__ bias,
                               int sh_off, int sc_off, half* __restrict__ o) {
    int row = blockIdx.x, b = row / L;
    const float* xr = x + (size_t)row * C;
    float s = 0.f;
    for (int c = threadIdx.x; c < C; c += blockDim.x) { float v = xr[c]; s += v * v; }
    __shared__ float red[32];
#pragma unroll
    for (int o2 = 16; o2 > 0; o2 >>= 1) s += __shfl_down_sync(0xffffffff, s, o2);
    if ((threadIdx.x & 31) == 0) red[threadIdx.x >> 5] = s;
    __syncthreads();
    if (threadIdx.x < 32) {
        float v = (threadIdx.x < (blockDim.x >> 5)) ? red[threadIdx.x] : 0.f;
#pragma unroll
        for (int o2 = 16; o2 > 0; o2 >>= 1) v += __shfl_down_sync(0xffffffff, v, o2);
        if (threadIdx.x == 0) red[0] = v;
    }
    __syncthreads();
    float inv = rsqrtf(red[0] / (float)C + EPS);
    for (int c = threadIdx.x; c < C; c += blockDim.x) {
        float n = xr[c] * inv * w[c];
        if (mods) {
            float sc = mods[(size_t)b * 6 * C + sc_off + c] + bias[sc_off + c];
            float sh = mods[(size_t)b * 6 * C + sh_off + c] + bias[sh_off + c];
            n = n * (1.f + sc) + sh;
        }
        o[(size_t)row * C + c] = __float2half(n);
    }
}
__global__ void residual_kernel(const float* __restrict__ x, const float* __restrict__ p,
                                const float* __restrict__ mods, const float* __restrict__ bias,
                                int g_off, float* __restrict__ out) {
    size_t i = (size_t)blockIdx.x * blockDim.x + threadIdx.x;
    if (i >= (size_t)BL * C) return;
    float g = 1.f;
    if (mods) {
        int c = (int)(i % C), b = (int)(i / ((size_t)L * C));
        g = mods[(size_t)b * 6 * C + g_off + c] + bias[g_off + c];
    }
    out[i] = x[i] + g * p[i];
}
__global__ void swiglu_kernel(const float* __restrict__ gu, half* __restrict__ o, size_t n) {
    size_t i = (size_t)blockIdx.x * blockDim.x + threadIdx.x;
    if (i >= n) return;
    size_t row = i >> 12, c = i & (FF - 1);
    float v = gu[(row << 13) + c];
    float u = gu[(row << 13) + FF + c];
    o[i] = __float2half((v / (1.f + __expf(-v))) * u);
}

// ---- launch ----
#define GSYM(p, s) cudaGetSymbolAddress((void**)&p, s)
extern "C" void kernel_launch(void* const* d_in, const int* in_sizes, int n_in,
                              void* d_out, int out_size) {
    const float* x     = (const float*)d_in[0];
    const float* t_mod = (const float*)d_in[1];
    const float* audio = (const float*)d_in[2];
    const float* fcos  = (const float*)d_in[3];
    const float* fsin  = (const float*)d_in[4];
    const float* n1w   = (const float*)d_in[5];
    const float* n2w   = (const float*)d_in[6];
    const float* n3w   = (const float*)d_in[7];
    const float* Wqkv  = (const float*)d_in[8];
    const float* Wsa   = (const float*)d_in[9];
    const float* Wq    = (const float*)d_in[10];
    const float* Wkv   = (const float*)d_in[11];
    const float* Wca   = (const float*)d_in[12];
    const float* Wg    = (const float*)d_in[13];
    const float* Wu    = (const float*)d_in[14];
    const float* Wd    = (const float*)d_in[15];
    const float* adaW  = (const float*)d_in[16];
    const float* adaB  = (const float*)d_in[17];
    float* out = (float*)d_out;

    float *silu_p, *mods_p, *qkv_p, *proj_p, *x_p, *kv_p, *gu_p;
    half *act, *ctx, *sm, *qh_p, *kh_p, *vt_p;
    half *qkvw, *saw, *qw, *kvw, *caw, *guw, *dw, *adw;
    GSYM(silu_p, g_silu); GSYM(mods_p, g_mods); GSYM(qkv_p, g_qkv);
    GSYM(proj_p, g_proj); GSYM(x_p, g_x); GSYM(kv_p, g_kvc); GSYM(gu_p, g_gu);
    GSYM(act, g_act); GSYM(ctx, g_ctx); GSYM(sm, g_sm);
    GSYM(qh_p, g_qh); GSYM(kh_p, g_kh); GSYM(vt_p, g_vt);
    GSYM(qkvw, w_qkv); GSYM(saw, w_sa); GSYM(qw, w_q); GSYM(kvw, w_kv);
    GSYM(caw, w_ca); GSYM(guw, w_gu); GSYM(dw, w_d); GSYM(adw, w_ada);

    const size_t NXC = (size_t)BL * C;
    wconvert(Wqkv, qkvw, C, 3*C);
    wconvert(Wsa,  saw,  C, C);
    wconvert(Wq,   qw,   C, C);
    wconvert(Wkv,  kvw,  TD, 2*C);
    wconvert(Wca,  caw,  C, C);
    wconvert(Wg,   guw,                C, FF);
    wconvert(Wu,   guw + (size_t)FF*C, C, FF);
    wconvert(Wd,   dw,   FF, C);
    wconvert(adaW, adw,  C, 6*C);

    // adaLN (M padded to 128; bias folded at consumers)
    silu_kernel<<<(B*C + 255)/256, 256>>>(t_mod, silu_p, B*C);
    aconvert_kernel<<<(128*C + 255)/256, 256>>>(silu_p, sm, 128*C);
    wgemm(sm, adw, mods_p, 128, 6*C, C);

    // ---- self-attention ----
    rmsnorm_kernel<<<BL, 256>>>(x, n1w, mods_p, adaB, 0, C, act);
    wgemm(act, qkvw, qkv_p, BL, 3*C, C);
    sa_prep_kernel<<<(B*L*H*32 + 255)/256, 256>>>(qkv_p, fcos, fsin, qh_p, kh_p, vt_p);
    fattn(qh_p, kh_p, vt_p, act, L);
    wgemm(act, saw, proj_p, BL, C, C);
    residual_kernel<<<(int)((NXC + 255)/256), 256>>>(x, proj_p, mods_p, adaB, 2*C, x_p);

    // ---- cross-attention ----
    rmsnorm_kernel<<<BL, 256>>>(x_p, n2w, nullptr, nullptr, 0, 0, act);
    wgemm(act, qw, qkv_p, BL, C, C);
    aconvert_kernel<<<(BL2*TD + 255)/256, 256>>>(audio, ctx, (size_t)BL2*TD);
    wgemm(ctx, kvw, kv_p, BL2, 2*C, TD);
    ca_prep_q_kernel<<<(B*L*C + 255)/256, 256>>>(qkv_p, qh_p);
    ca_prep_kv_kernel<<<(B*L2*C + 255)/256, 256>>>(kv_p, kh_p, vt_p);
    fattn(qh_p, kh_p, vt_p, act, L2);
    wgemm(act, caw, proj_p, BL, C, C);
    residual_kernel<<<(int)((NXC + 255)/256), 256>>>(x_p, proj_p, nullptr, nullptr, 0, x_p);

    // ---- MLP (gate+up fused, N=2*FF) ----
    rmsnorm_kernel<<<BL, 256>>>(x_p, n3w, mods_p, adaB, 3*C, 4*C, act);
    wgemm(act, guw, gu_p, BL, 2*FF, C);
    {
        size_t n = (size_t)BL * FF;
        swiglu_kernel<<<(int)((n + 255)/256), 256>>>(gu_p, act, n);
    }
    wgemm(act, dw, proj_p, BL, C, FF);
    residual_kernel<<<(int)((NXC + 255)/256), 256>>>(x_p, proj_p, mods_p, adaB, 5*C, out);
}

// round 11
// speedup vs baseline: 6.2192x; 1.0525x over previous
#include <cuda_runtime.h>
#include <cuda_fp16.h>
#include <stdint.h>

#define B 2
#define L 2048
#define C 1024
#define H 16
#define D 64
#define L2 512
#define TD 768
#define FF 4096
#define EPS 1e-6f
#define BL 4096
#define BL2 1024
#define ZB 32
#define SCL 0.180336880f   // 0.125 * log2(e): scores in log2 domain

// ---- scratch ----
__device__ float g_silu[128 * C];
__device__ float g_mods[128 * 6 * C];
__device__ float g_x[BL * C];
__device__ half g_qkvh[BL * 3 * C];
__device__ half g_kvh[BL2 * 2 * C];
__device__ half g_guh[(size_t)BL * 2 * FF];
__device__ half g_act[(size_t)BL * FF];
__device__ half g_ctx[BL2 * TD];
__device__ half g_sm[128 * C];
// attention operand buffers
__device__ half g_qh[(size_t)ZB * L * D];
__device__ half g_kh[(size_t)ZB * L * D];
__device__ half g_vt[(size_t)ZB * D * L];
// weights fp16, transposed [N][K]
__device__ half w_qkv[3*C*C];
__device__ half w_sa[C*C];
__device__ half w_q[C*C];
__device__ half w_kv[2*C*TD];
__device__ half w_ca[C*C];
__device__ half w_gu[(size_t)2*FF*C];
__device__ half w_d[(size_t)FF*C];
__device__ half w_ada[6*C*C];

// ---- helpers ----
__device__ __forceinline__ uint32_t smem_u32(const void* p) {
    uint32_t a;
    asm("{ .reg .u64 t; cvta.to.shared.u64 t, %1; cvt.u32.u64 %0, t; }" : "=r"(a) : "l"(p));
    return a;
}
__device__ __forceinline__ void cp16(uint32_t s, const void* g) {
    asm volatile("cp.async.cg.shared.global [%0], [%1], 16;" :: "r"(s), "l"(g));
}
__device__ __forceinline__ void ldsm4(uint32_t* r, uint32_t a) {
    asm volatile("ldmatrix.sync.aligned.m8n8.x4.shared.b16 {%0,%1,%2,%3}, [%4];"
        : "=r"(r[0]), "=r"(r[1]), "=r"(r[2]), "=r"(r[3]) : "r"(a));
}
__device__ __forceinline__ void mma16816(float* d, const uint32_t* a, uint32_t b0, uint32_t b1) {
    asm volatile("mma.sync.aligned.m16n8k16.row.col.f32.f16.f16.f32 "
        "{%0,%1,%2,%3}, {%4,%5,%6,%7}, {%8,%9}, {%0,%1,%2,%3};"
        : "+f"(d[0]), "+f"(d[1]), "+f"(d[2]), "+f"(d[3])
        : "r"(a[0]), "r"(a[1]), "r"(a[2]), "r"(a[3]), "r"(b0), "r"(b1));
}
// packed fp16 2^x of two floats: lo = 2^a, hi = 2^b
__device__ __forceinline__ uint32_t ex2h2(float a, float b) {
    uint32_t h;
    asm("{ .reg .b32 t;\n\t"
        "cvt.rn.f16x2.f32 t, %2, %1;\n\t"
        "ex2.approx.f16x2 %0, t; }"
        : "=r"(h) : "f"(a), "f"(b));
    return h;
}

// ---- templated pipelined fp16 mma GEMM with optional fused residual epilogue ----
// C[z][M,N] = A[z][M,K] @ B0[z][N,K]^T ; if resx: out = resx + gate*acc (float only)
#define NSTAGE 3

template<int BN, typename OT>
__global__ void __launch_bounds__(256) gmma(
    const half* __restrict__ Ax, const half* __restrict__ B0,
    OT* __restrict__ Co, int M, int N, int K,
    size_t sA, size_t sB, size_t sC,
    const float* __restrict__ resx, const float* __restrict__ mods,
    const float* __restrict__ bias, int goff)
{
    constexpr int BNB = BN * 64;
    constexpr int STG = 8192 + BNB;
    constexpr int WN = (BN == 256) ? 4 : 2;
    constexpr int WM = 8 / WN;
    constexpr int MF = (128 / WM) / 16;
    constexpr int NF = (BN / WN) / 8;
    constexpr int TOT = 512 + BN * 4;

    extern __shared__ char smem[];
    uint32_t sb = smem_u32(smem);
    const int tid = threadIdx.x, lane = tid & 31, wid = tid >> 5;
    const int wm = (wid % WM) * MF * 16;
    const int wn = (wid / WM) * NF * 8;
    const int tM = blockIdx.y << 7, tN = blockIdx.x * BN;
    const int z = blockIdx.z;
    Ax += (size_t)z * sA; B0 += (size_t)z * sB; Co += (size_t)z * sC;

    float acc[MF][NF][4];
#pragma unroll
    for (int f = 0; f < MF; f++)
#pragma unroll
        for (int n = 0; n < NF; n++)
#pragma unroll
            for (int v = 0; v < 4; v++) acc[f][n][v] = 0.f;

    const int kIters = K >> 5;

    auto load_stage = [&](int s, int k0) {
        for (int id = tid; id < TOT; id += 256) {
            const half* g; uint32_t dst;
            if (id < 512) {
                int row = id >> 2, c = id & 3;
                g = Ax + (size_t)(tM + row) * K + k0 + (c << 3);
                dst = sb + s * STG + row * 64 + ((c ^ (row & 3)) << 4);
            } else {
                int a = id - 512;
                int row = a >> 2, c = a & 3;
                g = B0 + (size_t)(tN + row) * K + k0 + (c << 3);
                dst = sb + s * STG + 8192 + row * 64 + ((c ^ (row & 3)) << 4);
            }
            cp16(dst, g);
        }
    };

    for (int s = 0; s < NSTAGE - 1; s++) {
        load_stage(s, s << 5);
        asm volatile("cp.async.commit_group;");
    }

    const int lrow = lane & 15, lch = lane >> 4;

    for (int it = 0; it < kIters; it++) {
        asm volatile("cp.async.wait_group 1;");
        __syncthreads();
        if (it + NSTAGE - 1 < kIters)
            load_stage((it + NSTAGE - 1) % NSTAGE, (it + NSTAGE - 1) << 5);
        asm volatile("cp.async.commit_group;");

        uint32_t stg = sb + (uint32_t)(it % NSTAGE) * STG;
#pragma unroll
        for (int ks = 0; ks < 2; ks++) {
            int ch = (ks << 1) + lch;
            uint32_t a[MF][4], b[NF / 2][4];
#pragma unroll
            for (int f = 0; f < MF; f++) {
                int row = wm + (f << 4) + lrow;
                ldsm4(a[f], stg + row * 64 + ((ch ^ (row & 3)) << 4));
            }
#pragma unroll
            for (int p = 0; p < NF / 2; p++) {
                int row = wn + (p << 4) + lrow;
                ldsm4(b[p], stg + 8192u + row * 64 + ((ch ^ (row & 3)) << 4));
            }
#pragma unroll
            for (int f = 0; f < MF; f++)
#pragma unroll
                for (int n = 0; n < NF; n++)
                    mma16816(acc[f][n], a[f], b[n >> 1][n & 1], b[n >> 1][2 + (n & 1)]);
        }
    }

    const int bb = tM >> 11;   // batch index for mods (only when resx)
#pragma unroll
    for (int f = 0; f < MF; f++) {
        int r0 = tM + wm + (f << 4) + (lane >> 2);
#pragma unroll
        for (int n = 0; n < NF; n++) {
            int col = tN + wn + (n << 3) + ((lane & 3) << 1);
            if (sizeof(OT) == 4) {
                float* Cf = (float*)Co;
                float v[4] = {acc[f][n][0], acc[f][n][1], acc[f][n][2], acc[f][n][3]};
                if (resx) {
                    float g0 = 1.f, g1 = 1.f;
                    if (mods) {
                        g0 = mods[(size_t)bb * 6 * C + goff + col]     + bias[goff + col];
                        g1 = mods[(size_t)bb * 6 * C + goff + col + 1] + bias[goff + col + 1];
                    }
                    v[0] = resx[(size_t)r0 * N + col]       + g0 * v[0];
                    v[1] = resx[(size_t)r0 * N + col + 1]   + g1 * v[1];
                    v[2] = resx[(size_t)(r0+8) * N + col]   + g0 * v[2];
                    v[3] = resx[(size_t)(r0+8) * N + col+1] + g1 * v[3];
                }
                *(float2*)(Cf + (size_t)r0 * N + col)       = make_float2(v[0], v[1]);
                *(float2*)(Cf + (size_t)(r0 + 8) * N + col) = make_float2(v[2], v[3]);
            } else {
                half2 v0 = __floats2half2_rn(acc[f][n][0], acc[f][n][1]);
                half2 v1 = __floats2half2_rn(acc[f][n][2], acc[f][n][3]);
                *(half2*)((half*)Co + (size_t)r0 * N + col) = v0;
                *(half2*)((half*)Co + (size_t)(r0 + 8) * N + col) = v1;
            }
        }
    }
}

#define GSM (NSTAGE * (8192 + 16384))
static inline void wgemm_f(const half* A, const half* Bw, float* Co, int M, int N, int K) {
    cudaFuncSetAttribute(gmma<256,float>, cudaFuncAttributeMaxDynamicSharedMemorySize, GSM);
    gmma<256,float><<<dim3(N/256, M/128, 1), 256, GSM>>>(A, Bw, Co, M, N, K, 0, 0, 0,
                                                         nullptr, nullptr, nullptr, 0);
}
static inline void wgemm_h(const half* A, const half* Bw, half* Co, int M, int N, int K) {
    cudaFuncSetAttribute(gmma<256,half>, cudaFuncAttributeMaxDynamicSharedMemorySize, GSM);
    gmma<256,half><<<dim3(N/256, M/128, 1), 256, GSM>>>(A, Bw, Co, M, N, K, 0, 0, 0,
                                                        nullptr, nullptr, nullptr, 0);
}
static inline void wgemm_res(const half* A, const half* Bw, float* Co, int M, int N, int K,
                             const float* resx, const float* mods, const float* bias, int goff) {
    cudaFuncSetAttribute(gmma<256,float>, cudaFuncAttributeMaxDynamicSharedMemorySize, GSM);
    gmma<256,float><<<dim3(N/256, M/128, 1), 256, GSM>>>(A, Bw, Co, M, N, K, 0, 0, 0,
                                                         resx, mods, bias, goff);
}

// ---- fused flash attention (ex2.f16x2 softmax, mma row-sums) ----
#define FA_SMEM 49152

__global__ void __launch_bounds__(256) fattn_kernel(
    const half* __restrict__ Qg, const half* __restrict__ Kg, const half* __restrict__ Vt,
    half* __restrict__ act, int Lk)
{
    extern __shared__ char smem[];
    uint32_t sb = smem_u32(smem);
    const uint32_t sQ = sb, sKV = sb + 16384;
    const int tid = threadIdx.x, lane = tid & 31, wid = tid >> 5;
    const int lrow = lane & 15, lch = lane >> 4;
    const int z = blockIdx.y;
    const int q0 = blockIdx.x << 7;
    const half* Qz = Qg + ((size_t)z * L + q0) * D;
    const half* Kz = Kg + (size_t)z * Lk * D;
    const half* Vz = Vt + (size_t)z * D * Lk;
    const uint32_t ONE2 = 0x3C003C00u;   // half2(1,1)

    for (int id = tid; id < 1024; id += 256) {
        int row = id >> 3, c = id & 7;
        cp16(sQ + row * 128 + ((c ^ (row & 7)) << 4), Qz + row * D + c * 8);
    }
    auto load_kv = [&](int j, int buf) {
        uint32_t base = sKV + (uint32_t)buf * 16384;
        for (int id = tid; id < 1024; id += 256) {
            int row = (id >> 3) & 63, c = id & 7;
            if (id < 512)
                cp16(base + row * 128 + ((c ^ (row & 7)) << 4),
                     Kz + (size_t)(j * 64 + row) * D + c * 8);
            else
                cp16(base + 8192 + row * 128 + ((c ^ (row & 7)) << 4),
                     Vz + (size_t)row * Lk + j * 64 + c * 8);
        }
    };
    load_kv(0, 0);
    asm volatile("cp.async.commit_group;");
    const int nch = Lk >> 6;
    load_kv(1, 1);
    asm volatile("cp.async.commit_group;");

    float accO[8][4], accL[4];
#pragma unroll
    for (int n = 0; n < 8; n++)
#pragma unroll
        for (int v = 0; v < 4; v++) accO[n][v] = 0.f;
#pragma unroll
    for (int v = 0; v < 4; v++) accL[v] = 0.f;
    float m0 = -1e30f, m1 = -1e30f;
    uint32_t aq[4][4];

    for (int j = 0; j < nch; j++) {
        asm volatile("cp.async.wait_group 1;");
        __syncthreads();
        if (j == 0) {
#pragma unroll
            for (int ks = 0; ks < 4; ks++) {
                int row = (wid << 4) + lrow;
                int ch = (ks << 1) + lch;
                ldsm4(aq[ks], sQ + row * 128 + ((ch ^ (row & 7)) << 4));
            }
        }
        uint32_t bK = sKV + (uint32_t)(j & 1) * 16384;
        uint32_t bV = bK + 8192;

        // S = Q @ K^T (log2 domain)
        float s[8][4];
#pragma unroll
        for (int n = 0; n < 8; n++)
#pragma unroll
            for (int v = 0; v < 4; v++) s[n][v] = 0.f;
#pragma unroll
        for (int ks = 0; ks < 4; ks++) {
            uint32_t b[4][4];
            int ch = (ks << 1) + lch;
#pragma unroll
            for (int p = 0; p < 4; p++) {
                int row = (p << 4) + lrow;
                ldsm4(b[p], bK + row * 128 + ((ch ^ (row & 7)) << 4));
            }
#pragma unroll
            for (int n = 0; n < 8; n++)
                mma16816(s[n], aq[ks], b[n >> 1][n & 1], b[n >> 1][2 + (n & 1)]);
        }

        // online softmax, base-2
        float mt0 = -1e30f, mt1 = -1e30f;
#pragma unroll
        for (int n = 0; n < 8; n++) {
            mt0 = fmaxf(mt0, fmaxf(s[n][0], s[n][1]));
            mt1 = fmaxf(mt1, fmaxf(s[n][2], s[n][3]));
        }
        mt0 = fmaxf(mt0, __shfl_xor_sync(0xffffffff, mt0, 1));
        mt0 = fmaxf(mt0, __shfl_xor_sync(0xffffffff, mt0, 2));
        mt1 = fmaxf(mt1, __shfl_xor_sync(0xffffffff, mt1, 1));
        mt1 = fmaxf(mt1, __shfl_xor_sync(0xffffffff, mt1, 2));
        float M0 = fmaxf(m0, mt0), M1 = fmaxf(m1, mt1);
        float c0 = exp2f(m0 - M0), c1 = exp2f(m1 - M1);
        m0 = M0; m1 = M1;

        // P = 2^(s - M) directly as packed fp16 A-fragments
        uint32_t pa[4][4];
#pragma unroll
        for (int t = 0; t < 4; t++) {
            pa[t][0] = ex2h2(s[2*t][0]   - M0, s[2*t][1]   - M0);
            pa[t][1] = ex2h2(s[2*t][2]   - M1, s[2*t][3]   - M1);
            pa[t][2] = ex2h2(s[2*t+1][0] - M0, s[2*t+1][1] - M0);
            pa[t][3] = ex2h2(s[2*t+1][2] - M1, s[2*t+1][3] - M1);
        }

        // rescale accumulators
#pragma unroll
        for (int n = 0; n < 8; n++) {
            accO[n][0] *= c0; accO[n][1] *= c0;
            accO[n][2] *= c1; accO[n][3] *= c1;
        }
        accL[0] *= c0; accL[2] *= c1;

        // row sums via mma with ones-B (exact w.r.t. fp16 P)
#pragma unroll
        for (int kt = 0; kt < 4; kt++)
            mma16816(accL, pa[kt], ONE2, ONE2);

        // O += P @ V
#pragma unroll
        for (int kt = 0; kt < 4; kt++) {
            uint32_t b[4][4];
            int ch = (kt << 1) + lch;
#pragma unroll
            for (int p = 0; p < 4; p++) {
                int row = (p << 4) + lrow;
                ldsm4(b[p], bV + row * 128 + ((ch ^ (row & 7)) << 4));
            }
#pragma unroll
            for (int n = 0; n < 8; n++)
                mma16816(accO[n], pa[kt], b[n >> 1][n & 1], b[n >> 1][2 + (n & 1)]);
        }

        __syncthreads();
        if (j + 2 < nch) load_kv(j + 2, j & 1);
        asm volatile("cp.async.commit_group;");
    }

    float inv0 = 1.f / accL[0], inv1 = 1.f / accL[2];
    int b = z >> 4, h = z & 15;
    int row0 = q0 + (wid << 4) + (lane >> 2);
    half* a0 = act + ((size_t)(b * L + row0) * C) + h * 64;
    half* a1 = a0 + (size_t)8 * C;
#pragma unroll
    for (int n = 0; n < 8; n++) {
        int col = (n << 3) + ((lane & 3) << 1);
        *(half2*)(a0 + col) = __floats2half2_rn(accO[n][0] * inv0, accO[n][1] * inv0);
        *(half2*)(a1 + col) = __floats2half2_rn(accO[n][2] * inv1, accO[n][3] * inv1);
    }
}

static inline void fattn(const half* Q, const half* K, const half* Vt, half* act, int Lk) {
    cudaFuncSetAttribute(fattn_kernel, cudaFuncAttributeMaxDynamicSharedMemorySize, FA_SMEM);
    fattn_kernel<<<dim3(L/128, ZB), 256, FA_SMEM>>>(Q, K, Vt, act, Lk);
}

// ---- attention preps (q pre-scaled by 0.125*log2e) ----
__global__ void sa_prep_kernel(const half* __restrict__ qkv,
                               const float* __restrict__ fc, const float* __restrict__ fs,
                               half* __restrict__ qh, half* __restrict__ kh,
                               half* __restrict__ vt) {
    int i = blockIdx.x * blockDim.x + threadIdx.x;
    if (i >= B * L * H * 32) return;
    int p = i & 31, t = i >> 5;
    int h = t & 15; t >>= 4;
    int l = t & 2047; int b = t >> 11;
    float c = fc[l * 32 + p], s = fs[l * 32 + p];
    size_t rb = ((size_t)b * L + l) * 3072 + h * 64 + 2 * p;
    float q0 = __half2float(qkv[rb]), q1 = __half2float(qkv[rb + 1]);
    float k0 = __half2float(qkv[rb + 1024]), k1 = __half2float(qkv[rb + 1025]);
    half v0 = qkv[rb + 2048], v1 = qkv[rb + 2049];
    int z = b * H + h;
    size_t qo = ((size_t)z * L + l) * 64 + 2 * p;
    qh[qo]   = __float2half((q0 * c - q1 * s) * SCL);
    qh[qo+1] = __float2half((q0 * s + q1 * c) * SCL);
    kh[qo]   = __float2half(k0 * c - k1 * s);
    kh[qo+1] = __float2half(k0 * s + k1 * c);
    vt[((size_t)z * 64 + 2*p)     * L + l] = v0;
    vt[((size_t)z * 64 + 2*p + 1) * L + l] = v1;
}
__global__ void ca_prep_q_kernel(const half* __restrict__ qc, half* __restrict__ qh) {
    int i = blockIdx.x * blockDim.x + threadIdx.x;
    if (i >= B * L * C) return;
    int col = i & 1023, row = i >> 10;
    int h = col >> 6, d = col & 63;
    int b = row >> 11, l = row & 2047;
    qh[(((size_t)(b * H + h)) * L + l) * 64 + d] = __float2half(__half2float(qc[i]) * SCL);
}
__global__ void ca_prep_kv_kernel(const half* __restrict__ kv,
                                  half* __restrict__ kh, half* __restrict__ vt) {
    int i = blockIdx.x * blockDim.x + threadIdx.x;
    if (i >= B * L2 * C) return;
    int col = i & 1023, row = i >> 10;
    int h = col >> 6, d = col & 63;
    int b = row >> 9, k = row & 511;
    int z = b * H + h;
    kh[((size_t)z * L2 + k) * 64 + d] = kv[(size_t)row * 2048 + col];
    vt[((size_t)z * 64 + d) * L2 + k] = kv[(size_t)row * 2048 + 1024 + col];
}

// ---- converts ----
__global__ void wconvert_kernel(const float* __restrict__ W, half* __restrict__ Th,
                                int K, int N) {
    __shared__ float t[32][33];
    int k0 = blockIdx.y * 32, n0 = blockIdx.x * 32;
    int tx = threadIdx.x, ty = threadIdx.y;
#pragma unroll
    for (int i = 0; i < 32; i += 8) t[ty + i][tx] = W[(size_t)(k0 + ty + i) * N + n0 + tx];
    __syncthreads();
#pragma unroll
    for (int i = 0; i < 32; i += 8)
        Th[(size_t)(n0 + ty + i) * K + k0 + tx] = __float2half(t[tx][ty + i]);
}
static inline void wconvert(const float* W, half* Th, int K, int N) {
    wconvert_kernel<<<dim3(N/32, K/32), dim3(32, 8)>>>(W, Th, K, N);
}
__global__ void aconvert_kernel(const float* __restrict__ a, half* __restrict__ o, size_t n) {
    size_t i = (size_t)blockIdx.x * blockDim.x + threadIdx.x;
    if (i >= n) return;
    o[i] = __float2half(a[i]);
}

// ---- elementwise ----
__global__ void silu_kernel(const float* __restrict__ in, float* __restrict__ o, int n) {
    int i = blockIdx.x * blockDim.x + threadIdx.x;
    if (i >= n) return;
    float v = in[i];
    o[i] = v / (1.f + __expf(-v));
}
__global__ void rmsnorm_kernel(const float* __restrict__ x, const float* __restrict__ w,
                               const float* __restrict__ mods, const float* __restrict__ bias,
                               int sh_off, int sc_off, half* __restrict__ o) {
    int row = blockIdx.x, b = row / L;
    const float* xr = x + (size_t)row * C;
    float s = 0.f;
    for (int c = threadIdx.x; c < C; c += blockDim.x) { float v = xr[c]; s += v * v; }
    __shared__ float red[32];
#pragma unroll
    for (int o2 = 16; o2 > 0; o2 >>= 1) s += __shfl_down_sync(0xffffffff, s, o2);
    if ((threadIdx.x & 31) == 0) red[threadIdx.x >> 5] = s;
    __syncthreads();
    if (threadIdx.x < 32) {
        float v = (threadIdx.x < (blockDim.x >> 5)) ? red[threadIdx.x] : 0.f;
#pragma unroll
        for (int o2 = 16; o2 > 0; o2 >>= 1) v += __shfl_down_sync(0xffffffff, v, o2);
        if (threadIdx.x == 0) red[0] = v;
    }
    __syncthreads();
    float inv = rsqrtf(red[0] / (float)C + EPS);
    for (int c = threadIdx.x; c < C; c += blockDim.x) {
        float n = xr[c] * inv * w[c];
        if (mods) {
            float sc = mods[(size_t)b * 6 * C + sc_off + c] + bias[sc_off + c];
            float sh = mods[(size_t)b * 6 * C + sh_off + c] + bias[sh_off + c];
            n = n * (1.f + sc) + sh;
        }
        o[(size_t)row * C + c] = __float2half(n);
    }
}
// gu half [row][2FF]: gate cols [0,FF), up cols [FF,2FF); act half out (half2 grain)
__global__ void swiglu_kernel(const half* __restrict__ gu, half* __restrict__ o, size_t n2) {
    size_t i = (size_t)blockIdx.x * blockDim.x + threadIdx.x;
    if (i >= n2) return;
    size_t row = i >> 11, cp = i & 2047;            // FF/2 = 2048 half2 per row
    const half2* g2 = (const half2*)gu + (row << 12) + cp;   // 2FF/2 = 4096
    float2 g = __half22float2(*g2);
    float2 u = __half22float2(*(g2 + 2048));
    float r0 = (g.x / (1.f + __expf(-g.x))) * u.x;
    float r1 = (g.y / (1.f + __expf(-g.y))) * u.y;
    ((half2*)o)[i] = __floats2half2_rn(r0, r1);
}

// ---- launch ----
#define GSYM(p, s) cudaGetSymbolAddress((void**)&p, s)
extern "C" void kernel_launch(void* const* d_in, const int* in_sizes, int n_in,
                              void* d_out, int out_size) {
    const float* x     = (const float*)d_in[0];
    const float* t_mod = (const float*)d_in[1];
    const float* audio = (const float*)d_in[2];
    const float* fcos  = (const float*)d_in[3];
    const float* fsin  = (const float*)d_in[4];
    const float* n1w   = (const float*)d_in[5];
    const float* n2w   = (const float*)d_in[6];
    const float* n3w   = (const float*)d_in[7];
    const float* Wqkv  = (const float*)d_in[8];
    const float* Wsa   = (const float*)d_in[9];
    const float* Wq    = (const float*)d_in[10];
    const float* Wkv   = (const float*)d_in[11];
    const float* Wca   = (const float*)d_in[12];
    const float* Wg    = (const float*)d_in[13];
    const float* Wu    = (const float*)d_in[14];
    const float* Wd    = (const float*)d_in[15];
    const float* adaW  = (const float*)d_in[16];
    const float* adaB  = (const float*)d_in[17];
    float* out = (float*)d_out;

    float *silu_p, *mods_p, *x_p;
    half *qkvh_p, *kvh_p, *guh_p, *act, *ctx, *sm, *qh_p, *kh_p, *vt_p;
    half *qkvw, *saw, *qw, *kvw, *caw, *guw, *dw, *adw;
    GSYM(silu_p, g_silu); GSYM(mods_p, g_mods); GSYM(x_p, g_x);
    GSYM(qkvh_p, g_qkvh); GSYM(kvh_p, g_kvh); GSYM(guh_p, g_guh);
    GSYM(act, g_act); GSYM(ctx, g_ctx); GSYM(sm, g_sm);
    GSYM(qh_p, g_qh); GSYM(kh_p, g_kh); GSYM(vt_p, g_vt);
    GSYM(qkvw, w_qkv); GSYM(saw, w_sa); GSYM(qw, w_q); GSYM(kvw, w_kv);
    GSYM(caw, w_ca); GSYM(guw, w_gu); GSYM(dw, w_d); GSYM(adw, w_ada);

    wconvert(Wqkv, qkvw, C, 3*C);
    wconvert(Wsa,  saw,  C, C);
    wconvert(Wq,   qw,   C, C);
    wconvert(Wkv,  kvw,  TD, 2*C);
    wconvert(Wca,  caw,  C, C);
    wconvert(Wg,   guw,                C, FF);
    wconvert(Wu,   guw + (size_t)FF*C, C, FF);
    wconvert(Wd,   dw,   FF, C);
    wconvert(adaW, adw,  C, 6*C);

    // adaLN (M padded to 128; bias folded at consumers)
    silu_kernel<<<(B*C + 255)/256, 256>>>(t_mod, silu_p, B*C);
    aconvert_kernel<<<(128*C + 255)/256, 256>>>(silu_p, sm, 128*C);
    wgemm_f(sm, adw, mods_p, 128, 6*C, C);

    // ---- self-attention ----
    rmsnorm_kernel<<<BL, 256>>>(x, n1w, mods_p, adaB, 0, C, act);
    wgemm_h(act, qkvw, qkvh_p, BL, 3*C, C);
    sa_prep_kernel<<<(B*L*H*32 + 255)/256, 256>>>(qkvh_p, fcos, fsin, qh_p, kh_p, vt_p);
    fattn(qh_p, kh_p, vt_p, act, L);
    wgemm_res(act, saw, x_p, BL, C, C, x, mods_p, adaB, 2*C);

    // ---- cross-attention ----
    rmsnorm_kernel<<<BL, 256>>>(x_p, n2w, nullptr, nullptr, 0, 0, act);
    wgemm_h(act, qw, qkvh_p, BL, C, C);
    aconvert_kernel<<<(BL2*TD + 255)/256, 256>>>(audio, ctx, (size_t)BL2*TD);
    wgemm_h(ctx, kvw, kvh_p, BL2, 2*C, TD);
    ca_prep_q_kernel<<<(B*L*C + 255)/256, 256>>>(qkvh_p, qh_p);
    ca_prep_kv_kernel<<<(B*L2*C + 255)/256, 256>>>(kvh_p, kh_p, vt_p);
    fattn(qh_p, kh_p, vt_p, act, L2);
    wgemm_res(act, caw, x_p, BL, C, C, x_p, nullptr, nullptr, 0);

    // ---- MLP (gate+up fused, N=2*FF) ----
    rmsnorm_kernel<<<BL, 256>>>(x_p, n3w, mods_p, adaB, 3*C, 4*C, act);
    wgemm_h(act, guw, guh_p, BL, 2*FF, C);
    {
        size_t n2 = (size_t)BL * FF / 2;
        swiglu_kernel<<<(int)((n2 + 255)/256), 256>>>(guh_p, act, n2);
    }
    wgemm_res(act, dw, out, BL, C, FF, x_p, mods_p, adaB, 5*C);
}

// round 12
// speedup vs baseline: 6.6482x; 1.0690x over previous
#include <cuda_runtime.h>
#include <cuda_fp16.h>
#include <stdint.h>

#define B 2
#define L 2048
#define C 1024
#define H 16
#define D 64
#define L2 512
#define TD 768
#define FF 4096
#define EPS 1e-6f
#define BL 4096
#define BL2 1024
#define ZB 32
#define SCL 0.180336880f   // 0.125 * log2(e)

// ---- scratch ----
__device__ float g_silu[128 * C];
__device__ float g_mods[128 * 6 * C];
__device__ float g_x[BL * C];
__device__ half g_h[(size_t)BL * FF];        // mlp hidden
__device__ half g_act[(size_t)BL * C];       // attention io
__device__ half g_ctx[BL2 * TD];
__device__ half g_sm[128 * C];
__device__ half g_qh[(size_t)ZB * L * D];
__device__ half g_kh[(size_t)ZB * L * D];
__device__ half g_vt[(size_t)ZB * D * L];
// weights fp16, transposed [N][K]
__device__ half w_qkv[3*C*C];
__device__ half w_sa[C*C];
__device__ half w_q[C*C];
__device__ half w_kv[2*C*TD];
__device__ half w_ca[C*C];
__device__ half w_gu[(size_t)2*FF*C];        // gate/up row-interleaved
__device__ half w_d[(size_t)FF*C];
__device__ half w_ada[6*C*C];

// ---- helpers ----
__device__ __forceinline__ uint32_t smem_u32(const void* p) {
    uint32_t a;
    asm("{ .reg .u64 t; cvta.to.shared.u64 t, %1; cvt.u32.u64 %0, t; }" : "=r"(a) : "l"(p));
    return a;
}
__device__ __forceinline__ void cp16(uint32_t s, const void* g) {
    asm volatile("cp.async.cg.shared.global [%0], [%1], 16;" :: "r"(s), "l"(g));
}
__device__ __forceinline__ void ldsm4(uint32_t* r, uint32_t a) {
    asm volatile("ldmatrix.sync.aligned.m8n8.x4.shared.b16 {%0,%1,%2,%3}, [%4];"
        : "=r"(r[0]), "=r"(r[1]), "=r"(r[2]), "=r"(r[3]) : "r"(a));
}
__device__ __forceinline__ void mma16816(float* d, const uint32_t* a, uint32_t b0, uint32_t b1) {
    asm volatile("mma.sync.aligned.m16n8k16.row.col.f32.f16.f16.f32 "
        "{%0,%1,%2,%3}, {%4,%5,%6,%7}, {%8,%9}, {%0,%1,%2,%3};"
        : "+f"(d[0]), "+f"(d[1]), "+f"(d[2]), "+f"(d[3])
        : "r"(a[0]), "r"(a[1]), "r"(a[2]), "r"(a[3]), "r"(b0), "r"(b1));
}
__device__ __forceinline__ uint32_t ex2h2(float a, float b) {
    uint32_t h;
    asm("{ .reg .b32 t;\n\t"
        "cvt.rn.f16x2.f32 t, %2, %1;\n\t"
        "ex2.approx.f16x2 %0, t; }"
        : "=r"(h) : "f"(a), "f"(b));
    return h;
}
__device__ __forceinline__ float siluf(float v) { return v / (1.f + __expf(-v)); }

// ---- pipelined fp16 mma GEMM with fused epilogues ----
// EPI: 0 = float out (+ optional residual x + gate*acc)
//      2 = swiglu: interleaved gate/up cols -> half out [M][FF]
//      3 = SA qkv: rope q,k -> qh,kh; v -> vt  (N=3072, Lk=L)
//      4 = CA q: scale -> qh                    (N=1024, Lk=L)
//      5 = CA kv: k -> kh, v -> vt              (N=2048, Lk=L2, M=BL2)
#define NSTAGE 3

template<int EPI>
__global__ void __launch_bounds__(256) gmma(
    const half* __restrict__ Ax, const half* __restrict__ B0,
    void* __restrict__ Cout, int M, int N, int K,
    const float* __restrict__ resx, const float* __restrict__ mods,
    const float* __restrict__ bias, int goff,
    const float* __restrict__ fc, const float* __restrict__ fs,
    half* __restrict__ khp, half* __restrict__ vtp, int Lk)
{
    constexpr int STG = 8192 + 16384;
    extern __shared__ char smem[];
    uint32_t sb = smem_u32(smem);
    const int tid = threadIdx.x, lane = tid & 31, wid = tid >> 5;
    const int wm = (wid & 1) << 6;          // WM=2
    const int wn = (wid >> 1) << 6;         // WN=4, 64 cols each
    const int tM = blockIdx.y << 7, tN = blockIdx.x << 8;

    float acc[4][8][4];
#pragma unroll
    for (int f = 0; f < 4; f++)
#pragma unroll
        for (int n = 0; n < 8; n++)
#pragma unroll
            for (int v = 0; v < 4; v++) acc[f][n][v] = 0.f;

    const int kIters = K >> 5;

    auto load_stage = [&](int s, int k0) {
        for (int id = tid; id < 1536; id += 256) {
            const half* g; uint32_t dst;
            if (id < 512) {
                int row = id >> 2, c = id & 3;
                g = Ax + (size_t)(tM + row) * K + k0 + (c << 3);
                dst = sb + s * STG + row * 64 + ((c ^ (row & 3)) << 4);
            } else {
                int a = id - 512;
                int row = a >> 2, c = a & 3;
                g = B0 + (size_t)(tN + row) * K + k0 + (c << 3);
                dst = sb + s * STG + 8192 + row * 64 + ((c ^ (row & 3)) << 4);
            }
            cp16(dst, g);
        }
    };

    for (int s = 0; s < NSTAGE - 1; s++) {
        load_stage(s, s << 5);
        asm volatile("cp.async.commit_group;");
    }

    const int lrow = lane & 15, lch = lane >> 4;

    for (int it = 0; it < kIters; it++) {
        asm volatile("cp.async.wait_group 1;");
        __syncthreads();
        if (it + NSTAGE - 1 < kIters)
            load_stage((it + NSTAGE - 1) % NSTAGE, (it + NSTAGE - 1) << 5);
        asm volatile("cp.async.commit_group;");

        uint32_t stg = sb + (uint32_t)(it % NSTAGE) * STG;
#pragma unroll
        for (int ks = 0; ks < 2; ks++) {
            int ch = (ks << 1) + lch;
            uint32_t a[4][4], b[4][4];
#pragma unroll
            for (int f = 0; f < 4; f++) {
                int row = wm + (f << 4) + lrow;
                ldsm4(a[f], stg + row * 64 + ((ch ^ (row & 3)) << 4));
            }
#pragma unroll
            for (int p = 0; p < 4; p++) {
                int row = wn + (p << 4) + lrow;
                ldsm4(b[p], stg + 8192u + row * 64 + ((ch ^ (row & 3)) << 4));
            }
#pragma unroll
            for (int f = 0; f < 4; f++)
#pragma unroll
                for (int n = 0; n < 8; n++)
                    mma16816(acc[f][n], a[f], b[n >> 1][n & 1], b[n >> 1][2 + (n & 1)]);
        }
    }

    const int bb = (EPI == 5) ? 0 : (tM >> 11);
#pragma unroll
    for (int f = 0; f < 4; f++) {
        int r0 = tM + wm + (f << 4) + (lane >> 2);
#pragma unroll
        for (int n = 0; n < 8; n++) {
            int col = tN + wn + (n << 3) + ((lane & 3) << 1);
            float v0 = acc[f][n][0], v1 = acc[f][n][1];
            float v2 = acc[f][n][2], v3 = acc[f][n][3];
            if (EPI == 0) {
                float* Cf = (float*)Cout;
                if (resx) {
                    float g0 = 1.f, g1 = 1.f;
                    if (mods) {
                        g0 = mods[(size_t)bb * 6 * C + goff + col]     + bias[goff + col];
                        g1 = mods[(size_t)bb * 6 * C + goff + col + 1] + bias[goff + col + 1];
                    }
                    v0 = resx[(size_t)r0 * N + col]         + g0 * v0;
                    v1 = resx[(size_t)r0 * N + col + 1]     + g1 * v1;
                    v2 = resx[(size_t)(r0+8) * N + col]     + g0 * v2;
                    v3 = resx[(size_t)(r0+8) * N + col + 1] + g1 * v3;
                }
                *(float2*)(Cf + (size_t)r0 * N + col)       = make_float2(v0, v1);
                *(float2*)(Cf + (size_t)(r0 + 8) * N + col) = make_float2(v2, v3);
            } else if (EPI == 2) {
                half* act = (half*)Cout;
                int oc = col >> 1;
                act[(size_t)r0 * FF + oc]       = __float2half(siluf(v0) * v1);
                act[(size_t)(r0 + 8) * FF + oc] = __float2half(siluf(v2) * v3);
            } else if (EPI == 3) {
                int l0 = r0 & 2047, l1 = (r0 + 8) & 2047;
                int sec = col >> 10, cc = col & 1023;
                int h = cc >> 6, d = cc & 63, p = d >> 1;
                int z = bb * H + h;
                if (sec < 2) {
                    float c0 = fc[l0*32+p], s0 = fs[l0*32+p];
                    float c1 = fc[l1*32+p], s1 = fs[l1*32+p];
                    float a0 = v0*c0 - v1*s0, b0 = v0*s0 + v1*c0;
                    float a1 = v2*c1 - v3*s1, b1 = v2*s1 + v3*c1;
                    half* dst;
                    if (sec == 0) { a0*=SCL; b0*=SCL; a1*=SCL; b1*=SCL; dst = (half*)Cout; }
                    else dst = khp;
                    *(half2*)(dst + ((size_t)z * L + l0) * 64 + d) = __floats2half2_rn(a0, b0);
                    *(half2*)(dst + ((size_t)z * L + l1) * 64 + d) = __floats2half2_rn(a1, b1);
                } else {
                    vtp[((size_t)z * 64 + d)     * L + l0] = __float2half(v0);
                    vtp[((size_t)z * 64 + d + 1) * L + l0] = __float2half(v1);
                    vtp[((size_t)z * 64 + d)     * L + l1] = __float2half(v2);
                    vtp[((size_t)z * 64 + d + 1) * L + l1] = __float2half(v3);
                }
            } else if (EPI == 4) {
                int l0 = r0 & 2047, l1 = (r0 + 8) & 2047;
                int h = col >> 6, d = col & 63;
                int z = bb * H + h;
                half* qh = (half*)Cout;
                *(half2*)(qh + ((size_t)z * L + l0) * 64 + d) = __floats2half2_rn(v0*SCL, v1*SCL);
                *(half2*)(qh + ((size_t)z * L + l1) * 64 + d) = __floats2half2_rn(v2*SCL, v3*SCL);
            } else if (EPI == 5) {
                int b2 = r0 >> 9;
                int k0 = r0 & 511, k1 = (r0 + 8) & 511;
                int sec = col >> 10, cc = col & 1023;
                int h = cc >> 6, d = cc & 63;
                int z = b2 * H + h;
                if (sec == 0) {
                    half* kh = (half*)Cout;
                    *(half2*)(kh + ((size_t)z * L2 + k0) * 64 + d) = __floats2half2_rn(v0, v1);
                    *(half2*)(kh + ((size_t)z * L2 + k1) * 64 + d) = __floats2half2_rn(v2, v3);
                } else {
                    vtp[((size_t)z * 64 + d)     * L2 + k0] = __float2half(v0);
                    vtp[((size_t)z * 64 + d + 1) * L2 + k0] = __float2half(v1);
                    vtp[((size_t)z * 64 + d)     * L2 + k1] = __float2half(v2);
                    vtp[((size_t)z * 64 + d + 1) * L2 + k1] = __float2half(v3);
                }
            }
        }
    }
}

#define GSM (NSTAGE * (8192 + 16384))
template<int EPI>
static inline void launch_gmma(const half* A, const half* Bw, void* Co, int M, int N, int K,
                               const float* resx, const float* mods, const float* bias, int goff,
                               const float* fc, const float* fs, half* kh, half* vt, int Lk) {
    cudaFuncSetAttribute(gmma<EPI>, cudaFuncAttributeMaxDynamicSharedMemorySize, GSM);
    gmma<EPI><<<dim3(N/256, M/128), 256, GSM>>>(A, Bw, Co, M, N, K,
                                                resx, mods, bias, goff, fc, fs, kh, vt, Lk);
}

// ---- fused flash attention (ex2.f16x2 softmax, mma row-sums) ----
#define FA_SMEM 49152

__global__ void __launch_bounds__(256) fattn_kernel(
    const half* __restrict__ Qg, const half* __restrict__ Kg, const half* __restrict__ Vt,
    half* __restrict__ act, int Lk)
{
    extern __shared__ char smem[];
    uint32_t sb = smem_u32(smem);
    const uint32_t sQ = sb, sKV = sb + 16384;
    const int tid = threadIdx.x, lane = tid & 31, wid = tid >> 5;
    const int lrow = lane & 15, lch = lane >> 4;
    const int z = blockIdx.y;
    const int q0 = blockIdx.x << 7;
    const half* Qz = Qg + ((size_t)z * L + q0) * D;
    const half* Kz = Kg + (size_t)z * Lk * D;
    const half* Vz = Vt + (size_t)z * D * Lk;
    const uint32_t ONE2 = 0x3C003C00u;

    for (int id = tid; id < 1024; id += 256) {
        int row = id >> 3, c = id & 7;
        cp16(sQ + row * 128 + ((c ^ (row & 7)) << 4), Qz + row * D + c * 8);
    }
    auto load_kv = [&](int j, int buf) {
        uint32_t base = sKV + (uint32_t)buf * 16384;
        for (int id = tid; id < 1024; id += 256) {
            int row = (id >> 3) & 63, c = id & 7;
            if (id < 512)
                cp16(base + row * 128 + ((c ^ (row & 7)) << 4),
                     Kz + (size_t)(j * 64 + row) * D + c * 8);
            else
                cp16(base + 8192 + row * 128 + ((c ^ (row & 7)) << 4),
                     Vz + (size_t)row * Lk + j * 64 + c * 8);
        }
    };
    load_kv(0, 0);
    asm volatile("cp.async.commit_group;");
    const int nch = Lk >> 6;
    load_kv(1, 1);
    asm volatile("cp.async.commit_group;");

    float accO[8][4], accL[4];
#pragma unroll
    for (int n = 0; n < 8; n++)
#pragma unroll
        for (int v = 0; v < 4; v++) accO[n][v] = 0.f;
#pragma unroll
    for (int v = 0; v < 4; v++) accL[v] = 0.f;
    float m0 = -1e30f, m1 = -1e30f;
    uint32_t aq[4][4];

    for (int j = 0; j < nch; j++) {
        asm volatile("cp.async.wait_group 1;");
        __syncthreads();
        if (j == 0) {
#pragma unroll
            for (int ks = 0; ks < 4; ks++) {
                int row = (wid << 4) + lrow;
                int ch = (ks << 1) + lch;
                ldsm4(aq[ks], sQ + row * 128 + ((ch ^ (row & 7)) << 4));
            }
        }
        uint32_t bK = sKV + (uint32_t)(j & 1) * 16384;
        uint32_t bV = bK + 8192;

        float s[8][4];
#pragma unroll
        for (int n = 0; n < 8; n++)
#pragma unroll
            for (int v = 0; v < 4; v++) s[n][v] = 0.f;
#pragma unroll
        for (int ks = 0; ks < 4; ks++) {
            uint32_t b[4][4];
            int ch = (ks << 1) + lch;
#pragma unroll
            for (int p = 0; p < 4; p++) {
                int row = (p << 4) + lrow;
                ldsm4(b[p], bK + row * 128 + ((ch ^ (row & 7)) << 4));
            }
#pragma unroll
            for (int n = 0; n < 8; n++)
                mma16816(s[n], aq[ks], b[n >> 1][n & 1], b[n >> 1][2 + (n & 1)]);
        }

        float mt0 = -1e30f, mt1 = -1e30f;
#pragma unroll
        for (int n = 0; n < 8; n++) {
            mt0 = fmaxf(mt0, fmaxf(s[n][0], s[n][1]));
            mt1 = fmaxf(mt1, fmaxf(s[n][2], s[n][3]));
        }
        mt0 = fmaxf(mt0, __shfl_xor_sync(0xffffffff, mt0, 1));
        mt0 = fmaxf(mt0, __shfl_xor_sync(0xffffffff, mt0, 2));
        mt1 = fmaxf(mt1, __shfl_xor_sync(0xffffffff, mt1, 1));
        mt1 = fmaxf(mt1, __shfl_xor_sync(0xffffffff, mt1, 2));
        float M0 = fmaxf(m0, mt0), M1 = fmaxf(m1, mt1);
        float c0 = exp2f(m0 - M0), c1 = exp2f(m1 - M1);
        m0 = M0; m1 = M1;

        uint32_t pa[4][4];
#pragma unroll
        for (int t = 0; t < 4; t++) {
            pa[t][0] = ex2h2(s[2*t][0]   - M0, s[2*t][1]   - M0);
            pa[t][1] = ex2h2(s[2*t][2]   - M1, s[2*t][3]   - M1);
            pa[t][2] = ex2h2(s[2*t+1][0] - M0, s[2*t+1][1] - M0);
            pa[t][3] = ex2h2(s[2*t+1][2] - M1, s[2*t+1][3] - M1);
        }

#pragma unroll
        for (int n = 0; n < 8; n++) {
            accO[n][0] *= c0; accO[n][1] *= c0;
            accO[n][2] *= c1; accO[n][3] *= c1;
        }
        accL[0] *= c0; accL[2] *= c1;
#pragma unroll
        for (int kt = 0; kt < 4; kt++)
            mma16816(accL, pa[kt], ONE2, ONE2);

#pragma unroll
        for (int kt = 0; kt < 4; kt++) {
            uint32_t b[4][4];
            int ch = (kt << 1) + lch;
#pragma unroll
            for (int p = 0; p < 4; p++) {
                int row = (p << 4) + lrow;
                ldsm4(b[p], bV + row * 128 + ((ch ^ (row & 7)) << 4));
            }
#pragma unroll
            for (int n = 0; n < 8; n++)
                mma16816(accO[n], pa[kt], b[n >> 1][n & 1], b[n >> 1][2 + (n & 1)]);
        }

        __syncthreads();
        if (j + 2 < nch) load_kv(j + 2, j & 1);
        asm volatile("cp.async.commit_group;");
    }

    float inv0 = 1.f / accL[0], inv1 = 1.f / accL[2];
    int b = z >> 4, h = z & 15;
    int row0 = q0 + (wid << 4) + (lane >> 2);
    half* a0 = act + ((size_t)(b * L + row0) * C) + h * 64;
    half* a1 = a0 + (size_t)8 * C;
#pragma unroll
    for (int n = 0; n < 8; n++) {
        int col = (n << 3) + ((lane & 3) << 1);
        *(half2*)(a0 + col) = __floats2half2_rn(accO[n][0] * inv0, accO[n][1] * inv0);
        *(half2*)(a1 + col) = __floats2half2_rn(accO[n][2] * inv1, accO[n][3] * inv1);
    }
}

static inline void fattn(const half* Q, const half* K, const half* Vt, half* act, int Lk) {
    cudaFuncSetAttribute(fattn_kernel, cudaFuncAttributeMaxDynamicSharedMemorySize, FA_SMEM);
    fattn_kernel<<<dim3(L/128, ZB), 256, FA_SMEM>>>(Q, K, Vt, act, Lk);
}

// ---- converts ----
__global__ void wconvert_kernel(const float* __restrict__ W, half* __restrict__ Th,
                                int K, int N, int rstride, int roff) {
    __shared__ float t[32][33];
    int k0 = blockIdx.y * 32, n0 = blockIdx.x * 32;
    int tx = threadIdx.x, ty = threadIdx.y;
#pragma unroll
    for (int i = 0; i < 32; i += 8) t[ty + i][tx] = W[(size_t)(k0 + ty + i) * N + n0 + tx];
    __syncthreads();
#pragma unroll
    for (int i = 0; i < 32; i += 8)
        Th[(size_t)((n0 + ty + i) * rstride + roff) * K + k0 + tx] = __float2half(t[tx][ty + i]);
}
static inline void wconvert(const float* W, half* Th, int K, int N, int rs = 1, int ro = 0) {
    wconvert_kernel<<<dim3(N/32, K/32), dim3(32, 8)>>>(W, Th, K, N, rs, ro);
}
__global__ void aconvert_kernel(const float* __restrict__ a, half* __restrict__ o, size_t n) {
    size_t i = (size_t)blockIdx.x * blockDim.x + threadIdx.x;
    if (i >= n) return;
    o[i] = __float2half(a[i]);
}

// ---- elementwise ----
__global__ void silu_kernel(const float* __restrict__ in, float* __restrict__ o, int n) {
    int i = blockIdx.x * blockDim.x + threadIdx.x;
    if (i >= n) return;
    o[i] = siluf(in[i]);
}
__global__ void rmsnorm_kernel(const float* __restrict__ x, const float* __restrict__ w,
                               const float* __restrict__ mods, const float* __restrict__ bias,
                               int sh_off, int sc_off, half* __restrict__ o) {
    int row = blockIdx.x, b = row / L;
    const float* xr = x + (size_t)row * C;
    float s = 0.f;
    for (int c = threadIdx.x; c < C; c += blockDim.x) { float v = xr[c]; s += v * v; }
    __shared__ float red[32];
#pragma unroll
    for (int o2 = 16; o2 > 0; o2 >>= 1) s += __shfl_down_sync(0xffffffff, s, o2);
    if ((threadIdx.x & 31) == 0) red[threadIdx.x >> 5] = s;
    __syncthreads();
    if (threadIdx.x < 32) {
        float v = (threadIdx.x < (blockDim.x >> 5)) ? red[threadIdx.x] : 0.f;
#pragma unroll
        for (int o2 = 16; o2 > 0; o2 >>= 1) v += __shfl_down_sync(0xffffffff, v, o2);
        if (threadIdx.x == 0) red[0] = v;
    }
    __syncthreads();
    float inv = rsqrtf(red[0] / (float)C + EPS);
    for (int c = threadIdx.x; c < C; c += blockDim.x) {
        float n = xr[c] * inv * w[c];
        if (mods) {
            float sc = mods[(size_t)b * 6 * C + sc_off + c] + bias[sc_off + c];
            float sh = mods[(size_t)b * 6 * C + sh_off + c] + bias[sh_off + c];
            n = n * (1.f + sc) + sh;
        }
        o[(size_t)row * C + c] = __float2half(n);
    }
}

// ---- launch ----
#define GSYM(p, s) cudaGetSymbolAddress((void**)&p, s)
extern "C" void kernel_launch(void* const* d_in, const int* in_sizes, int n_in,
                              void* d_out, int out_size) {
    const float* x     = (const float*)d_in[0];
    const float* t_mod = (const float*)d_in[1];
    const float* audio = (const float*)d_in[2];
    const float* fcos  = (const float*)d_in[3];
    const float* fsin  = (const float*)d_in[4];
    const float* n1w   = (const float*)d_in[5];
    const float* n2w   = (const float*)d_in[6];
    const float* n3w   = (const float*)d_in[7];
    const float* Wqkv  = (const float*)d_in[8];
    const float* Wsa   = (const float*)d_in[9];
    const float* Wq    = (const float*)d_in[10];
    const float* Wkv   = (const float*)d_in[11];
    const float* Wca   = (const float*)d_in[12];
    const float* Wg    = (const float*)d_in[13];
    const float* Wu    = (const float*)d_in[14];
    const float* Wd    = (const float*)d_in[15];
    const float* adaW  = (const float*)d_in[16];
    const float* adaB  = (const float*)d_in[17];
    float* out = (float*)d_out;

    float *silu_p, *mods_p, *x_p;
    half *hid, *act, *ctx, *sm, *qh_p, *kh_p, *vt_p;
    half *qkvw, *saw, *qw, *kvw, *caw, *guw, *dw, *adw;
    GSYM(silu_p, g_silu); GSYM(mods_p, g_mods); GSYM(x_p, g_x);
    GSYM(hid, g_h); GSYM(act, g_act); GSYM(ctx, g_ctx); GSYM(sm, g_sm);
    GSYM(qh_p, g_qh); GSYM(kh_p, g_kh); GSYM(vt_p, g_vt);
    GSYM(qkvw, w_qkv); GSYM(saw, w_sa); GSYM(qw, w_q); GSYM(kvw, w_kv);
    GSYM(caw, w_ca); GSYM(guw, w_gu); GSYM(dw, w_d); GSYM(adw, w_ada);

    wconvert(Wqkv, qkvw, C, 3*C);
    wconvert(Wsa,  saw,  C, C);
    wconvert(Wq,   qw,   C, C);
    wconvert(Wkv,  kvw,  TD, 2*C);
    wconvert(Wca,  caw,  C, C);
    wconvert(Wg,   guw,  C, FF, 2, 0);    // interleaved: row 2i = gate_i
    wconvert(Wu,   guw,  C, FF, 2, 1);    //              row 2i+1 = up_i
    wconvert(Wd,   dw,   FF, C);
    wconvert(adaW, adw,  C, 6*C);

    // adaLN (M padded to 128; bias folded at consumers)
    silu_kernel<<<(B*C + 255)/256, 256>>>(t_mod, silu_p, B*C);
    aconvert_kernel<<<(128*C + 255)/256, 256>>>(silu_p, sm, 128*C);
    launch_gmma<0>(sm, adw, mods_p, 128, 6*C, C,
                   nullptr, nullptr, nullptr, 0, nullptr, nullptr, nullptr, nullptr, 0);

    // ---- self-attention ----
    rmsnorm_kernel<<<BL, 256>>>(x, n1w, mods_p, adaB, 0, C, act);
    launch_gmma<3>(act, qkvw, qh_p, BL, 3*C, C,
                   nullptr, nullptr, nullptr, 0, fcos, fsin, kh_p, vt_p, L);
    fattn(qh_p, kh_p, vt_p, act, L);
    launch_gmma<0>(act, saw, x_p, BL, C, C,
                   x, mods_p, adaB, 2*C, nullptr, nullptr, nullptr, nullptr, 0);

    // ---- cross-attention ----
    rmsnorm_kernel<<<BL, 256>>>(x_p, n2w, nullptr, nullptr, 0, 0, act);
    launch_gmma<4>(act, qw, qh_p, BL, C, C,
                   nullptr, nullptr, nullptr, 0, nullptr, nullptr, nullptr, nullptr, L);
    aconvert_kernel<<<(BL2*TD + 255)/256, 256>>>(audio, ctx, (size_t)BL2*TD);
    launch_gmma<5>(ctx, kvw, kh_p, BL2, 2*C, TD,
                   nullptr, nullptr, nullptr, 0, nullptr, nullptr, nullptr, vt_p, L2);
    fattn(qh_p, kh_p, vt_p, act, L2);
    launch_gmma<0>(act, caw, x_p, BL, C, C,
                   x_p, nullptr, nullptr, 0, nullptr, nullptr, nullptr, nullptr, 0);

    // ---- MLP (gate+up fused + swiglu epilogue) ----
    rmsnorm_kernel<<<BL, 256>>>(x_p, n3w, mods_p, adaB, 3*C, 4*C, act);
    launch_gmma<2>(act, guw, hid, BL, 2*FF, C,
                   nullptr, nullptr, nullptr, 0, nullptr, nullptr, nullptr, nullptr, 0);
    launch_gmma<0>(hid, dw, out, BL, C, FF,
                   x_p, mods_p, adaB, 5*C, nullptr, nullptr, nullptr, nullptr, 0);
}

// round 13
// speedup vs baseline: 6.7880x; 1.0210x over previous
#include <cuda_runtime.h>
#include <cuda_fp16.h>
#include <stdint.h>

#define B 2
#define L 2048
#define C 1024
#define H 16
#define D 64
#define L2 512
#define TD 768
#define FF 4096
#define EPS 1e-6f
#define BL 4096
#define BL2 1024
#define ZB 32
#define SCL 0.180336880f   // 0.125 * log2(e)

// ---- scratch ----
__device__ float g_silu[128 * C];
__device__ float g_mods[128 * 6 * C];
__device__ float g_x[BL * C];
__device__ half g_h[(size_t)BL * FF];
__device__ half g_act[(size_t)BL * C];
__device__ half g_ctx[BL2 * TD];
__device__ half g_sm[128 * C];
__device__ half g_qh[(size_t)ZB * L * D];
__device__ half g_kh[(size_t)ZB * L * D];
__device__ half g_v[(size_t)ZB * L * D];     // V row-major [z][Lk][D]
// weights fp16, transposed [N][K]
__device__ half w_qkv[3*C*C];
__device__ half w_sa[C*C];
__device__ half w_q[C*C];
__device__ half w_kv[2*C*TD];
__device__ half w_ca[C*C];
__device__ half w_gu[(size_t)2*FF*C];        // gate/up row-interleaved
__device__ half w_d[(size_t)FF*C];
__device__ half w_ada[6*C*C];

// ---- helpers ----
__device__ __forceinline__ uint32_t smem_u32(const void* p) {
    uint32_t a;
    asm("{ .reg .u64 t; cvta.to.shared.u64 t, %1; cvt.u32.u64 %0, t; }" : "=r"(a) : "l"(p));
    return a;
}
__device__ __forceinline__ void cp16(uint32_t s, const void* g) {
    asm volatile("cp.async.cg.shared.global [%0], [%1], 16;" :: "r"(s), "l"(g));
}
__device__ __forceinline__ void ldsm4(uint32_t* r, uint32_t a) {
    asm volatile("ldmatrix.sync.aligned.m8n8.x4.shared.b16 {%0,%1,%2,%3}, [%4];"
        : "=r"(r[0]), "=r"(r[1]), "=r"(r[2]), "=r"(r[3]) : "r"(a));
}
__device__ __forceinline__ void ldsm4t(uint32_t* r, uint32_t a) {
    asm volatile("ldmatrix.sync.aligned.m8n8.x4.trans.shared.b16 {%0,%1,%2,%3}, [%4];"
        : "=r"(r[0]), "=r"(r[1]), "=r"(r[2]), "=r"(r[3]) : "r"(a));
}
__device__ __forceinline__ void mma16816(float* d, const uint32_t* a, uint32_t b0, uint32_t b1) {
    asm volatile("mma.sync.aligned.m16n8k16.row.col.f32.f16.f16.f32 "
        "{%0,%1,%2,%3}, {%4,%5,%6,%7}, {%8,%9}, {%0,%1,%2,%3};"
        : "+f"(d[0]), "+f"(d[1]), "+f"(d[2]), "+f"(d[3])
        : "r"(a[0]), "r"(a[1]), "r"(a[2]), "r"(a[3]), "r"(b0), "r"(b1));
}
__device__ __forceinline__ uint32_t ex2h2(float a, float b) {
    uint32_t h;
    asm("{ .reg .b32 t;\n\t"
        "cvt.rn.f16x2.f32 t, %2, %1;\n\t"
        "ex2.approx.f16x2 %0, t; }"
        : "=r"(h) : "f"(a), "f"(b));
    return h;
}
__device__ __forceinline__ float siluf(float v) { return v / (1.f + __expf(-v)); }

// ---- pipelined fp16 mma GEMM with fused epilogues ----
// EPI: 0 = float out (+ optional residual x + gate*acc)
//      2 = swiglu (interleaved gate/up) -> half [M][FF]
//      3 = SA qkv: rope q,k -> qh,kh; v row-major
//      4 = CA q
//      5 = CA kv
#define NSTAGE 4
#define STG 24576

template<int EPI>
__global__ void __launch_bounds__(256) gmma(
    const half* __restrict__ Ax, const half* __restrict__ B0,
    void* __restrict__ Cout, int M, int N, int K,
    const float* __restrict__ resx, const float* __restrict__ mods,
    const float* __restrict__ bias, int goff,
    const float* __restrict__ fc, const float* __restrict__ fs,
    half* __restrict__ khp, half* __restrict__ vtp, int Lk)
{
    extern __shared__ char smem[];
    uint32_t sb = smem_u32(smem);
    const int tid = threadIdx.x, lane = tid & 31, wid = tid >> 5;
    const int wm = (wid & 1) << 6;
    const int wn = (wid >> 1) << 6;
    const int tM = blockIdx.y << 7, tN = blockIdx.x << 8;

    float acc[4][8][4];
#pragma unroll
    for (int f = 0; f < 4; f++)
#pragma unroll
        for (int n = 0; n < 8; n++)
#pragma unroll
            for (int v = 0; v < 4; v++) acc[f][n][v] = 0.f;

    const int kIters = K >> 5;

    auto load_stage = [&](int s, int k0) {
        for (int id = tid; id < 1536; id += 256) {
            const half* g; uint32_t dst;
            if (id < 512) {
                int row = id >> 2, c = id & 3;
                g = Ax + (size_t)(tM + row) * K + k0 + (c << 3);
                dst = sb + s * STG + row * 64 + ((c ^ (row & 3)) << 4);
            } else {
                int a = id - 512;
                int row = a >> 2, c = a & 3;
                g = B0 + (size_t)(tN + row) * K + k0 + (c << 3);
                dst = sb + s * STG + 8192 + row * 64 + ((c ^ (row & 3)) << 4);
            }
            cp16(dst, g);
        }
    };

    for (int s = 0; s < NSTAGE - 1; s++) {
        load_stage(s, s << 5);
        asm volatile("cp.async.commit_group;");
    }

    const int lrow = lane & 15, lch = lane >> 4;

    for (int it = 0; it < kIters; it++) {
        asm volatile("cp.async.wait_group 2;");
        __syncthreads();
        if (it + NSTAGE - 1 < kIters)
            load_stage((it + NSTAGE - 1) % NSTAGE, (it + NSTAGE - 1) << 5);
        asm volatile("cp.async.commit_group;");

        uint32_t stg = sb + (uint32_t)(it % NSTAGE) * STG;
#pragma unroll
        for (int ks = 0; ks < 2; ks++) {
            int ch = (ks << 1) + lch;
            uint32_t a[4][4], b[4][4];
#pragma unroll
            for (int f = 0; f < 4; f++) {
                int row = wm + (f << 4) + lrow;
                ldsm4(a[f], stg + row * 64 + ((ch ^ (row & 3)) << 4));
            }
#pragma unroll
            for (int p = 0; p < 4; p++) {
                int row = wn + (p << 4) + lrow;
                ldsm4(b[p], stg + 8192u + row * 64 + ((ch ^ (row & 3)) << 4));
            }
#pragma unroll
            for (int f = 0; f < 4; f++)
#pragma unroll
                for (int n = 0; n < 8; n++)
                    mma16816(acc[f][n], a[f], b[n >> 1][n & 1], b[n >> 1][2 + (n & 1)]);
        }
    }

    const int bb = (EPI == 5) ? 0 : (tM >> 11);
#pragma unroll
    for (int f = 0; f < 4; f++) {
        int r0 = tM + wm + (f << 4) + (lane >> 2);
#pragma unroll
        for (int n = 0; n < 8; n++) {
            int col = tN + wn + (n << 3) + ((lane & 3) << 1);
            float v0 = acc[f][n][0], v1 = acc[f][n][1];
            float v2 = acc[f][n][2], v3 = acc[f][n][3];
            if (EPI == 0) {
                float* Cf = (float*)Cout;
                if (resx) {
                    float g0 = 1.f, g1 = 1.f;
                    if (mods) {
                        g0 = mods[(size_t)bb * 6 * C + goff + col]     + bias[goff + col];
                        g1 = mods[(size_t)bb * 6 * C + goff + col + 1] + bias[goff + col + 1];
                    }
                    v0 = resx[(size_t)r0 * N + col]         + g0 * v0;
                    v1 = resx[(size_t)r0 * N + col + 1]     + g1 * v1;
                    v2 = resx[(size_t)(r0+8) * N + col]     + g0 * v2;
                    v3 = resx[(size_t)(r0+8) * N + col + 1] + g1 * v3;
                }
                *(float2*)(Cf + (size_t)r0 * N + col)       = make_float2(v0, v1);
                *(float2*)(Cf + (size_t)(r0 + 8) * N + col) = make_float2(v2, v3);
            } else if (EPI == 2) {
                half* act = (half*)Cout;
                int oc = col >> 1;
                act[(size_t)r0 * FF + oc]       = __float2half(siluf(v0) * v1);
                act[(size_t)(r0 + 8) * FF + oc] = __float2half(siluf(v2) * v3);
            } else if (EPI == 3) {
                int l0 = r0 & 2047, l1 = (r0 + 8) & 2047;
                int sec = col >> 10, cc = col & 1023;
                int h = cc >> 6, d = cc & 63, p = d >> 1;
                int z = bb * H + h;
                if (sec < 2) {
                    float c0 = fc[l0*32+p], s0 = fs[l0*32+p];
                    float c1 = fc[l1*32+p], s1 = fs[l1*32+p];
                    float a0 = v0*c0 - v1*s0, b0 = v0*s0 + v1*c0;
                    float a1 = v2*c1 - v3*s1, b1 = v2*s1 + v3*c1;
                    half* dst;
                    if (sec == 0) { a0*=SCL; b0*=SCL; a1*=SCL; b1*=SCL; dst = (half*)Cout; }
                    else dst = khp;
                    *(half2*)(dst + ((size_t)z * L + l0) * 64 + d) = __floats2half2_rn(a0, b0);
                    *(half2*)(dst + ((size_t)z * L + l1) * 64 + d) = __floats2half2_rn(a1, b1);
                } else {
                    *(half2*)(vtp + ((size_t)z * L + l0) * 64 + d) = __floats2half2_rn(v0, v1);
                    *(half2*)(vtp + ((size_t)z * L + l1) * 64 + d) = __floats2half2_rn(v2, v3);
                }
            } else if (EPI == 4) {
                int l0 = r0 & 2047, l1 = (r0 + 8) & 2047;
                int h = col >> 6, d = col & 63;
                int z = bb * H + h;
                half* qh = (half*)Cout;
                *(half2*)(qh + ((size_t)z * L + l0) * 64 + d) = __floats2half2_rn(v0*SCL, v1*SCL);
                *(half2*)(qh + ((size_t)z * L + l1) * 64 + d) = __floats2half2_rn(v2*SCL, v3*SCL);
            } else if (EPI == 5) {
                int b2 = r0 >> 9;
                int k0 = r0 & 511, k1 = (r0 + 8) & 511;
                int sec = col >> 10, cc = col & 1023;
                int h = cc >> 6, d = cc & 63;
                int z = b2 * H + h;
                half* dst = (sec == 0) ? (half*)Cout : vtp;
                *(half2*)(dst + ((size_t)z * L2 + k0) * 64 + d) = __floats2half2_rn(v0, v1);
                *(half2*)(dst + ((size_t)z * L2 + k1) * 64 + d) = __floats2half2_rn(v2, v3);
            }
        }
    }
}

#define GSM (NSTAGE * STG)
template<int EPI>
static inline void launch_gmma(const half* A, const half* Bw, void* Co, int M, int N, int K,
                               const float* resx, const float* mods, const float* bias, int goff,
                               const float* fc, const float* fs, half* kh, half* vt, int Lk) {
    cudaFuncSetAttribute(gmma<EPI>, cudaFuncAttributeMaxDynamicSharedMemorySize, GSM);
    gmma<EPI><<<dim3(N/256, M/128), 256, GSM>>>(A, Bw, Co, M, N, K,
                                                resx, mods, bias, goff, fc, fs, kh, vt, Lk);
}

// ---- fused flash attention (V row-major, ldmatrix.trans for PV) ----
#define FA_SMEM 49152

__global__ void __launch_bounds__(256) fattn_kernel(
    const half* __restrict__ Qg, const half* __restrict__ Kg, const half* __restrict__ Vg,
    half* __restrict__ act, int Lk)
{
    extern __shared__ char smem[];
    uint32_t sb = smem_u32(smem);
    const uint32_t sQ = sb, sKV = sb + 16384;
    const int tid = threadIdx.x, lane = tid & 31, wid = tid >> 5;
    const int lrow = lane & 15, lch = lane >> 4;
    const int z = blockIdx.y;
    const int q0 = blockIdx.x << 7;
    const half* Qz = Qg + ((size_t)z * L + q0) * D;
    const half* Kz = Kg + (size_t)z * Lk * D;
    const half* Vz = Vg + (size_t)z * Lk * D;
    const uint32_t ONE2 = 0x3C003C00u;

    for (int id = tid; id < 1024; id += 256) {
        int row = id >> 3, c = id & 7;
        cp16(sQ + row * 128 + ((c ^ (row & 7)) << 4), Qz + row * D + c * 8);
    }
    auto load_kv = [&](int j, int buf) {
        uint32_t base = sKV + (uint32_t)buf * 16384;
        for (int id = tid; id < 1024; id += 256) {
            int row = (id >> 3) & 63, c = id & 7;
            const half* src = (id < 512) ? Kz : Vz;
            uint32_t off = (id < 512) ? 0u : 8192u;
            cp16(base + off + row * 128 + ((c ^ (row & 7)) << 4),
                 src + (size_t)(j * 64 + row) * D + c * 8);
        }
    };
    load_kv(0, 0);
    asm volatile("cp.async.commit_group;");
    const int nch = Lk >> 6;
    load_kv(1, 1);
    asm volatile("cp.async.commit_group;");

    float accO[8][4], accL[4];
#pragma unroll
    for (int n = 0; n < 8; n++)
#pragma unroll
        for (int v = 0; v < 4; v++) accO[n][v] = 0.f;
#pragma unroll
    for (int v = 0; v < 4; v++) accL[v] = 0.f;
    float m0 = -1e30f, m1 = -1e30f;
    uint32_t aq[4][4];

    for (int j = 0; j < nch; j++) {
        asm volatile("cp.async.wait_group 1;");
        __syncthreads();
        if (j == 0) {
#pragma unroll
            for (int ks = 0; ks < 4; ks++) {
                int row = (wid << 4) + lrow;
                int ch = (ks << 1) + lch;
                ldsm4(aq[ks], sQ + row * 128 + ((ch ^ (row & 7)) << 4));
            }
        }
        uint32_t bK = sKV + (uint32_t)(j & 1) * 16384;
        uint32_t bV = bK + 8192;

        float s[8][4];
#pragma unroll
        for (int n = 0; n < 8; n++)
#pragma unroll
            for (int v = 0; v < 4; v++) s[n][v] = 0.f;
#pragma unroll
        for (int ks = 0; ks < 4; ks++) {
            uint32_t b[4][4];
            int ch = (ks << 1) + lch;
#pragma unroll
            for (int p = 0; p < 4; p++) {
                int row = (p << 4) + lrow;
                ldsm4(b[p], bK + row * 128 + ((ch ^ (row & 7)) << 4));
            }
#pragma unroll
            for (int n = 0; n < 8; n++)
                mma16816(s[n], aq[ks], b[n >> 1][n & 1], b[n >> 1][2 + (n & 1)]);
        }

        float mt0 = -1e30f, mt1 = -1e30f;
#pragma unroll
        for (int n = 0; n < 8; n++) {
            mt0 = fmaxf(mt0, fmaxf(s[n][0], s[n][1]));
            mt1 = fmaxf(mt1, fmaxf(s[n][2], s[n][3]));
        }
        mt0 = fmaxf(mt0, __shfl_xor_sync(0xffffffff, mt0, 1));
        mt0 = fmaxf(mt0, __shfl_xor_sync(0xffffffff, mt0, 2));
        mt1 = fmaxf(mt1, __shfl_xor_sync(0xffffffff, mt1, 1));
        mt1 = fmaxf(mt1, __shfl_xor_sync(0xffffffff, mt1, 2));
        float M0 = fmaxf(m0, mt0), M1 = fmaxf(m1, mt1);
        float c0 = exp2f(m0 - M0), c1 = exp2f(m1 - M1);
        m0 = M0; m1 = M1;

        uint32_t pa[4][4];
#pragma unroll
        for (int t = 0; t < 4; t++) {
            pa[t][0] = ex2h2(s[2*t][0]   - M0, s[2*t][1]   - M0);
            pa[t][1] = ex2h2(s[2*t][2]   - M1, s[2*t][3]   - M1);
            pa[t][2] = ex2h2(s[2*t+1][0] - M0, s[2*t+1][1] - M0);
            pa[t][3] = ex2h2(s[2*t+1][2] - M1, s[2*t+1][3] - M1);
        }

#pragma unroll
        for (int n = 0; n < 8; n++) {
            accO[n][0] *= c0; accO[n][1] *= c0;
            accO[n][2] *= c1; accO[n][3] *= c1;
        }
        accL[0] *= c0; accL[2] *= c1;
#pragma unroll
        for (int kt = 0; kt < 4; kt++)
            mma16816(accL, pa[kt], ONE2, ONE2);

        // O += P @ V : V tile is [kv][d] row-major; transpose via ldmatrix.trans
#pragma unroll
        for (int kt = 0; kt < 4; kt++) {
            uint32_t bt[4][4];
#pragma unroll
            for (int p = 0; p < 4; p++) {
                int row = (kt << 4) + lrow;          // kv rows
                int ch = (p << 1) + lch;             // d 16B blocks
                ldsm4t(bt[p], bV + row * 128 + ((ch ^ (row & 7)) << 4));
            }
#pragma unroll
            for (int n = 0; n < 8; n++)
                mma16816(accO[n], pa[kt], bt[n >> 1][(n & 1) << 1], bt[n >> 1][((n & 1) << 1) + 1]);
        }

        __syncthreads();
        if (j + 2 < nch) load_kv(j + 2, j & 1);
        asm volatile("cp.async.commit_group;");
    }

    float inv0 = 1.f / accL[0], inv1 = 1.f / accL[2];
    int b = z >> 4, h = z & 15;
    int row0 = q0 + (wid << 4) + (lane >> 2);
    half* a0 = act + ((size_t)(b * L + row0) * C) + h * 64;
    half* a1 = a0 + (size_t)8 * C;
#pragma unroll
    for (int n = 0; n < 8; n++) {
        int col = (n << 3) + ((lane & 3) << 1);
        *(half2*)(a0 + col) = __floats2half2_rn(accO[n][0] * inv0, accO[n][1] * inv0);
        *(half2*)(a1 + col) = __floats2half2_rn(accO[n][2] * inv1, accO[n][3] * inv1);
    }
}

static inline void fattn(const half* Q, const half* K, const half* V, half* act, int Lk) {
    cudaFuncSetAttribute(fattn_kernel, cudaFuncAttributeMaxDynamicSharedMemorySize, FA_SMEM);
    fattn_kernel<<<dim3(L/128, ZB), 256, FA_SMEM>>>(Q, K, V, act, Lk);
}

// ---- converts ----
__global__ void wconvert_kernel(const float* __restrict__ W, half* __restrict__ Th,
                                int K, int N, int rstride, int roff) {
    __shared__ float t[32][33];
    int k0 = blockIdx.y * 32, n0 = blockIdx.x * 32;
    int tx = threadIdx.x, ty = threadIdx.y;
#pragma unroll
    for (int i = 0; i < 32; i += 8) t[ty + i][tx] = W[(size_t)(k0 + ty + i) * N + n0 + tx];
    __syncthreads();
#pragma unroll
    for (int i = 0; i < 32; i += 8)
        Th[(size_t)((n0 + ty + i) * rstride + roff) * K + k0 + tx] = __float2half(t[tx][ty + i]);
}
static inline void wconvert(const float* W, half* Th, int K, int N, int rs = 1, int ro = 0) {
    wconvert_kernel<<<dim3(N/32, K/32), dim3(32, 8)>>>(W, Th, K, N, rs, ro);
}
__global__ void aconvert_kernel(const float* __restrict__ a, half* __restrict__ o, size_t n) {
    size_t i = (size_t)blockIdx.x * blockDim.x + threadIdx.x;
    if (i >= n) return;
    o[i] = __float2half(a[i]);
}

// ---- elementwise ----
__global__ void silu_kernel(const float* __restrict__ in, float* __restrict__ o, int n) {
    int i = blockIdx.x * blockDim.x + threadIdx.x;
    if (i >= n) return;
    o[i] = siluf(in[i]);
}
// vectorized rmsnorm: 256 threads/row, float4 per thread (C=1024)
__global__ void rmsnorm_kernel(const float* __restrict__ x, const float* __restrict__ w,
                               const float* __restrict__ mods, const float* __restrict__ bias,
                               int sh_off, int sc_off, half* __restrict__ o) {
    int row = blockIdx.x, b = row / L;
    const float4* xr = (const float4*)(x + (size_t)row * C);
    float4 v = xr[threadIdx.x];
    float s = v.x*v.x + v.y*v.y + v.z*v.z + v.w*v.w;
    __shared__ float red[8];
#pragma unroll
    for (int o2 = 16; o2 > 0; o2 >>= 1) s += __shfl_xor_sync(0xffffffff, s, o2);
    if ((threadIdx.x & 31) == 0) red[threadIdx.x >> 5] = s;
    __syncthreads();
    s = red[threadIdx.x & 7];
#pragma unroll
    for (int o2 = 4; o2 > 0; o2 >>= 1) s += __shfl_xor_sync(0xffffffff, s, o2);
    float inv = rsqrtf(s / (float)C + EPS);
    int c = threadIdx.x << 2;
    float4 wv = *(const float4*)(w + c);
    float r[4] = {v.x * inv * wv.x, v.y * inv * wv.y, v.z * inv * wv.z, v.w * inv * wv.w};
    if (mods) {
        float4 sc = *(const float4*)(mods + (size_t)b * 6 * C + sc_off + c);
        float4 scb = *(const float4*)(bias + sc_off + c);
        float4 sh = *(const float4*)(mods + (size_t)b * 6 * C + sh_off + c);
        float4 shb = *(const float4*)(bias + sh_off + c);
        r[0] = r[0] * (1.f + sc.x + scb.x) + sh.x + shb.x;
        r[1] = r[1] * (1.f + sc.y + scb.y) + sh.y + shb.y;
        r[2] = r[2] * (1.f + sc.z + scb.z) + sh.z + shb.z;
        r[3] = r[3] * (1.f + sc.w + scb.w) + sh.w + shb.w;
    }
    half2 h0 = __floats2half2_rn(r[0], r[1]);
    half2 h1 = __floats2half2_rn(r[2], r[3]);
    uint2 pk = { *(uint32_t*)&h0, *(uint32_t*)&h1 };
    *(uint2*)(o + (size_t)row * C + c) = pk;
}

// ---- launch ----
#define GSYM(p, s) cudaGetSymbolAddress((void**)&p, s)
extern "C" void kernel_launch(void* const* d_in, const int* in_sizes, int n_in,
                              void* d_out, int out_size) {
    const float* x     = (const float*)d_in[0];
    const float* t_mod = (const float*)d_in[1];
    const float* audio = (const float*)d_in[2];
    const float* fcos  = (const float*)d_in[3];
    const float* fsin  = (const float*)d_in[4];
    const float* n1w   = (const float*)d_in[5];
    const float* n2w   = (const float*)d_in[6];
    const float* n3w   = (const float*)d_in[7];
    const float* Wqkv  = (const float*)d_in[8];
    const float* Wsa   = (const float*)d_in[9];
    const float* Wq    = (const float*)d_in[10];
    const float* Wkv   = (const float*)d_in[11];
    const float* Wca   = (const float*)d_in[12];
    const float* Wg    = (const float*)d_in[13];
    const float* Wu    = (const float*)d_in[14];
    const float* Wd    = (const float*)d_in[15];
    const float* adaW  = (const float*)d_in[16];
    const float* adaB  = (const float*)d_in[17];
    float* out = (float*)d_out;

    float *silu_p, *mods_p, *x_p;
    half *hid, *act, *ctx, *sm, *qh_p, *kh_p, *v_p;
    half *qkvw, *saw, *qw, *kvw, *caw, *guw, *dw, *adw;
    GSYM(silu_p, g_silu); GSYM(mods_p, g_mods); GSYM(x_p, g_x);
    GSYM(hid, g_h); GSYM(act, g_act); GSYM(ctx, g_ctx); GSYM(sm, g_sm);
    GSYM(qh_p, g_qh); GSYM(kh_p, g_kh); GSYM(v_p, g_v);
    GSYM(qkvw, w_qkv); GSYM(saw, w_sa); GSYM(qw, w_q); GSYM(kvw, w_kv);
    GSYM(caw, w_ca); GSYM(guw, w_gu); GSYM(dw, w_d); GSYM(adw, w_ada);

    wconvert(Wqkv, qkvw, C, 3*C);
    wconvert(Wsa,  saw,  C, C);
    wconvert(Wq,   qw,   C, C);
    wconvert(Wkv,  kvw,  TD, 2*C);
    wconvert(Wca,  caw,  C, C);
    wconvert(Wg,   guw,  C, FF, 2, 0);
    wconvert(Wu,   guw,  C, FF, 2, 1);
    wconvert(Wd,   dw,   FF, C);
    wconvert(adaW, adw,  C, 6*C);

    // adaLN (M padded to 128; bias folded at consumers)
    silu_kernel<<<(B*C + 255)/256, 256>>>(t_mod, silu_p, B*C);
    aconvert_kernel<<<(128*C + 255)/256, 256>>>(silu_p, sm, 128*C);
    launch_gmma<0>(sm, adw, mods_p, 128, 6*C, C,
                   nullptr, nullptr, nullptr, 0, nullptr, nullptr, nullptr, nullptr, 0);

    // ---- self-attention ----
    rmsnorm_kernel<<<BL, 256>>>(x, n1w, mods_p, adaB, 0, C, act);
    launch_gmma<3>(act, qkvw, qh_p, BL, 3*C, C,
                   nullptr, nullptr, nullptr, 0, fcos, fsin, kh_p, v_p, L);
    fattn(qh_p, kh_p, v_p, act, L);
    launch_gmma<0>(act, saw, x_p, BL, C, C,
                   x, mods_p, adaB, 2*C, nullptr, nullptr, nullptr, nullptr, 0);

    // ---- cross-attention ----
    rmsnorm_kernel<<<BL, 256>>>(x_p, n2w, nullptr, nullptr, 0, 0, act);
    launch_gmma<4>(act, qw, qh_p, BL, C, C,
                   nullptr, nullptr, nullptr, 0, nullptr, nullptr, nullptr, nullptr, L);
    aconvert_kernel<<<(BL2*TD + 255)/256, 256>>>(audio, ctx, (size_t)BL2*TD);
    launch_gmma<5>(ctx, kvw, kh_p, BL2, 2*C, TD,
                   nullptr, nullptr, nullptr, 0, nullptr, nullptr, nullptr, v_p, L2);
    fattn(qh_p, kh_p, v_p, act, L2);
    launch_gmma<0>(act, caw, x_p, BL, C, C,
                   x_p, nullptr, nullptr, 0, nullptr, nullptr, nullptr, nullptr, 0);

    // ---- MLP ----
    rmsnorm_kernel<<<BL, 256>>>(x_p, n3w, mods_p, adaB, 3*C, 4*C, act);
    launch_gmma<2>(act, guw, hid, BL, 2*FF, C,
                   nullptr, nullptr, nullptr, 0, nullptr, nullptr, nullptr, nullptr, 0);
    launch_gmma<0>(hid, dw, out, BL, C, FF,
                   x_p, mods_p, adaB, 5*C, nullptr, nullptr, nullptr, nullptr, 0);
}

// round 14
// speedup vs baseline: 8.7959x; 1.2958x over previous
#include <cuda_runtime.h>
#include <cuda_fp16.h>
#include <stdint.h>

#define B 2
#define L 2048
#define C 1024
#define H 16
#define D 64
#define L2 512
#define TD 768
#define FF 4096
#define EPS 1e-6f
#define BL 4096
#define BL2 1024
#define ZB 32
#define SCL 0.180336880f   // 0.125 * log2(e)

// ---- scratch ----
__device__ float g_mods[128 * 6 * C];
__device__ float g_x[BL * C];
__device__ half g_h[(size_t)BL * FF];
__device__ half g_act[(size_t)BL * C];
__device__ half g_ctx[BL2 * TD];
__device__ half g_sm[128 * C];
__device__ half g_qh[(size_t)ZB * L * D];
__device__ half g_kh[(size_t)ZB * L * D];
__device__ half g_v[(size_t)ZB * L * D];
// weights fp16, transposed [N][K]
__device__ half w_qkv[3*C*C];
__device__ half w_sa[C*C];
__device__ half w_q[C*C];
__device__ half w_kv[2*C*TD];
__device__ half w_ca[C*C];
__device__ half w_gu[(size_t)2*FF*C];
__device__ half w_d[(size_t)FF*C];
__device__ half w_ada[6*C*C];

// ---- helpers ----
__device__ __forceinline__ uint32_t smem_u32(const void* p) {
    uint32_t a;
    asm("{ .reg .u64 t; cvta.to.shared.u64 t, %1; cvt.u32.u64 %0, t; }" : "=r"(a) : "l"(p));
    return a;
}
__device__ __forceinline__ void cp16(uint32_t s, const void* g) {
    asm volatile("cp.async.cg.shared.global [%0], [%1], 16;" :: "r"(s), "l"(g));
}
__device__ __forceinline__ void ldsm4(uint32_t* r, uint32_t a) {
    asm volatile("ldmatrix.sync.aligned.m8n8.x4.shared.b16 {%0,%1,%2,%3}, [%4];"
        : "=r"(r[0]), "=r"(r[1]), "=r"(r[2]), "=r"(r[3]) : "r"(a));
}
__device__ __forceinline__ void ldsm4t(uint32_t* r, uint32_t a) {
    asm volatile("ldmatrix.sync.aligned.m8n8.x4.trans.shared.b16 {%0,%1,%2,%3}, [%4];"
        : "=r"(r[0]), "=r"(r[1]), "=r"(r[2]), "=r"(r[3]) : "r"(a));
}
__device__ __forceinline__ void mma16816(float* d, const uint32_t* a, uint32_t b0, uint32_t b1) {
    asm volatile("mma.sync.aligned.m16n8k16.row.col.f32.f16.f16.f32 "
        "{%0,%1,%2,%3}, {%4,%5,%6,%7}, {%8,%9}, {%0,%1,%2,%3};"
        : "+f"(d[0]), "+f"(d[1]), "+f"(d[2]), "+f"(d[3])
        : "r"(a[0]), "r"(a[1]), "r"(a[2]), "r"(a[3]), "r"(b0), "r"(b1));
}
__device__ __forceinline__ uint32_t ex2h2(float a, float b) {
    uint32_t h;
    asm("{ .reg .b32 t;\n\t"
        "cvt.rn.f16x2.f32 t, %2, %1;\n\t"
        "ex2.approx.f16x2 %0, t; }"
        : "=r"(h) : "f"(a), "f"(b));
    return h;
}
__device__ __forceinline__ float siluf(float v) { return v / (1.f + __expf(-v)); }

// ---- pipelined fp16 mma GEMM, K-chunk 64, fused epilogues ----
// EPI: 0 = float out (+ optional residual x + gate*acc)
//      2 = swiglu (interleaved gate/up) -> half [M][FF]
//      3 = SA qkv: rope q,k -> qh,kh; v row-major
//      4 = CA q   5 = CA kv
#define NSTAGE 3
#define STG 49152     // A 16K | B 32K

template<int EPI>
__global__ void __launch_bounds__(256) gmma(
    const half* __restrict__ Ax, const half* __restrict__ B0,
    void* __restrict__ Cout, int M, int N, int K,
    const float* __restrict__ resx, const float* __restrict__ mods,
    const float* __restrict__ bias, int goff,
    const float* __restrict__ fc, const float* __restrict__ fs,
    half* __restrict__ khp, half* __restrict__ vtp, int Lk)
{
    extern __shared__ char smem[];
    uint32_t sb = smem_u32(smem);
    const int tid = threadIdx.x, lane = tid & 31, wid = tid >> 5;
    const int wm = (wid & 1) << 6;
    const int wn = (wid >> 1) << 6;
    const int tM = blockIdx.y << 7, tN = blockIdx.x << 8;

    float acc[4][8][4];
#pragma unroll
    for (int f = 0; f < 4; f++)
#pragma unroll
        for (int n = 0; n < 8; n++)
#pragma unroll
            for (int v = 0; v < 4; v++) acc[f][n][v] = 0.f;

    const int kIters = K >> 6;

    auto load_stage = [&](int s, int k0) {
#pragma unroll
        for (int i = 0; i < 12; i++) {
            int id = tid + (i << 8);
            const half* g; uint32_t dst;
            if (id < 1024) {
                int row = id >> 3, c = id & 7;
                g = Ax + (size_t)(tM + row) * K + k0 + (c << 3);
                dst = sb + s * STG + row * 128 + ((c ^ (row & 7)) << 4);
            } else {
                int a = id - 1024;
                int row = a >> 3, c = a & 7;
                g = B0 + (size_t)(tN + row) * K + k0 + (c << 3);
                dst = sb + s * STG + 16384 + row * 128 + ((c ^ (row & 7)) << 4);
            }
            cp16(dst, g);
        }
    };

    for (int s = 0; s < NSTAGE - 1; s++) {
        load_stage(s, s << 6);
        asm volatile("cp.async.commit_group;");
    }

    const int lrow = lane & 15, lch = lane >> 4;

    for (int it = 0; it < kIters; it++) {
        asm volatile("cp.async.wait_group 1;");
        __syncthreads();
        if (it + NSTAGE - 1 < kIters)
            load_stage((it + NSTAGE - 1) % NSTAGE, (it + NSTAGE - 1) << 6);
        asm volatile("cp.async.commit_group;");

        uint32_t stg = sb + (uint32_t)(it % NSTAGE) * STG;
#pragma unroll
        for (int ks = 0; ks < 4; ks++) {
            int ch = (ks << 1) + lch;
            uint32_t a[4][4], b[4][4];
#pragma unroll
            for (int f = 0; f < 4; f++) {
                int row = wm + (f << 4) + lrow;
                ldsm4(a[f], stg + row * 128 + ((ch ^ (row & 7)) << 4));
            }
#pragma unroll
            for (int p = 0; p < 4; p++) {
                int row = wn + (p << 4) + lrow;
                ldsm4(b[p], stg + 16384u + row * 128 + ((ch ^ (row & 7)) << 4));
            }
#pragma unroll
            for (int f = 0; f < 4; f++)
#pragma unroll
                for (int n = 0; n < 8; n++)
                    mma16816(acc[f][n], a[f], b[n >> 1][n & 1], b[n >> 1][2 + (n & 1)]);
        }
    }

    const int bb = (EPI == 5) ? 0 : (tM >> 11);
#pragma unroll
    for (int f = 0; f < 4; f++) {
        int r0 = tM + wm + (f << 4) + (lane >> 2);
#pragma unroll
        for (int n = 0; n < 8; n++) {
            int col = tN + wn + (n << 3) + ((lane & 3) << 1);
            float v0 = acc[f][n][0], v1 = acc[f][n][1];
            float v2 = acc[f][n][2], v3 = acc[f][n][3];
            if (EPI == 0) {
                float* Cf = (float*)Cout;
                if (resx) {
                    float g0 = 1.f, g1 = 1.f;
                    if (mods) {
                        g0 = mods[(size_t)bb * 6 * C + goff + col]     + bias[goff + col];
                        g1 = mods[(size_t)bb * 6 * C + goff + col + 1] + bias[goff + col + 1];
                    }
                    v0 = resx[(size_t)r0 * N + col]         + g0 * v0;
                    v1 = resx[(size_t)r0 * N + col + 1]     + g1 * v1;
                    v2 = resx[(size_t)(r0+8) * N + col]     + g0 * v2;
                    v3 = resx[(size_t)(r0+8) * N + col + 1] + g1 * v3;
                }
                *(float2*)(Cf + (size_t)r0 * N + col)       = make_float2(v0, v1);
                *(float2*)(Cf + (size_t)(r0 + 8) * N + col) = make_float2(v2, v3);
            } else if (EPI == 2) {
                half* act = (half*)Cout;
                int oc = col >> 1;
                act[(size_t)r0 * FF + oc]       = __float2half(siluf(v0) * v1);
                act[(size_t)(r0 + 8) * FF + oc] = __float2half(siluf(v2) * v3);
            } else if (EPI == 3) {
                int l0 = r0 & 2047, l1 = (r0 + 8) & 2047;
                int sec = col >> 10, cc = col & 1023;
                int h = cc >> 6, d = cc & 63, p = d >> 1;
                int z = bb * H + h;
                if (sec < 2) {
                    float c0 = fc[l0*32+p], s0 = fs[l0*32+p];
                    float c1 = fc[l1*32+p], s1 = fs[l1*32+p];
                    float a0 = v0*c0 - v1*s0, b0 = v0*s0 + v1*c0;
                    float a1 = v2*c1 - v3*s1, b1 = v2*s1 + v3*c1;
                    half* dst;
                    if (sec == 0) { a0*=SCL; b0*=SCL; a1*=SCL; b1*=SCL; dst = (half*)Cout; }
                    else dst = khp;
                    *(half2*)(dst + ((size_t)z * L + l0) * 64 + d) = __floats2half2_rn(a0, b0);
                    *(half2*)(dst + ((size_t)z * L + l1) * 64 + d) = __floats2half2_rn(a1, b1);
                } else {
                    *(half2*)(vtp + ((size_t)z * L + l0) * 64 + d) = __floats2half2_rn(v0, v1);
                    *(half2*)(vtp + ((size_t)z * L + l1) * 64 + d) = __floats2half2_rn(v2, v3);
                }
            } else if (EPI == 4) {
                int l0 = r0 & 2047, l1 = (r0 + 8) & 2047;
                int h = col >> 6, d = col & 63;
                int z = bb * H + h;
                half* qh = (half*)Cout;
                *(half2*)(qh + ((size_t)z * L + l0) * 64 + d) = __floats2half2_rn(v0*SCL, v1*SCL);
                *(half2*)(qh + ((size_t)z * L + l1) * 64 + d) = __floats2half2_rn(v2*SCL, v3*SCL);
            } else if (EPI == 5) {
                int b2 = r0 >> 9;
                int k0 = r0 & 511, k1 = (r0 + 8) & 511;
                int sec = col >> 10, cc = col & 1023;
                int h = cc >> 6, d = cc & 63;
                int z = b2 * H + h;
                half* dst = (sec == 0) ? (half*)Cout : vtp;
                *(half2*)(dst + ((size_t)z * L2 + k0) * 64 + d) = __floats2half2_rn(v0, v1);
                *(half2*)(dst + ((size_t)z * L2 + k1) * 64 + d) = __floats2half2_rn(v2, v3);
            }
        }
    }
}

#define GSM (NSTAGE * STG)
template<int EPI>
static inline void launch_gmma(const half* A, const half* Bw, void* Co, int M, int N, int K,
                               const float* resx, const float* mods, const float* bias, int goff,
                               const float* fc, const float* fs, half* kh, half* vt, int Lk) {
    cudaFuncSetAttribute(gmma<EPI>, cudaFuncAttributeMaxDynamicSharedMemorySize, GSM);
    gmma<EPI><<<dim3(N/256, M/128), 256, GSM>>>(A, Bw, Co, M, N, K,
                                                resx, mods, bias, goff, fc, fs, kh, vt, Lk);
}

// ---- fused flash attention (V row-major, ldmatrix.trans for PV) ----
#define FA_SMEM 49152

__global__ void __launch_bounds__(256) fattn_kernel(
    const half* __restrict__ Qg, const half* __restrict__ Kg, const half* __restrict__ Vg,
    half* __restrict__ act, int Lk)
{
    extern __shared__ char smem[];
    uint32_t sb = smem_u32(smem);
    const uint32_t sQ = sb, sKV = sb + 16384;
    const int tid = threadIdx.x, lane = tid & 31, wid = tid >> 5;
    const int lrow = lane & 15, lch = lane >> 4;
    const int z = blockIdx.y;
    const int q0 = blockIdx.x << 7;
    const half* Qz = Qg + ((size_t)z * L + q0) * D;
    const half* Kz = Kg + (size_t)z * Lk * D;
    const half* Vz = Vg + (size_t)z * Lk * D;
    const uint32_t ONE2 = 0x3C003C00u;

    for (int id = tid; id < 1024; id += 256) {
        int row = id >> 3, c = id & 7;
        cp16(sQ + row * 128 + ((c ^ (row & 7)) << 4), Qz + row * D + c * 8);
    }
    auto load_kv = [&](int j, int buf) {
        uint32_t base = sKV + (uint32_t)buf * 16384;
        for (int id = tid; id < 1024; id += 256) {
            int row = (id >> 3) & 63, c = id & 7;
            const half* src = (id < 512) ? Kz : Vz;
            uint32_t off = (id < 512) ? 0u : 8192u;
            cp16(base + off + row * 128 + ((c ^ (row & 7)) << 4),
                 src + (size_t)(j * 64 + row) * D + c * 8);
        }
    };
    load_kv(0, 0);
    asm volatile("cp.async.commit_group;");
    const int nch = Lk >> 6;
    load_kv(1, 1);
    asm volatile("cp.async.commit_group;");

    float accO[8][4], accL[4];
#pragma unroll
    for (int n = 0; n < 8; n++)
#pragma unroll
        for (int v = 0; v < 4; v++) accO[n][v] = 0.f;
#pragma unroll
    for (int v = 0; v < 4; v++) accL[v] = 0.f;
    float m0 = -1e30f, m1 = -1e30f;
    uint32_t aq[4][4];

    for (int j = 0; j < nch; j++) {
        asm volatile("cp.async.wait_group 1;");
        __syncthreads();
        if (j == 0) {
#pragma unroll
            for (int ks = 0; ks < 4; ks++) {
                int row = (wid << 4) + lrow;
                int ch = (ks << 1) + lch;
                ldsm4(aq[ks], sQ + row * 128 + ((ch ^ (row & 7)) << 4));
            }
        }
        uint32_t bK = sKV + (uint32_t)(j & 1) * 16384;
        uint32_t bV = bK + 8192;

        float s[8][4];
#pragma unroll
        for (int n = 0; n < 8; n++)
#pragma unroll
            for (int v = 0; v < 4; v++) s[n][v] = 0.f;
#pragma unroll
        for (int ks = 0; ks < 4; ks++) {
            uint32_t b[4][4];
            int ch = (ks << 1) + lch;
#pragma unroll
            for (int p = 0; p < 4; p++) {
                int row = (p << 4) + lrow;
                ldsm4(b[p], bK + row * 128 + ((ch ^ (row & 7)) << 4));
            }
#pragma unroll
            for (int n = 0; n < 8; n++)
                mma16816(s[n], aq[ks], b[n >> 1][n & 1], b[n >> 1][2 + (n & 1)]);
        }

        float mt0 = -1e30f, mt1 = -1e30f;
#pragma unroll
        for (int n = 0; n < 8; n++) {
            mt0 = fmaxf(mt0, fmaxf(s[n][0], s[n][1]));
            mt1 = fmaxf(mt1, fmaxf(s[n][2], s[n][3]));
        }
        mt0 = fmaxf(mt0, __shfl_xor_sync(0xffffffff, mt0, 1));
        mt0 = fmaxf(mt0, __shfl_xor_sync(0xffffffff, mt0, 2));
        mt1 = fmaxf(mt1, __shfl_xor_sync(0xffffffff, mt1, 1));
        mt1 = fmaxf(mt1, __shfl_xor_sync(0xffffffff, mt1, 2));
        float M0 = fmaxf(m0, mt0), M1 = fmaxf(m1, mt1);
        float c0 = exp2f(m0 - M0), c1 = exp2f(m1 - M1);
        m0 = M0; m1 = M1;

        uint32_t pa[4][4];
#pragma unroll
        for (int t = 0; t < 4; t++) {
            pa[t][0] = ex2h2(s[2*t][0]   - M0, s[2*t][1]   - M0);
            pa[t][1] = ex2h2(s[2*t][2]   - M1, s[2*t][3]   - M1);
            pa[t][2] = ex2h2(s[2*t+1][0] - M0, s[2*t+1][1] - M0);
            pa[t][3] = ex2h2(s[2*t+1][2] - M1, s[2*t+1][3] - M1);
        }

#pragma unroll
        for (int n = 0; n < 8; n++) {
            accO[n][0] *= c0; accO[n][1] *= c0;
            accO[n][2] *= c1; accO[n][3] *= c1;
        }
        accL[0] *= c0; accL[2] *= c1;
#pragma unroll
        for (int kt = 0; kt < 4; kt++)
            mma16816(accL, pa[kt], ONE2, ONE2);

#pragma unroll
        for (int kt = 0; kt < 4; kt++) {
            uint32_t bt[4][4];
#pragma unroll
            for (int p = 0; p < 4; p++) {
                int row = (kt << 4) + lrow;
                int ch = (p << 1) + lch;
                ldsm4t(bt[p], bV + row * 128 + ((ch ^ (row & 7)) << 4));
            }
#pragma unroll
            for (int n = 0; n < 8; n++)
                mma16816(accO[n], pa[kt], bt[n >> 1][(n & 1) << 1], bt[n >> 1][((n & 1) << 1) + 1]);
        }

        __syncthreads();
        if (j + 2 < nch) load_kv(j + 2, j & 1);
        asm volatile("cp.async.commit_group;");
    }

    float inv0 = 1.f / accL[0], inv1 = 1.f / accL[2];
    int b = z >> 4, h = z & 15;
    int row0 = q0 + (wid << 4) + (lane >> 2);
    half* a0 = act + ((size_t)(b * L + row0) * C) + h * 64;
    half* a1 = a0 + (size_t)8 * C;
#pragma unroll
    for (int n = 0; n < 8; n++) {
        int col = (n << 3) + ((lane & 3) << 1);
        *(half2*)(a0 + col) = __floats2half2_rn(accO[n][0] * inv0, accO[n][1] * inv0);
        *(half2*)(a1 + col) = __floats2half2_rn(accO[n][2] * inv1, accO[n][3] * inv1);
    }
}

static inline void fattn(const half* Q, const half* K, const half* V, half* act, int Lk) {
    cudaFuncSetAttribute(fattn_kernel, cudaFuncAttributeMaxDynamicSharedMemorySize, FA_SMEM);
    fattn_kernel<<<dim3(L/128, ZB), 256, FA_SMEM>>>(Q, K, V, act, Lk);
}

// ---- merged weight convert: all 9 weights in ONE launch ----
struct WJob { const float* W; half* T; int K, N, rs, ro, tile0; };
struct WAll { WJob j[9]; int ntiles; };

__global__ void wconvert_all_kernel(WAll wa) {
    __shared__ float t[32][33];
    int g = blockIdx.x;
    int ji = 0;
#pragma unroll
    for (int k = 1; k < 9; k++) if (g >= wa.j[k].tile0) ji = k;
    WJob w = wa.j[ji];
    int lt = g - w.tile0;
    int nx = w.N >> 5;
    int n0 = (lt % nx) << 5, k0 = (lt / nx) << 5;
    int tx = threadIdx.x, ty = threadIdx.y;
#pragma unroll
    for (int i = 0; i < 32; i += 8) t[ty + i][tx] = w.W[(size_t)(k0 + ty + i) * w.N + n0 + tx];
    __syncthreads();
#pragma unroll
    for (int i = 0; i < 32; i += 8)
        w.T[(size_t)((n0 + ty + i) * w.rs + w.ro) * w.K + k0 + tx] = __float2half(t[tx][ty + i]);
}

// silu(t_mod) -> half, zero-pad rows [B,128)
__global__ void silu2h_kernel(const float* __restrict__ in, half* __restrict__ o) {
    int i = blockIdx.x * blockDim.x + threadIdx.x;
    if (i >= 128 * C) return;
    o[i] = (i < B * C) ? __float2half(siluf(in[i])) : __float2half(0.f);
}
__global__ void aconvert_kernel(const float* __restrict__ a, half* __restrict__ o, size_t n) {
    size_t i = (size_t)blockIdx.x * blockDim.x + threadIdx.x;
    if (i >= n) return;
    o[i] = __float2half(a[i]);
}

// vectorized rmsnorm
__global__ void rmsnorm_kernel(const float* __restrict__ x, const float* __restrict__ w,
                               const float* __restrict__ mods, const float* __restrict__ bias,
                               int sh_off, int sc_off, half* __restrict__ o) {
    int row = blockIdx.x, b = row / L;
    const float4* xr = (const float4*)(x + (size_t)row * C);
    float4 v = xr[threadIdx.x];
    float s = v.x*v.x + v.y*v.y + v.z*v.z + v.w*v.w;
    __shared__ float red[8];
#pragma unroll
    for (int o2 = 16; o2 > 0; o2 >>= 1) s += __shfl_xor_sync(0xffffffff, s, o2);
    if ((threadIdx.x & 31) == 0) red[threadIdx.x >> 5] = s;
    __syncthreads();
    s = red[threadIdx.x & 7];
#pragma unroll
    for (int o2 = 4; o2 > 0; o2 >>= 1) s += __shfl_xor_sync(0xffffffff, s, o2);
    float inv = rsqrtf(s / (float)C + EPS);
    int c = threadIdx.x << 2;
    float4 wv = *(const float4*)(w + c);
    float r[4] = {v.x * inv * wv.x, v.y * inv * wv.y, v.z * inv * wv.z, v.w * inv * wv.w};
    if (mods) {
        float4 sc = *(const float4*)(mods + (size_t)b * 6 * C + sc_off + c);
        float4 scb = *(const float4*)(bias + sc_off + c);
        float4 sh = *(const float4*)(mods + (size_t)b * 6 * C + sh_off + c);
        float4 shb = *(const float4*)(bias + sh_off + c);
        r[0] = r[0] * (1.f + sc.x + scb.x) + sh.x + shb.x;
        r[1] = r[1] * (1.f + sc.y + scb.y) + sh.y + shb.y;
        r[2] = r[2] * (1.f + sc.z + scb.z) + sh.z + shb.z;
        r[3] = r[3] * (1.f + sc.w + scb.w) + sh.w + shb.w;
    }
    half2 h0 = __floats2half2_rn(r[0], r[1]);
    half2 h1 = __floats2half2_rn(r[2], r[3]);
    uint2 pk = { *(uint32_t*)&h0, *(uint32_t*)&h1 };
    *(uint2*)(o + (size_t)row * C + c) = pk;
}

// ---- launch ----
#define GSYM(p, s) cudaGetSymbolAddress((void**)&p, s)
extern "C" void kernel_launch(void* const* d_in, const int* in_sizes, int n_in,
                              void* d_out, int out_size) {
    const float* x     = (const float*)d_in[0];
    const float* t_mod = (const float*)d_in[1];
    const float* audio = (const float*)d_in[2];
    const float* fcos  = (const float*)d_in[3];
    const float* fsin  = (const float*)d_in[4];
    const float* n1w   = (const float*)d_in[5];
    const float* n2w   = (const float*)d_in[6];
    const float* n3w   = (const float*)d_in[7];
    const float* Wqkv  = (const float*)d_in[8];
    const float* Wsa   = (const float*)d_in[9];
    const float* Wq    = (const float*)d_in[10];
    const float* Wkv   = (const float*)d_in[11];
    const float* Wca   = (const float*)d_in[12];
    const float* Wg    = (const float*)d_in[13];
    const float* Wu    = (const float*)d_in[14];
    const float* Wd    = (const float*)d_in[15];
    const float* adaW  = (const float*)d_in[16];
    const float* adaB  = (const float*)d_in[17];
    float* out = (float*)d_out;

    float *mods_p, *x_p;
    half *hid, *act, *ctx, *sm, *qh_p, *kh_p, *v_p;
    half *qkvw, *saw, *qw, *kvw, *caw, *guw, *dw, *adw;
    GSYM(mods_p, g_mods); GSYM(x_p, g_x);
    GSYM(hid, g_h); GSYM(act, g_act); GSYM(ctx, g_ctx); GSYM(sm, g_sm);
    GSYM(qh_p, g_qh); GSYM(kh_p, g_kh); GSYM(v_p, g_v);
    GSYM(qkvw, w_qkv); GSYM(saw, w_sa); GSYM(qw, w_q); GSYM(kvw, w_kv);
    GSYM(caw, w_ca); GSYM(guw, w_gu); GSYM(dw, w_d); GSYM(adw, w_ada);

    // merged weight convert: one launch
    WAll wa;
    const float* Ws[9] = {Wqkv, Wsa, Wq, Wkv, Wca, Wg, Wu, Wd, adaW};
    half* Ts[9] = {qkvw, saw, qw, kvw, caw, guw, guw, dw, adw};
    int Ks[9] = {C, C, C, TD, C, C, C, FF, C};
    int Ns[9] = {3*C, C, C, 2*C, C, FF, FF, C, 6*C};
    int Rs[9] = {1, 1, 1, 1, 1, 2, 2, 1, 1};
    int Ro[9] = {0, 0, 0, 0, 0, 0, 1, 0, 0};
    int tile = 0;
    for (int i = 0; i < 9; i++) {
        wa.j[i] = {Ws[i], Ts[i], Ks[i], Ns[i], Rs[i], Ro[i], tile};
        tile += (Ks[i] >> 5) * (Ns[i] >> 5);
    }
    wa.ntiles = tile;
    wconvert_all_kernel<<<tile, dim3(32, 8)>>>(wa);

    // adaLN (M padded to 128; bias folded at consumers)
    silu2h_kernel<<<(128*C + 255)/256, 256>>>(t_mod, sm);
    launch_gmma<0>(sm, adw, mods_p, 128, 6*C, C,
                   nullptr, nullptr, nullptr, 0, nullptr, nullptr, nullptr, nullptr, 0);

    // ---- self-attention ----
    rmsnorm_kernel<<<BL, 256>>>(x, n1w, mods_p, adaB, 0, C, act);
    launch_gmma<3>(act, qkvw, qh_p, BL, 3*C, C,
                   nullptr, nullptr, nullptr, 0, fcos, fsin, kh_p, v_p, L);
    fattn(qh_p, kh_p, v_p, act, L);
    launch_gmma<0>(act, saw, x_p, BL, C, C,
                   x, mods_p, adaB, 2*C, nullptr, nullptr, nullptr, nullptr, 0);

    // ---- cross-attention ----
    rmsnorm_kernel<<<BL, 256>>>(x_p, n2w, nullptr, nullptr, 0, 0, act);
    launch_gmma<4>(act, qw, qh_p, BL, C, C,
                   nullptr, nullptr, nullptr, 0, nullptr, nullptr, nullptr, nullptr, L);
    aconvert_kernel<<<(BL2*TD + 255)/256, 256>>>(audio, ctx, (size_t)BL2*TD);
    launch_gmma<5>(ctx, kvw, kh_p, BL2, 2*C, TD,
                   nullptr, nullptr, nullptr, 0, nullptr, nullptr, nullptr, v_p, L2);
    fattn(qh_p, kh_p, v_p, act, L2);
    launch_gmma<0>(act, caw, x_p, BL, C, C,
                   x_p, nullptr, nullptr, 0, nullptr, nullptr, nullptr, nullptr, 0);

    // ---- MLP ----
    rmsnorm_kernel<<<BL, 256>>>(x_p, n3w, mods_p, adaB, 3*C, 4*C, act);
    launch_gmma<2>(act, guw, hid, BL, 2*FF, C,
                   nullptr, nullptr, nullptr, 0, nullptr, nullptr, nullptr, nullptr, 0);
    launch_gmma<0>(hid, dw, out, BL, C, FF,
                   x_p, mods_p, adaB, 5*C, nullptr, nullptr, nullptr, nullptr, 0);
}